// round 1
// baseline (speedup 1.0000x reference)
#include <cuda_runtime.h>
#include <math.h>

#define BATCH 8
#define HH 56
#define WWID 56
#define CC 256
#define NHD 8
#define HD 32
#define NWIN 7
#define NREG 49
#define SREG 64
#define TOPK 4
#define TSZ 256
#define K2 32
#define M_TOK (BATCH*HH*WWID)          // 25088
#define SEQ_SIZE (BATCH*NHD*NREG*SREG*HD) // 6422528

// Scratch (device globals: allowed; no runtime allocation)
__device__ float g_Q[SEQ_SIZE];
__device__ float g_K[SEQ_SIZE];
__device__ float g_V[SEQ_SIZE];
__device__ float g_O[SEQ_SIZE];
__device__ float g_T[SEQ_SIZE];   // (B,H,W,C) pre-projection sum; same element count
__device__ float g_poolq[BATCH*NREG*CC];
__device__ float g_poolk[BATCH*NREG*CC];
__device__ int   g_topk[BATCH*NREG*TOPK];

// ---------------------------------------------------------------------------
// Kernel 1: QKV GEMM  (M=25088, N=768, K=256), epilogue scatters into
// region-sequence layout Q/K/V[b][head][region][s][d].
// ---------------------------------------------------------------------------
__global__ void qkv_gemm_kernel(const float* __restrict__ x,
                                const float* __restrict__ wq,
                                const float* __restrict__ bias)
{
    __shared__ float As[16][68];
    __shared__ float Bs[16][68];
    const int tx = threadIdx.x, ty = threadIdx.y;
    const int tid = ty * 16 + tx;
    const int m0 = blockIdx.y * 64, n0 = blockIdx.x * 64;

    float acc[4][4];
#pragma unroll
    for (int i = 0; i < 4; ++i)
#pragma unroll
        for (int j = 0; j < 4; ++j) acc[i][j] = 0.f;

    const int lrow = tid >> 2;      // 0..63
    const int lc4  = tid & 3;       // 0..3

    for (int k0 = 0; k0 < 256; k0 += 16) {
        float4 av = *reinterpret_cast<const float4*>(&x [(m0 + lrow) * 256 + k0 + lc4 * 4]);
        float4 bv = *reinterpret_cast<const float4*>(&wq[(n0 + lrow) * 256 + k0 + lc4 * 4]);
        As[lc4*4+0][lrow] = av.x; As[lc4*4+1][lrow] = av.y;
        As[lc4*4+2][lrow] = av.z; As[lc4*4+3][lrow] = av.w;
        Bs[lc4*4+0][lrow] = bv.x; Bs[lc4*4+1][lrow] = bv.y;
        Bs[lc4*4+2][lrow] = bv.z; Bs[lc4*4+3][lrow] = bv.w;
        __syncthreads();
#pragma unroll
        for (int k = 0; k < 16; ++k) {
            float4 a4 = *reinterpret_cast<float4*>(&As[k][ty * 4]);
            float4 b4 = *reinterpret_cast<float4*>(&Bs[k][tx * 4]);
            float aa[4] = {a4.x, a4.y, a4.z, a4.w};
            float bb[4] = {b4.x, b4.y, b4.z, b4.w};
#pragma unroll
            for (int i = 0; i < 4; ++i)
#pragma unroll
                for (int j = 0; j < 4; ++j) acc[i][j] += aa[i] * bb[j];
        }
        __syncthreads();
    }

    // Epilogue: scatter into seq layout. Within a thread the 4 n's stay in one
    // 32-wide head chunk (n0 multiple of 64, tx*4 multiple of 4).
    const int nbase = n0 + tx * 4;
    const int sec = nbase >> 8;          // 0=q 1=k 2=v
    const int cch = nbase & 255;
    const int mh  = cch >> 5;
    const int d0  = cch & 31;
    float* dst = (sec == 0) ? g_Q : (sec == 1 ? g_K : g_V);
    const float b0 = bias[nbase], b1 = bias[nbase+1], b2 = bias[nbase+2], b3 = bias[nbase+3];

#pragma unroll
    for (int i = 0; i < 4; ++i) {
        int m  = m0 + ty * 4 + i;
        int b  = m / 3136;
        int hw = m - b * 3136;
        int h  = hw / 56;
        int w  = hw - h * 56;
        int r  = (h >> 3) * 7 + (w >> 3);
        int ss = ((h & 7) << 3) | (w & 7);
        int off = ((b * 8 + mh) * 49 + r) * 2048 + ss * 32 + d0;
        float4 val = make_float4(acc[i][0] + b0, acc[i][1] + b1,
                                 acc[i][2] + b2, acc[i][3] + b3);
        *reinterpret_cast<float4*>(&dst[off]) = val;
    }
}

// ---------------------------------------------------------------------------
// Kernel 2: region average pooling of Q and K (routing inputs)
// ---------------------------------------------------------------------------
__global__ void pool_kernel()
{
    const int b = blockIdx.x / 49, r = blockIdx.x % 49;
    const int c = threadIdx.x;           // 0..255
    const int mh = c >> 5, d = c & 31;
    const int base = ((b * 8 + mh) * 49 + r) * 2048 + d;
    float sq = 0.f, sk = 0.f;
#pragma unroll 8
    for (int s = 0; s < 64; ++s) {
        sq += g_Q[base + s * 32];
        sk += g_K[base + s * 32];
    }
    g_poolq[(b * 49 + r) * 256 + c] = sq * (1.f / 64.f);
    g_poolk[(b * 49 + r) * 256 + c] = sk * (1.f / 64.f);
}

// ---------------------------------------------------------------------------
// Kernel 3: coarse routing — a_r[i,j] over 49 regions, top-4 region set
// ---------------------------------------------------------------------------
__global__ void route_kernel()
{
    const int b = blockIdx.x / 49, i = blockIdx.x % 49;
    __shared__ float qrow[256];
    __shared__ float scores[49];
    const int tid = threadIdx.x;
    qrow[tid] = g_poolq[(b * 49 + i) * 256 + tid];
    __syncthreads();
    const int warp = tid >> 5, lane = tid & 31;
    for (int j = warp; j < 49; j += 8) {
        const float* kr = g_poolk + (b * 49 + j) * 256;
        float s = 0.f;
#pragma unroll
        for (int cc = lane; cc < 256; cc += 32) s += qrow[cc] * kr[cc];
#pragma unroll
        for (int off = 16; off; off >>= 1) s += __shfl_xor_sync(0xffffffffu, s, off);
        if (lane == 0) scores[j] = s;
    }
    __syncthreads();
    if (tid == 0) {
        for (int t = 0; t < 4; ++t) {
            float bv = -INFINITY; int bj = 0;
            for (int j = 0; j < 49; ++j)
                if (scores[j] > bv) { bv = scores[j]; bj = j; }
            g_topk[(b * 49 + i) * 4 + t] = bj;
            scores[bj] = -INFINITY;
        }
    }
}

// ---------------------------------------------------------------------------
// Kernel 4: sparse attention per (b, head, region).
// Scores 64x256, exact token top-32 via 32 rounds of warp argmax
// (tie -> lowest TS index, matching jax.lax.top_k), fused softmax + AV.
// ---------------------------------------------------------------------------
__global__ void attn_kernel()
{
    extern __shared__ float smem[];
    float* Qs = smem;                  // 64*32        = 2048
    float* Ks = smem + 2048;           // 256*33 (pad) = 8448
    float* Vs = smem + 2048 + 8448;    // 256*32       = 8192

    const int blk = blockIdx.x;
    const int b   = blk / (NHD * NREG);
    const int rem = blk % (NHD * NREG);
    const int mh  = rem / NREG;
    const int r   = rem % NREG;
    const int tid = threadIdx.x;
    const int qbase = ((b * 8 + mh) * 49 + r) * 2048;

    for (int idx = tid; idx < 2048; idx += 256) Qs[idx] = g_Q[qbase + idx];
#pragma unroll
    for (int t = 0; t < 4; ++t) {
        const int rr = g_topk[(b * 49 + r) * 4 + t];
        const int base = ((b * 8 + mh) * 49 + rr) * 2048;
        for (int idx = tid; idx < 2048; idx += 256) {
            Ks[(t * 64 + (idx >> 5)) * 33 + (idx & 31)] = g_K[base + idx];
            Vs[t * 2048 + idx] = g_V[base + idx];
        }
    }
    __syncthreads();

    const int warp = tid >> 5, lane = tid & 31;
    const float scale = 0.0625f;   // C^-0.5

    for (int rowIt = 0; rowIt < 8; ++rowIt) {
        const int s = warp * 8 + rowIt;
        float sc[8];
#pragma unroll
        for (int t = 0; t < 8; ++t) sc[t] = 0.f;
        const float* qrow = Qs + s * 32;
        const float* kp = Ks + lane * 33;   // row (t*32+lane) = kp + t*1056
#pragma unroll 4
        for (int d = 0; d < 32; ++d) {
            const float qd = qrow[d];
#pragma unroll
            for (int t = 0; t < 8; ++t) sc[t] += qd * kp[t * 1056 + d];
        }
#pragma unroll
        for (int t = 0; t < 8; ++t) sc[t] *= scale;

        float rowmax = 0.f, denom = 0.f, o = 0.f;
        for (int it = 0; it < 32; ++it) {
            float bv = sc[0]; int bt = 0;
#pragma unroll
            for (int t = 1; t < 8; ++t)
                if (sc[t] > bv) { bv = sc[t]; bt = t; }
            int bj = bt * 32 + lane;
#pragma unroll
            for (int off = 16; off; off >>= 1) {
                float ov = __shfl_xor_sync(0xffffffffu, bv, off);
                int   oj = __shfl_xor_sync(0xffffffffu, bj, off);
                if (ov > bv || (ov == bv && oj < bj)) { bv = ov; bj = oj; }
            }
            if (it == 0) rowmax = bv;
            const float wgt = __expf(bv - rowmax);
            denom += wgt;
            o += wgt * Vs[bj * 32 + lane];
            if (lane == (bj & 31)) sc[bj >> 5] = -INFINITY;
        }
        g_O[qbase + s * 32 + lane] = o / denom;
    }
}

// ---------------------------------------------------------------------------
// Kernel 5: t = attn_out (seq->spatial) + LePE depthwise 3x3 over V, NHWC
// ---------------------------------------------------------------------------
__global__ void lepe_kernel(const float* __restrict__ lw,
                            const float* __restrict__ lb)
{
    const int idx = blockIdx.x * 256 + threadIdx.x;
    const int c   = idx & 255;
    const int pos = idx >> 8;
    const int w   = pos % 56;
    const int t2  = pos / 56;
    const int h   = t2 % 56;
    const int b   = t2 / 56;
    const int mh = c >> 5, d = c & 31;
    const int hbase = (b * 8 + mh) * 49;
    const int oaddr = (hbase + (h >> 3) * 7 + (w >> 3)) * 2048
                    + (((h & 7) << 3) | (w & 7)) * 32 + d;
    float acc = lb[c];
#pragma unroll
    for (int ky = 0; ky < 3; ++ky) {
        const int y = h + ky - 1;
        if (y < 0 || y >= 56) continue;
#pragma unroll
        for (int kx = 0; kx < 3; ++kx) {
            const int x = w + kx - 1;
            if (x < 0 || x >= 56) continue;
            const int va = (hbase + (y >> 3) * 7 + (x >> 3)) * 2048
                         + (((y & 7) << 3) | (x & 7)) * 32 + d;
            acc += g_V[va] * lw[c * 9 + ky * 3 + kx];
        }
    }
    g_T[idx] = g_O[oaddr] + acc;
}

// ---------------------------------------------------------------------------
// Kernel 6: output projection GEMM (M=25088, N=256, K=256) -> NHWC out
// ---------------------------------------------------------------------------
__global__ void out_gemm_kernel(const float* __restrict__ wo,
                                const float* __restrict__ bo,
                                float* __restrict__ out)
{
    __shared__ float As[16][68];
    __shared__ float Bs[16][68];
    const int tx = threadIdx.x, ty = threadIdx.y;
    const int tid = ty * 16 + tx;
    const int m0 = blockIdx.y * 64, n0 = blockIdx.x * 64;

    float acc[4][4];
#pragma unroll
    for (int i = 0; i < 4; ++i)
#pragma unroll
        for (int j = 0; j < 4; ++j) acc[i][j] = 0.f;

    const int lrow = tid >> 2, lc4 = tid & 3;

    for (int k0 = 0; k0 < 256; k0 += 16) {
        float4 av = *reinterpret_cast<const float4*>(&g_T[(m0 + lrow) * 256 + k0 + lc4 * 4]);
        float4 bv = *reinterpret_cast<const float4*>(&wo [(n0 + lrow) * 256 + k0 + lc4 * 4]);
        As[lc4*4+0][lrow] = av.x; As[lc4*4+1][lrow] = av.y;
        As[lc4*4+2][lrow] = av.z; As[lc4*4+3][lrow] = av.w;
        Bs[lc4*4+0][lrow] = bv.x; Bs[lc4*4+1][lrow] = bv.y;
        Bs[lc4*4+2][lrow] = bv.z; Bs[lc4*4+3][lrow] = bv.w;
        __syncthreads();
#pragma unroll
        for (int k = 0; k < 16; ++k) {
            float4 a4 = *reinterpret_cast<float4*>(&As[k][ty * 4]);
            float4 b4 = *reinterpret_cast<float4*>(&Bs[k][tx * 4]);
            float aa[4] = {a4.x, a4.y, a4.z, a4.w};
            float bb[4] = {b4.x, b4.y, b4.z, b4.w};
#pragma unroll
            for (int i = 0; i < 4; ++i)
#pragma unroll
                for (int j = 0; j < 4; ++j) acc[i][j] += aa[i] * bb[j];
        }
        __syncthreads();
    }

    const int nbase = n0 + tx * 4;
    const float b0 = bo[nbase], b1 = bo[nbase+1], b2 = bo[nbase+2], b3 = bo[nbase+3];
#pragma unroll
    for (int i = 0; i < 4; ++i) {
        const int m = m0 + ty * 4 + i;
        float4 val = make_float4(acc[i][0] + b0, acc[i][1] + b1,
                                 acc[i][2] + b2, acc[i][3] + b3);
        *reinterpret_cast<float4*>(&out[m * 256 + nbase]) = val;
    }
}

// ---------------------------------------------------------------------------
extern "C" void kernel_launch(void* const* d_in, const int* in_sizes, int n_in,
                              void* d_out, int out_size)
{
    const float* x      = (const float*)d_in[0];
    const float* qkv_w  = (const float*)d_in[1];
    const float* qkv_b  = (const float*)d_in[2];
    const float* lepe_w = (const float*)d_in[3];
    const float* lepe_b = (const float*)d_in[4];
    const float* out_w  = (const float*)d_in[5];
    const float* out_b  = (const float*)d_in[6];
    float* out = (float*)d_out;

    const int attn_smem = (2048 + 8448 + 8192) * (int)sizeof(float); // 74752 B
    cudaFuncSetAttribute(attn_kernel, cudaFuncAttributeMaxDynamicSharedMemorySize, attn_smem);

    qkv_gemm_kernel<<<dim3(12, 392), dim3(16, 16)>>>(x, qkv_w, qkv_b);
    pool_kernel<<<392, 256>>>();
    route_kernel<<<392, 256>>>();
    attn_kernel<<<BATCH * NHD * NREG, 256, attn_smem>>>();
    lepe_kernel<<<M_TOK, 256>>>(lepe_w, lepe_b);
    out_gemm_kernel<<<dim3(4, 392), dim3(16, 16)>>>(out_w, out_b, out);
}

// round 2
// speedup vs baseline: 1.3147x; 1.3147x over previous
#include <cuda_runtime.h>
#include <math.h>

#define BATCH 8
#define NHD 8
#define HD 32
#define NREG 49
#define SREG 64
#define TOPK 4
#define M_TOK (BATCH*56*56)                 // 25088
#define SEQ_SIZE (BATCH*NHD*NREG*SREG*HD)   // 6422528

__device__ float g_Q[SEQ_SIZE];
__device__ float g_K[SEQ_SIZE];
__device__ float g_V[SEQ_SIZE];
__device__ float g_O[SEQ_SIZE];
__device__ float g_T[SEQ_SIZE];
__device__ float g_poolq[BATCH*NREG*256];
__device__ float g_poolk[BATCH*NREG*256];
__device__ int   g_topk[BATCH*NREG*TOPK];

// ---------------------------------------------------------------------------
// QKV GEMM (M=25088, N=768, K=256): 128x128 tile, 8x8 microtile.
// Epilogue scatters into region-sequence layout Q/K/V[b][head][region][s][d].
// ---------------------------------------------------------------------------
__global__ void __launch_bounds__(256, 2)
qkv_gemm_kernel(const float* __restrict__ x,
                const float* __restrict__ wq,
                const float* __restrict__ bias)
{
    __shared__ float As[16][132];
    __shared__ float Bs[16][132];
    const int tx = threadIdx.x, ty = threadIdx.y;
    const int tid = ty * 16 + tx;
    const int m0 = blockIdx.y * 128, n0 = blockIdx.x * 128;

    float acc[8][8];
#pragma unroll
    for (int i = 0; i < 8; ++i)
#pragma unroll
        for (int j = 0; j < 8; ++j) acc[i][j] = 0.f;

    const int r0 = tid >> 2;   // 0..63
    const int c0 = tid & 3;    // k-quad

    for (int k0 = 0; k0 < 256; k0 += 16) {
#pragma unroll
        for (int p = 0; p < 2; ++p) {
            const int r = r0 + p * 64;
            float4 av = *(const float4*)&x [(m0 + r) * 256 + k0 + c0 * 4];
            float4 bv = *(const float4*)&wq[(n0 + r) * 256 + k0 + c0 * 4];
            As[c0*4+0][r] = av.x; As[c0*4+1][r] = av.y;
            As[c0*4+2][r] = av.z; As[c0*4+3][r] = av.w;
            Bs[c0*4+0][r] = bv.x; Bs[c0*4+1][r] = bv.y;
            Bs[c0*4+2][r] = bv.z; Bs[c0*4+3][r] = bv.w;
        }
        __syncthreads();
#pragma unroll
        for (int k = 0; k < 16; ++k) {
            float a[8], b[8];
            *(float4*)&a[0] = *(float4*)&As[k][ty * 8];
            *(float4*)&a[4] = *(float4*)&As[k][ty * 8 + 4];
            *(float4*)&b[0] = *(float4*)&Bs[k][tx * 8];
            *(float4*)&b[4] = *(float4*)&Bs[k][tx * 8 + 4];
#pragma unroll
            for (int i = 0; i < 8; ++i)
#pragma unroll
                for (int j = 0; j < 8; ++j) acc[i][j] = fmaf(a[i], b[j], acc[i][j]);
        }
        __syncthreads();
    }

    const int nbase = n0 + tx * 8;          // 8 consecutive n, within one 32-chunk
    const int sec = nbase >> 8;             // 0=q 1=k 2=v
    const int cch = nbase & 255;
    const int mh  = cch >> 5, d0 = cch & 31;
    float* dst = (sec == 0) ? g_Q : (sec == 1 ? g_K : g_V);
    float bb[8];
    *(float4*)&bb[0] = *(const float4*)&bias[nbase];
    *(float4*)&bb[4] = *(const float4*)&bias[nbase + 4];

#pragma unroll
    for (int i = 0; i < 8; ++i) {
        int m  = m0 + ty * 8 + i;
        int b  = m / 3136;
        int hw = m - b * 3136;
        int h  = hw / 56;
        int w  = hw - h * 56;
        int r  = (h >> 3) * 7 + (w >> 3);
        int ss = ((h & 7) << 3) | (w & 7);
        int off = ((b * 8 + mh) * 49 + r) * 2048 + ss * 32 + d0;
        float4 v0 = make_float4(acc[i][0]+bb[0], acc[i][1]+bb[1], acc[i][2]+bb[2], acc[i][3]+bb[3]);
        float4 v1 = make_float4(acc[i][4]+bb[4], acc[i][5]+bb[5], acc[i][6]+bb[6], acc[i][7]+bb[7]);
        *(float4*)&dst[off]     = v0;
        *(float4*)&dst[off + 4] = v1;
    }
}

// ---------------------------------------------------------------------------
// Region average pooling of Q and K
// ---------------------------------------------------------------------------
__global__ void pool_kernel()
{
    const int b = blockIdx.x / 49, r = blockIdx.x % 49;
    const int c = threadIdx.x;
    const int mh = c >> 5, d = c & 31;
    const int base = ((b * 8 + mh) * 49 + r) * 2048 + d;
    float sq = 0.f, sk = 0.f;
#pragma unroll 8
    for (int s = 0; s < 64; ++s) {
        sq += g_Q[base + s * 32];
        sk += g_K[base + s * 32];
    }
    g_poolq[(b * 49 + r) * 256 + c] = sq * (1.f / 64.f);
    g_poolk[(b * 49 + r) * 256 + c] = sk * (1.f / 64.f);
}

// ---------------------------------------------------------------------------
// Coarse routing: top-4 region set per (b, region)
// ---------------------------------------------------------------------------
__global__ void route_kernel()
{
    const int b = blockIdx.x / 49, i = blockIdx.x % 49;
    __shared__ float qrow[256];
    __shared__ float scores[49];
    const int tid = threadIdx.x;
    qrow[tid] = g_poolq[(b * 49 + i) * 256 + tid];
    __syncthreads();
    const int warp = tid >> 5, lane = tid & 31;
    for (int j = warp; j < 49; j += 8) {
        const float* kr = g_poolk + (b * 49 + j) * 256;
        float s = 0.f;
#pragma unroll
        for (int cc = lane; cc < 256; cc += 32) s += qrow[cc] * kr[cc];
#pragma unroll
        for (int off = 16; off; off >>= 1) s += __shfl_xor_sync(0xffffffffu, s, off);
        if (lane == 0) scores[j] = s;
    }
    __syncthreads();
    if (tid == 0) {
        for (int t = 0; t < 4; ++t) {
            float bv = -INFINITY; int bj = 0;
            for (int j = 0; j < 49; ++j)
                if (scores[j] > bv) { bv = scores[j]; bj = j; }
            g_topk[(b * 49 + i) * 4 + t] = bj;
            scores[bj] = -INFINITY;
        }
    }
}

// ---------------------------------------------------------------------------
// Sparse attention per (b, head, region). Token top-32 via per-lane sorted
// stash + REDUX head merge. Tie-break = lowest TS index (matches lax.top_k).
// ---------------------------------------------------------------------------
#define CASD(a, b) { unsigned long long _x = key[a], _y = key[b]; \
                     bool _p = _x > _y; \
                     key[a] = _p ? _x : _y; key[b] = _p ? _y : _x; }

__global__ void __launch_bounds__(256, 2) attn_kernel()
{
    extern __shared__ float smem[];
    float* Qs = smem;                        // 64*32            = 2048 f
    float* Ks = smem + 2048;                 // 256 rows * 36    = 9216 f
    float* Vs = smem + 2048 + 9216;          // 256*32           = 8192 f
    unsigned long long* stash =
        (unsigned long long*)(smem + 2048 + 9216 + 8192);  // 8w*32l*9 u64 = 18432 B

    const int blk = blockIdx.x;
    const int b   = blk / (NHD * NREG);
    const int rem = blk % (NHD * NREG);
    const int mh  = rem / NREG;
    const int r   = rem % NREG;
    const int tid = threadIdx.x;
    const int qbase = ((b * 8 + mh) * 49 + r) * 2048;
    const float scale = 0.0625f;

    for (int idx = tid; idx < 2048; idx += 256) Qs[idx] = g_Q[qbase + idx] * scale;
#pragma unroll
    for (int t = 0; t < 4; ++t) {
        const int rr = g_topk[(b * 49 + r) * 4 + t];
        const int base = ((b * 8 + mh) * 49 + rr) * 2048;
        for (int idx = tid; idx < 2048; idx += 256) {
            Ks[(t * 64 + (idx >> 5)) * 36 + (idx & 31)] = g_K[base + idx];
            Vs[t * 2048 + idx] = g_V[base + idx];
        }
    }
    __syncthreads();

    const int warp = tid >> 5, lane = tid & 31;
    unsigned long long* mystash = stash + (warp * 32 + lane) * 9;

    for (int rowIt = 0; rowIt < 8; ++rowIt) {
        const int s = warp * 8 + rowIt;

        // ---- scores for j = t*32+lane, t=0..7 ----
        float q[32];
#pragma unroll
        for (int i = 0; i < 8; ++i)
            *(float4*)&q[i * 4] = *(const float4*)&Qs[s * 32 + i * 4];

        unsigned long long key[8];
#pragma unroll
        for (int t = 0; t < 8; ++t) {
            const float* kr = Ks + (t * 32 + lane) * 36;
            float acc = 0.f;
#pragma unroll
            for (int i = 0; i < 8; ++i) {
                float4 k4 = *(const float4*)&kr[i * 4];
                acc = fmaf(q[i*4+0], k4.x, acc);
                acc = fmaf(q[i*4+1], k4.y, acc);
                acc = fmaf(q[i*4+2], k4.z, acc);
                acc = fmaf(q[i*4+3], k4.w, acc);
            }
            unsigned ub = __float_as_uint(acc);
            unsigned um = (ub & 0x80000000u) ? ~ub : (ub | 0x80000000u);
            key[t] = ((unsigned long long)um << 32) |
                     (unsigned)(255 - (t * 32 + lane));
        }

        // ---- per-lane sort descending (Batcher 8-net, 19 CAS) ----
        CASD(0,1) CASD(2,3) CASD(4,5) CASD(6,7)
        CASD(0,2) CASD(1,3) CASD(4,6) CASD(5,7)
        CASD(1,2) CASD(5,6)
        CASD(0,4) CASD(1,5) CASD(2,6) CASD(3,7)
        CASD(2,4) CASD(3,5)
        CASD(1,2) CASD(3,4) CASD(5,6)

#pragma unroll
        for (int i = 1; i < 8; ++i) mystash[i] = key[i];

        // ---- 32 pops: REDUX merge of heads, fused softmax + AV ----
        unsigned long long head = key[0];
        int ptr = 1;
        float m = 0.f, denom = 0.f, o = 0.f;
#pragma unroll 4
        for (int it = 0; it < 32; ++it) {
            unsigned hv  = (unsigned)(head >> 32);
            unsigned win = __reduce_max_sync(0xffffffffu, hv);
            unsigned hl  = (unsigned)head;
            unsigned wl  = __reduce_max_sync(0xffffffffu, (hv == win) ? hl : 0u);
            int j = 255 - (int)wl;
            unsigned fb = (win & 0x80000000u) ? (win & 0x7fffffffu) : ~win;
            float val = __uint_as_float(fb);
            if (it == 0) m = val;
            float w = __expf(val - m);
            denom += w;
            o = fmaf(w, Vs[j * 32 + lane], o);
            if (hv == win && hl == wl) {
                head = (ptr < 8) ? mystash[ptr] : 0ull;
                ++ptr;
            }
        }
        g_O[qbase + s * 32 + lane] = o / denom;
    }
}

// ---------------------------------------------------------------------------
// t = attn_out (seq->spatial) + LePE depthwise 3x3 over V, NHWC
// ---------------------------------------------------------------------------
__global__ void lepe_kernel(const float* __restrict__ lw,
                            const float* __restrict__ lb)
{
    const int idx = blockIdx.x * 256 + threadIdx.x;
    const int c   = idx & 255;
    const int pos = idx >> 8;
    const int w   = pos % 56;
    const int t2  = pos / 56;
    const int h   = t2 % 56;
    const int b   = t2 / 56;
    const int mh = c >> 5, d = c & 31;
    const int hbase = (b * 8 + mh) * 49;
    const int oaddr = (hbase + (h >> 3) * 7 + (w >> 3)) * 2048
                    + (((h & 7) << 3) | (w & 7)) * 32 + d;
    float acc = lb[c];
#pragma unroll
    for (int ky = 0; ky < 3; ++ky) {
        const int y = h + ky - 1;
        if (y < 0 || y >= 56) continue;
#pragma unroll
        for (int kx = 0; kx < 3; ++kx) {
            const int x = w + kx - 1;
            if (x < 0 || x >= 56) continue;
            const int va = (hbase + (y >> 3) * 7 + (x >> 3)) * 2048
                         + (((y & 7) << 3) | (x & 7)) * 32 + d;
            acc += g_V[va] * lw[c * 9 + ky * 3 + kx];
        }
    }
    g_T[idx] = g_O[oaddr] + acc;
}

// ---------------------------------------------------------------------------
// Output projection GEMM (M=25088, N=256, K=256), 128x128 tile, 8x8 micro.
// ---------------------------------------------------------------------------
__global__ void __launch_bounds__(256, 2)
out_gemm_kernel(const float* __restrict__ wo,
                const float* __restrict__ bo,
                float* __restrict__ out)
{
    __shared__ float As[16][132];
    __shared__ float Bs[16][132];
    const int tx = threadIdx.x, ty = threadIdx.y;
    const int tid = ty * 16 + tx;
    const int m0 = blockIdx.y * 128, n0 = blockIdx.x * 128;

    float acc[8][8];
#pragma unroll
    for (int i = 0; i < 8; ++i)
#pragma unroll
        for (int j = 0; j < 8; ++j) acc[i][j] = 0.f;

    const int r0 = tid >> 2, c0 = tid & 3;

    for (int k0 = 0; k0 < 256; k0 += 16) {
#pragma unroll
        for (int p = 0; p < 2; ++p) {
            const int r = r0 + p * 64;
            float4 av = *(const float4*)&g_T[(m0 + r) * 256 + k0 + c0 * 4];
            float4 bv = *(const float4*)&wo [(n0 + r) * 256 + k0 + c0 * 4];
            As[c0*4+0][r] = av.x; As[c0*4+1][r] = av.y;
            As[c0*4+2][r] = av.z; As[c0*4+3][r] = av.w;
            Bs[c0*4+0][r] = bv.x; Bs[c0*4+1][r] = bv.y;
            Bs[c0*4+2][r] = bv.z; Bs[c0*4+3][r] = bv.w;
        }
        __syncthreads();
#pragma unroll
        for (int k = 0; k < 16; ++k) {
            float a[8], b[8];
            *(float4*)&a[0] = *(float4*)&As[k][ty * 8];
            *(float4*)&a[4] = *(float4*)&As[k][ty * 8 + 4];
            *(float4*)&b[0] = *(float4*)&Bs[k][tx * 8];
            *(float4*)&b[4] = *(float4*)&Bs[k][tx * 8 + 4];
#pragma unroll
            for (int i = 0; i < 8; ++i)
#pragma unroll
                for (int j = 0; j < 8; ++j) acc[i][j] = fmaf(a[i], b[j], acc[i][j]);
        }
        __syncthreads();
    }

    const int nbase = n0 + tx * 8;
    float bb[8];
    *(float4*)&bb[0] = *(const float4*)&bo[nbase];
    *(float4*)&bb[4] = *(const float4*)&bo[nbase + 4];
#pragma unroll
    for (int i = 0; i < 8; ++i) {
        const int m = m0 + ty * 8 + i;
        float4 v0 = make_float4(acc[i][0]+bb[0], acc[i][1]+bb[1], acc[i][2]+bb[2], acc[i][3]+bb[3]);
        float4 v1 = make_float4(acc[i][4]+bb[4], acc[i][5]+bb[5], acc[i][6]+bb[6], acc[i][7]+bb[7]);
        *(float4*)&out[m * 256 + nbase]     = v0;
        *(float4*)&out[m * 256 + nbase + 4] = v1;
    }
}

// ---------------------------------------------------------------------------
extern "C" void kernel_launch(void* const* d_in, const int* in_sizes, int n_in,
                              void* d_out, int out_size)
{
    const float* x      = (const float*)d_in[0];
    const float* qkv_w  = (const float*)d_in[1];
    const float* qkv_b  = (const float*)d_in[2];
    const float* lepe_w = (const float*)d_in[3];
    const float* lepe_b = (const float*)d_in[4];
    const float* out_w  = (const float*)d_in[5];
    const float* out_b  = (const float*)d_in[6];
    float* out = (float*)d_out;

    const int attn_smem = (2048 + 9216 + 8192) * 4 + 8 * 32 * 9 * 8;  // 96256 B
    cudaFuncSetAttribute(attn_kernel, cudaFuncAttributeMaxDynamicSharedMemorySize, attn_smem);

    qkv_gemm_kernel<<<dim3(6, 196), dim3(16, 16)>>>(x, qkv_w, qkv_b);
    pool_kernel<<<392, 256>>>();
    route_kernel<<<392, 256>>>();
    attn_kernel<<<BATCH * NHD * NREG, 256, attn_smem>>>();
    lepe_kernel<<<M_TOK, 256>>>(lepe_w, lepe_b);
    out_gemm_kernel<<<dim3(2, 196), dim3(16, 16)>>>(out_w, out_b, out);
}

// round 4
// speedup vs baseline: 1.7387x; 1.3225x over previous
#include <cuda_runtime.h>
#include <math.h>

#define BATCH 8
#define NHD 8
#define HD 32
#define NREG 49
#define SREG 64
#define TOPK 4
#define M_TOK (BATCH*56*56)                 // 25088
#define SEQ_SIZE (BATCH*NHD*NREG*SREG*HD)   // 6422528

__device__ float g_Q[SEQ_SIZE];
__device__ float g_K[SEQ_SIZE];
__device__ float g_V[SEQ_SIZE];
__device__ float g_O[SEQ_SIZE];
__device__ float g_T[SEQ_SIZE];
__device__ float g_poolq[BATCH*NREG*256];
__device__ float g_poolk[BATCH*NREG*256];
__device__ int   g_topk[BATCH*NREG*TOPK];

// ---------------------------------------------------------------------------
// QKV GEMM (M=25088, N=768, K=256): 128x128 tile, 8x8 microtile.
// ---------------------------------------------------------------------------
__global__ void __launch_bounds__(256, 2)
qkv_gemm_kernel(const float* __restrict__ x,
                const float* __restrict__ wq,
                const float* __restrict__ bias)
{
    __shared__ float As[16][132];
    __shared__ float Bs[16][132];
    const int tx = threadIdx.x, ty = threadIdx.y;
    const int tid = ty * 16 + tx;
    const int m0 = blockIdx.y * 128, n0 = blockIdx.x * 128;

    float acc[8][8];
#pragma unroll
    for (int i = 0; i < 8; ++i)
#pragma unroll
        for (int j = 0; j < 8; ++j) acc[i][j] = 0.f;

    const int r0 = tid >> 2, c0 = tid & 3;

    for (int k0 = 0; k0 < 256; k0 += 16) {
#pragma unroll
        for (int p = 0; p < 2; ++p) {
            const int r = r0 + p * 64;
            float4 av = *(const float4*)&x [(m0 + r) * 256 + k0 + c0 * 4];
            float4 bv = *(const float4*)&wq[(n0 + r) * 256 + k0 + c0 * 4];
            As[c0*4+0][r] = av.x; As[c0*4+1][r] = av.y;
            As[c0*4+2][r] = av.z; As[c0*4+3][r] = av.w;
            Bs[c0*4+0][r] = bv.x; Bs[c0*4+1][r] = bv.y;
            Bs[c0*4+2][r] = bv.z; Bs[c0*4+3][r] = bv.w;
        }
        __syncthreads();
#pragma unroll
        for (int k = 0; k < 16; ++k) {
            float a[8], b[8];
            *(float4*)&a[0] = *(float4*)&As[k][ty * 8];
            *(float4*)&a[4] = *(float4*)&As[k][ty * 8 + 4];
            *(float4*)&b[0] = *(float4*)&Bs[k][tx * 8];
            *(float4*)&b[4] = *(float4*)&Bs[k][tx * 8 + 4];
#pragma unroll
            for (int i = 0; i < 8; ++i)
#pragma unroll
                for (int j = 0; j < 8; ++j) acc[i][j] = fmaf(a[i], b[j], acc[i][j]);
        }
        __syncthreads();
    }

    const int nbase = n0 + tx * 8;
    const int sec = nbase >> 8;
    const int cch = nbase & 255;
    const int mh  = cch >> 5, d0 = cch & 31;
    float* dst = (sec == 0) ? g_Q : (sec == 1 ? g_K : g_V);
    float bb[8];
    *(float4*)&bb[0] = *(const float4*)&bias[nbase];
    *(float4*)&bb[4] = *(const float4*)&bias[nbase + 4];

#pragma unroll
    for (int i = 0; i < 8; ++i) {
        int m  = m0 + ty * 8 + i;
        int b  = m / 3136;
        int hw = m - b * 3136;
        int h  = hw / 56;
        int w  = hw - h * 56;
        int r  = (h >> 3) * 7 + (w >> 3);
        int ss = ((h & 7) << 3) | (w & 7);
        int off = ((b * 8 + mh) * 49 + r) * 2048 + ss * 32 + d0;
        float4 v0 = make_float4(acc[i][0]+bb[0], acc[i][1]+bb[1], acc[i][2]+bb[2], acc[i][3]+bb[3]);
        float4 v1 = make_float4(acc[i][4]+bb[4], acc[i][5]+bb[5], acc[i][6]+bb[6], acc[i][7]+bb[7]);
        *(float4*)&dst[off]     = v0;
        *(float4*)&dst[off + 4] = v1;
    }
}

// ---------------------------------------------------------------------------
// Region average pooling of Q and K
// ---------------------------------------------------------------------------
__global__ void pool_kernel()
{
    const int b = blockIdx.x / 49, r = blockIdx.x % 49;
    const int c = threadIdx.x;
    const int mh = c >> 5, d = c & 31;
    const int base = ((b * 8 + mh) * 49 + r) * 2048 + d;
    float sq = 0.f, sk = 0.f;
#pragma unroll 8
    for (int s = 0; s < 64; ++s) {
        sq += g_Q[base + s * 32];
        sk += g_K[base + s * 32];
    }
    g_poolq[(b * 49 + r) * 256 + c] = sq * (1.f / 64.f);
    g_poolk[(b * 49 + r) * 256 + c] = sk * (1.f / 64.f);
}

// ---------------------------------------------------------------------------
// Coarse routing: top-4 region set per (b, region)
// ---------------------------------------------------------------------------
__global__ void route_kernel()
{
    const int b = blockIdx.x / 49, i = blockIdx.x % 49;
    __shared__ float qrow[256];
    __shared__ float scores[49];
    const int tid = threadIdx.x;
    qrow[tid] = g_poolq[(b * 49 + i) * 256 + tid];
    __syncthreads();
    const int warp = tid >> 5, lane = tid & 31;
    for (int j = warp; j < 49; j += 8) {
        const float* kr = g_poolk + (b * 49 + j) * 256;
        float s = 0.f;
#pragma unroll
        for (int cc = lane; cc < 256; cc += 32) s += qrow[cc] * kr[cc];
#pragma unroll
        for (int off = 16; off; off >>= 1) s += __shfl_xor_sync(0xffffffffu, s, off);
        if (lane == 0) scores[j] = s;
    }
    __syncthreads();
    if (tid == 0) {
        for (int t = 0; t < 4; ++t) {
            float bv = -INFINITY; int bj = 0;
            for (int j = 0; j < 49; ++j)
                if (scores[j] > bv) { bv = scores[j]; bj = j; }
            g_topk[(b * 49 + i) * 4 + t] = bj;
            scores[bj] = -INFINITY;
        }
    }
}

// ---------------------------------------------------------------------------
// Sparse attention per (b, head, region).
// Token top-32 via exact binary bit-search for the 32nd-largest key +
// ballot-ranked tie resolution (lowest index first, matching lax.top_k).
// Two rows per warp interleaved to hide reduce latency.
// ---------------------------------------------------------------------------
__device__ __forceinline__ unsigned fkey(float v) {
    unsigned u = __float_as_uint(v);
    return (u & 0x80000000u) ? ~u : (u | 0x80000000u);
}
__device__ __forceinline__ float fkeyinv(unsigned k) {
    return __uint_as_float((k & 0x80000000u) ? (k & 0x7fffffffu) : ~k);
}

__global__ void __launch_bounds__(256, 3) attn_kernel()
{
    extern __shared__ float smem[];
    float* Ks = smem;                       // 256 rows * stride 36 = 9216 f
    float* Vs = smem + 9216;                // 256*32 = 8192 f
    unsigned long long* plist =
        (unsigned long long*)(smem + 9216 + 8192);  // 8 warps * 64 u64 = 4096 B

    const int blk = blockIdx.x;
    const int b   = blk / (NHD * NREG);
    const int rem = blk % (NHD * NREG);
    const int mh  = rem / NREG;
    const int r   = rem % NREG;
    const int tid = threadIdx.x;
    const int qbase = ((b * 8 + mh) * 49 + r) * 2048;
    const float scale = 0.0625f;
    const unsigned FULL = 0xffffffffu;

#pragma unroll
    for (int t = 0; t < 4; ++t) {
        const int rr = g_topk[(b * 49 + r) * 4 + t];
        const int base = ((b * 8 + mh) * 49 + rr) * 2048;
        for (int idx = tid; idx < 2048; idx += 256) {
            Ks[(t * 64 + (idx >> 5)) * 36 + (idx & 31)] = g_K[base + idx];
            Vs[t * 2048 + idx] = g_V[base + idx];
        }
    }
    __syncthreads();

    const int warp = tid >> 5, lane = tid & 31;
    const unsigned lanelt = (1u << lane) - 1u;
    unsigned long long* myp = plist + warp * 64;

#pragma unroll 1
    for (int pr = 0; pr < 4; ++pr) {
        const int sA = warp * 8 + pr * 2, sB = sA + 1;

        // ---- scores: two rows share K smem traffic ----
        float aA[8], aB[8];
#pragma unroll
        for (int t = 0; t < 8; ++t) { aA[t] = 0.f; aB[t] = 0.f; }
        const float* qA = g_Q + qbase + sA * 32;
        const float* qB = g_Q + qbase + sB * 32;
#pragma unroll
        for (int i = 0; i < 8; ++i) {
            const float4 q4A = *(const float4*)&qA[i * 4];
            const float4 q4B = *(const float4*)&qB[i * 4];
#pragma unroll
            for (int t = 0; t < 8; ++t) {
                const float4 k4 = *(const float4*)&Ks[(t * 32 + lane) * 36 + i * 4];
                aA[t] = fmaf(q4A.x, k4.x, fmaf(q4A.y, k4.y,
                        fmaf(q4A.z, k4.z, fmaf(q4A.w, k4.w, aA[t]))));
                aB[t] = fmaf(q4B.x, k4.x, fmaf(q4B.y, k4.y,
                        fmaf(q4B.z, k4.z, fmaf(q4B.w, k4.w, aB[t]))));
            }
        }

        unsigned kA[8], kB[8], mxA = 0u, mxB = 0u;
#pragma unroll
        for (int t = 0; t < 8; ++t) {
            kA[t] = fkey(aA[t] * scale);
            kB[t] = fkey(aB[t] * scale);
            mxA = kA[t] > mxA ? kA[t] : mxA;
            mxB = kB[t] > mxB ? kB[t] : mxB;
        }
        mxA = __reduce_max_sync(FULL, mxA);
        mxB = __reduce_max_sync(FULL, mxB);
        const float mA = fkeyinv(mxA), mB = fkeyinv(mxB);

        // ---- exact 32nd-largest key via binary bit-search ----
        unsigned TA = 0u, TB = 0u;
#pragma unroll
        for (int bit = 31; bit >= 0; --bit) {
            const unsigned cA = TA | (1u << bit);
            const unsigned cB = TB | (1u << bit);
            int na = 0, nb = 0;
#pragma unroll
            for (int t = 0; t < 8; ++t) {
                na += (kA[t] >= cA);
                nb += (kB[t] >= cB);
            }
            na = __reduce_add_sync(FULL, na);
            nb = __reduce_add_sync(FULL, nb);
            if (na >= 32) TA = cA;
            if (nb >= 32) TB = cB;
        }

        int cgA = 0, cgB = 0;
#pragma unroll
        for (int t = 0; t < 8; ++t) { cgA += (kA[t] > TA); cgB += (kB[t] > TB); }
        cgA = __reduce_add_sync(FULL, cgA);
        cgB = __reduce_add_sync(FULL, cgB);
        const int extraA = 32 - cgA, extraB = 32 - cgB;

        // ---- compaction: strict-greater all in; ties by lowest j ----
        __syncwarp();
        int offA = 0, tieA = 0, offB = 0, tieB = 0;
#pragma unroll
        for (int t = 0; t < 8; ++t) {
            {
                const bool gt = kA[t] > TA;
                const bool eq = kA[t] == TA;
                const unsigned meq = __ballot_sync(FULL, eq);
                const bool sel = gt || (eq && (tieA + __popc(meq & lanelt) < extraA));
                const unsigned msel = __ballot_sync(FULL, sel);
                if (sel) {
                    const int pos = offA + __popc(msel & lanelt);
                    const float w = __expf(fkeyinv(kA[t]) - mA);
                    myp[pos] = ((unsigned long long)__float_as_uint(w) << 32)
                             | (unsigned)(t * 32 + lane);
                }
                offA += __popc(msel);
                tieA += __popc(meq);
            }
            {
                const bool gt = kB[t] > TB;
                const bool eq = kB[t] == TB;
                const unsigned meq = __ballot_sync(FULL, eq);
                const bool sel = gt || (eq && (tieB + __popc(meq & lanelt) < extraB));
                const unsigned msel = __ballot_sync(FULL, sel);
                if (sel) {
                    const int pos = offB + __popc(msel & lanelt);
                    const float w = __expf(fkeyinv(kB[t]) - mB);
                    myp[32 + pos] = ((unsigned long long)__float_as_uint(w) << 32)
                                  | (unsigned)(t * 32 + lane);
                }
                offB += __popc(msel);
                tieB += __popc(meq);
            }
        }
        __syncwarp();

        // ---- fused softmax-normalize + AV over the 32-entry compact list ----
        float oA = 0.f, dA = 0.f, oB = 0.f, dB = 0.f;
#pragma unroll 8
        for (int i = 0; i < 32; ++i) {
            const unsigned long long pa = myp[i];
            const unsigned long long pb = myp[32 + i];
            const float wa = __uint_as_float((unsigned)(pa >> 32));
            const float wb = __uint_as_float((unsigned)(pb >> 32));
            const int ja = (int)(pa & 0xffffu);
            const int jb = (int)(pb & 0xffffu);
            dA += wa; dB += wb;
            oA = fmaf(wa, Vs[ja * 32 + lane], oA);
            oB = fmaf(wb, Vs[jb * 32 + lane], oB);
        }
        g_O[qbase + sA * 32 + lane] = oA / dA;
        g_O[qbase + sB * 32 + lane] = oB / dB;
        __syncwarp();
    }
}

// ---------------------------------------------------------------------------
// t = attn_out (seq->spatial) + LePE depthwise 3x3 over V, NHWC
// ---------------------------------------------------------------------------
__global__ void lepe_kernel(const float* __restrict__ lw,
                            const float* __restrict__ lb)
{
    const int idx = blockIdx.x * 256 + threadIdx.x;
    const int c   = idx & 255;
    const int pos = idx >> 8;
    const int w   = pos % 56;
    const int t2  = pos / 56;
    const int h   = t2 % 56;
    const int b   = t2 / 56;
    const int mh = c >> 5, d = c & 31;
    const int hbase = (b * 8 + mh) * 49;
    const int oaddr = (hbase + (h >> 3) * 7 + (w >> 3)) * 2048
                    + (((h & 7) << 3) | (w & 7)) * 32 + d;
    float acc = lb[c];
#pragma unroll
    for (int ky = 0; ky < 3; ++ky) {
        const int y = h + ky - 1;
        if (y < 0 || y >= 56) continue;
#pragma unroll
        for (int kx = 0; kx < 3; ++kx) {
            const int x = w + kx - 1;
            if (x < 0 || x >= 56) continue;
            const int va = (hbase + (y >> 3) * 7 + (x >> 3)) * 2048
                         + (((y & 7) << 3) | (x & 7)) * 32 + d;
            acc += g_V[va] * lw[c * 9 + ky * 3 + kx];
        }
    }
    g_T[idx] = g_O[oaddr] + acc;
}

// ---------------------------------------------------------------------------
// Output projection GEMM (M=25088, N=256, K=256), 128x128 tile, 8x8 micro.
// ---------------------------------------------------------------------------
__global__ void __launch_bounds__(256, 2)
out_gemm_kernel(const float* __restrict__ wo,
                const float* __restrict__ bo,
                float* __restrict__ out)
{
    __shared__ float As[16][132];
    __shared__ float Bs[16][132];
    const int tx = threadIdx.x, ty = threadIdx.y;
    const int tid = ty * 16 + tx;
    const int m0 = blockIdx.y * 128, n0 = blockIdx.x * 128;

    float acc[8][8];
#pragma unroll
    for (int i = 0; i < 8; ++i)
#pragma unroll
        for (int j = 0; j < 8; ++j) acc[i][j] = 0.f;

    const int r0 = tid >> 2, c0 = tid & 3;

    for (int k0 = 0; k0 < 256; k0 += 16) {
#pragma unroll
        for (int p = 0; p < 2; ++p) {
            const int r = r0 + p * 64;
            float4 av = *(const float4*)&g_T[(m0 + r) * 256 + k0 + c0 * 4];
            float4 bv = *(const float4*)&wo [(n0 + r) * 256 + k0 + c0 * 4];
            As[c0*4+0][r] = av.x; As[c0*4+1][r] = av.y;
            As[c0*4+2][r] = av.z; As[c0*4+3][r] = av.w;
            Bs[c0*4+0][r] = bv.x; Bs[c0*4+1][r] = bv.y;
            Bs[c0*4+2][r] = bv.z; Bs[c0*4+3][r] = bv.w;
        }
        __syncthreads();
#pragma unroll
        for (int k = 0; k < 16; ++k) {
            float a[8], b[8];
            *(float4*)&a[0] = *(float4*)&As[k][ty * 8];
            *(float4*)&a[4] = *(float4*)&As[k][ty * 8 + 4];
            *(float4*)&b[0] = *(float4*)&Bs[k][tx * 8];
            *(float4*)&b[4] = *(float4*)&Bs[k][tx * 8 + 4];
#pragma unroll
            for (int i = 0; i < 8; ++i)
#pragma unroll
                for (int j = 0; j < 8; ++j) acc[i][j] = fmaf(a[i], b[j], acc[i][j]);
        }
        __syncthreads();
    }

    const int nbase = n0 + tx * 8;
    float bb[8];
    *(float4*)&bb[0] = *(const float4*)&bo[nbase];
    *(float4*)&bb[4] = *(const float4*)&bo[nbase + 4];
#pragma unroll
    for (int i = 0; i < 8; ++i) {
        const int m = m0 + ty * 8 + i;
        float4 v0 = make_float4(acc[i][0]+bb[0], acc[i][1]+bb[1], acc[i][2]+bb[2], acc[i][3]+bb[3]);
        float4 v1 = make_float4(acc[i][4]+bb[4], acc[i][5]+bb[5], acc[i][6]+bb[6], acc[i][7]+bb[7]);
        *(float4*)&out[m * 256 + nbase]     = v0;
        *(float4*)&out[m * 256 + nbase + 4] = v1;
    }
}

// ---------------------------------------------------------------------------
extern "C" void kernel_launch(void* const* d_in, const int* in_sizes, int n_in,
                              void* d_out, int out_size)
{
    const float* x      = (const float*)d_in[0];
    const float* qkv_w  = (const float*)d_in[1];
    const float* qkv_b  = (const float*)d_in[2];
    const float* lepe_w = (const float*)d_in[3];
    const float* lepe_b = (const float*)d_in[4];
    const float* out_w  = (const float*)d_in[5];
    const float* out_b  = (const float*)d_in[6];
    float* out = (float*)d_out;

    const int attn_smem = (9216 + 8192) * 4 + 8 * 64 * 8;   // 73728 B
    cudaFuncSetAttribute(attn_kernel, cudaFuncAttributeMaxDynamicSharedMemorySize, attn_smem);

    qkv_gemm_kernel<<<dim3(6, 196), dim3(16, 16)>>>(x, qkv_w, qkv_b);
    pool_kernel<<<392, 256>>>();
    route_kernel<<<392, 256>>>();
    attn_kernel<<<BATCH * NHD * NREG, 256, attn_smem>>>();
    lepe_kernel<<<M_TOK, 256>>>(lepe_w, lepe_b);
    out_gemm_kernel<<<dim3(2, 196), dim3(16, 16)>>>(out_w, out_b, out);
}

// round 5
// speedup vs baseline: 1.7568x; 1.0104x over previous
#include <cuda_runtime.h>
#include <math.h>

#define BATCH 8
#define NHD 8
#define HD 32
#define NREG 49
#define SREG 64
#define TOPK 4
#define M_TOK (BATCH*56*56)                 // 25088
#define SEQ_SIZE (BATCH*NHD*NREG*SREG*HD)   // 6422528

__device__ float g_Q[SEQ_SIZE];
__device__ float g_K[SEQ_SIZE];
__device__ float g_V[SEQ_SIZE];
__device__ float g_O[SEQ_SIZE];
__device__ float g_T[SEQ_SIZE];
__device__ float g_poolq[BATCH*NREG*256];
__device__ float g_poolk[BATCH*NREG*256];
__device__ int   g_topk[BATCH*NREG*TOPK];

// ---------------------------------------------------------------------------
// QKV GEMM (M=25088, N=768, K=256): 128x128 tile, 8x8 microtile.
// ---------------------------------------------------------------------------
__global__ void __launch_bounds__(256, 2)
qkv_gemm_kernel(const float* __restrict__ x,
                const float* __restrict__ wq,
                const float* __restrict__ bias)
{
    __shared__ float As[16][132];
    __shared__ float Bs[16][132];
    const int tx = threadIdx.x, ty = threadIdx.y;
    const int tid = ty * 16 + tx;
    const int m0 = blockIdx.y * 128, n0 = blockIdx.x * 128;

    float acc[8][8];
#pragma unroll
    for (int i = 0; i < 8; ++i)
#pragma unroll
        for (int j = 0; j < 8; ++j) acc[i][j] = 0.f;

    const int r0 = tid >> 2, c0 = tid & 3;

    for (int k0 = 0; k0 < 256; k0 += 16) {
#pragma unroll
        for (int p = 0; p < 2; ++p) {
            const int r = r0 + p * 64;
            float4 av = *(const float4*)&x [(m0 + r) * 256 + k0 + c0 * 4];
            float4 bv = *(const float4*)&wq[(n0 + r) * 256 + k0 + c0 * 4];
            As[c0*4+0][r] = av.x; As[c0*4+1][r] = av.y;
            As[c0*4+2][r] = av.z; As[c0*4+3][r] = av.w;
            Bs[c0*4+0][r] = bv.x; Bs[c0*4+1][r] = bv.y;
            Bs[c0*4+2][r] = bv.z; Bs[c0*4+3][r] = bv.w;
        }
        __syncthreads();
#pragma unroll
        for (int k = 0; k < 16; ++k) {
            float a[8], b[8];
            *(float4*)&a[0] = *(float4*)&As[k][ty * 8];
            *(float4*)&a[4] = *(float4*)&As[k][ty * 8 + 4];
            *(float4*)&b[0] = *(float4*)&Bs[k][tx * 8];
            *(float4*)&b[4] = *(float4*)&Bs[k][tx * 8 + 4];
#pragma unroll
            for (int i = 0; i < 8; ++i)
#pragma unroll
                for (int j = 0; j < 8; ++j) acc[i][j] = fmaf(a[i], b[j], acc[i][j]);
        }
        __syncthreads();
    }

    const int nbase = n0 + tx * 8;
    const int sec = nbase >> 8;
    const int cch = nbase & 255;
    const int mh  = cch >> 5, d0 = cch & 31;
    float* dst = (sec == 0) ? g_Q : (sec == 1 ? g_K : g_V);
    float bb[8];
    *(float4*)&bb[0] = *(const float4*)&bias[nbase];
    *(float4*)&bb[4] = *(const float4*)&bias[nbase + 4];

#pragma unroll
    for (int i = 0; i < 8; ++i) {
        int m  = m0 + ty * 8 + i;
        int b  = m / 3136;
        int hw = m - b * 3136;
        int h  = hw / 56;
        int w  = hw - h * 56;
        int r  = (h >> 3) * 7 + (w >> 3);
        int ss = ((h & 7) << 3) | (w & 7);
        int off = ((b * 8 + mh) * 49 + r) * 2048 + ss * 32 + d0;
        float4 v0 = make_float4(acc[i][0]+bb[0], acc[i][1]+bb[1], acc[i][2]+bb[2], acc[i][3]+bb[3]);
        float4 v1 = make_float4(acc[i][4]+bb[4], acc[i][5]+bb[5], acc[i][6]+bb[6], acc[i][7]+bb[7]);
        *(float4*)&dst[off]     = v0;
        *(float4*)&dst[off + 4] = v1;
    }
}

// ---------------------------------------------------------------------------
// Region average pooling of Q and K
// ---------------------------------------------------------------------------
__global__ void pool_kernel()
{
    const int b = blockIdx.x / 49, r = blockIdx.x % 49;
    const int c = threadIdx.x;
    const int mh = c >> 5, d = c & 31;
    const int base = ((b * 8 + mh) * 49 + r) * 2048 + d;
    float sq = 0.f, sk = 0.f;
#pragma unroll 8
    for (int s = 0; s < 64; ++s) {
        sq += g_Q[base + s * 32];
        sk += g_K[base + s * 32];
    }
    g_poolq[(b * 49 + r) * 256 + c] = sq * (1.f / 64.f);
    g_poolk[(b * 49 + r) * 256 + c] = sk * (1.f / 64.f);
}

// ---------------------------------------------------------------------------
// Coarse routing: top-4 region set per (b, region)
// ---------------------------------------------------------------------------
__global__ void route_kernel()
{
    const int b = blockIdx.x / 49, i = blockIdx.x % 49;
    __shared__ float qrow[256];
    __shared__ float scores[49];
    const int tid = threadIdx.x;
    qrow[tid] = g_poolq[(b * 49 + i) * 256 + tid];
    __syncthreads();
    const int warp = tid >> 5, lane = tid & 31;
    for (int j = warp; j < 49; j += 8) {
        const float* kr = g_poolk + (b * 49 + j) * 256;
        float s = 0.f;
#pragma unroll
        for (int cc = lane; cc < 256; cc += 32) s += qrow[cc] * kr[cc];
#pragma unroll
        for (int off = 16; off; off >>= 1) s += __shfl_xor_sync(0xffffffffu, s, off);
        if (lane == 0) scores[j] = s;
    }
    __syncthreads();
    if (tid == 0) {
        for (int t = 0; t < 4; ++t) {
            float bv = -INFINITY; int bj = 0;
            for (int j = 0; j < 49; ++j)
                if (scores[j] > bv) { bv = scores[j]; bj = j; }
            g_topk[(b * 49 + i) * 4 + t] = bj;
            scores[bj] = -INFINITY;
        }
    }
}

// ---------------------------------------------------------------------------
// Sparse attention per (b, head, region). 512 threads, 16 warps, 4 rows/warp.
// Token top-32 via exact binary bit-search (packed two-row REDUX counts) +
// ballot-ranked tie resolution (lowest index first, matching lax.top_k).
// ---------------------------------------------------------------------------
__device__ __forceinline__ unsigned fkey(float v) {
    unsigned u = __float_as_uint(v);
    return (u & 0x80000000u) ? ~u : (u | 0x80000000u);
}
__device__ __forceinline__ float fkeyinv(unsigned k) {
    return __uint_as_float((k & 0x80000000u) ? (k & 0x7fffffffu) : ~k);
}

__global__ void __launch_bounds__(512, 2) attn_kernel()
{
    extern __shared__ float smem[];
    float* Ks = smem;                       // 256 rows * stride 36 = 9216 f
    float* Vs = smem + 9216;                // 256*32 = 8192 f
    unsigned long long* plist =
        (unsigned long long*)(smem + 9216 + 8192);  // 16 warps * 64 u64 = 8192 B

    const int blk = blockIdx.x;
    const int b   = blk / (NHD * NREG);
    const int rem = blk % (NHD * NREG);
    const int mh  = rem / NREG;
    const int r   = rem % NREG;
    const int tid = threadIdx.x;
    const int qbase = ((b * 8 + mh) * 49 + r) * 2048;
    const float scale = 0.0625f;
    const unsigned FULL = 0xffffffffu;

#pragma unroll
    for (int t = 0; t < 4; ++t) {
        const int rr = g_topk[(b * 49 + r) * 4 + t];
        const int base = ((b * 8 + mh) * 49 + rr) * 2048;
        for (int idx = tid; idx < 2048; idx += 512) {
            Ks[(t * 64 + (idx >> 5)) * 36 + (idx & 31)] = g_K[base + idx];
            Vs[t * 2048 + idx] = g_V[base + idx];
        }
    }
    __syncthreads();

    const int warp = tid >> 5, lane = tid & 31;
    const unsigned lanelt = (1u << lane) - 1u;
    unsigned long long* myp = plist + warp * 64;

#pragma unroll 1
    for (int pr = 0; pr < 2; ++pr) {
        const int sA = warp * 4 + pr * 2, sB = sA + 1;

        // ---- scores: two rows share K smem traffic; q pre-scaled ----
        float aA[8], aB[8];
#pragma unroll
        for (int t = 0; t < 8; ++t) { aA[t] = 0.f; aB[t] = 0.f; }
        const float* qA = g_Q + qbase + sA * 32;
        const float* qB = g_Q + qbase + sB * 32;
#pragma unroll
        for (int i = 0; i < 8; ++i) {
            float4 q4A = *(const float4*)&qA[i * 4];
            float4 q4B = *(const float4*)&qB[i * 4];
            q4A.x *= scale; q4A.y *= scale; q4A.z *= scale; q4A.w *= scale;
            q4B.x *= scale; q4B.y *= scale; q4B.z *= scale; q4B.w *= scale;
#pragma unroll
            for (int t = 0; t < 8; ++t) {
                const float4 k4 = *(const float4*)&Ks[(t * 32 + lane) * 36 + i * 4];
                aA[t] = fmaf(q4A.x, k4.x, fmaf(q4A.y, k4.y,
                        fmaf(q4A.z, k4.z, fmaf(q4A.w, k4.w, aA[t]))));
                aB[t] = fmaf(q4B.x, k4.x, fmaf(q4B.y, k4.y,
                        fmaf(q4B.z, k4.z, fmaf(q4B.w, k4.w, aB[t]))));
            }
        }

        unsigned kA[8], kB[8], mxA = 0u, mxB = 0u;
#pragma unroll
        for (int t = 0; t < 8; ++t) {
            kA[t] = fkey(aA[t]);
            kB[t] = fkey(aB[t]);
            mxA = kA[t] > mxA ? kA[t] : mxA;
            mxB = kB[t] > mxB ? kB[t] : mxB;
        }
        mxA = __reduce_max_sync(FULL, mxA);
        mxB = __reduce_max_sync(FULL, mxB);
        const float mA = fkeyinv(mxA), mB = fkeyinv(mxB);

        // ---- exact 32nd-largest key via binary bit-search (packed counts) ----
        unsigned TA = 0u, TB = 0u;
#pragma unroll
        for (int bit = 31; bit >= 0; --bit) {
            const unsigned cA = TA | (1u << bit);
            const unsigned cB = TB | (1u << bit);
            unsigned n = 0;
#pragma unroll
            for (int t = 0; t < 8; ++t) {
                n += (kA[t] >= cA);
                n += (kB[t] >= cB) << 16;
            }
            n = __reduce_add_sync(FULL, n);
            if ((n & 0xffffu) >= 32) TA = cA;
            if ((n >> 16)     >= 32) TB = cB;
        }

        unsigned cg = 0;
#pragma unroll
        for (int t = 0; t < 8; ++t) {
            cg += (kA[t] > TA);
            cg += (kB[t] > TB) << 16;
        }
        cg = __reduce_add_sync(FULL, cg);
        const int extraA = 32 - (int)(cg & 0xffffu);
        const int extraB = 32 - (int)(cg >> 16);

        // ---- compaction: strict-greater all in; ties by lowest j ----
        __syncwarp();
        int offA = 0, tieA = 0, offB = 0, tieB = 0;
#pragma unroll
        for (int t = 0; t < 8; ++t) {
            {
                const bool gt = kA[t] > TA;
                const bool eq = kA[t] == TA;
                const unsigned meq = __ballot_sync(FULL, eq);
                const bool sel = gt || (eq && (tieA + __popc(meq & lanelt) < extraA));
                const unsigned msel = __ballot_sync(FULL, sel);
                if (sel) {
                    const int pos = offA + __popc(msel & lanelt);
                    const float w = __expf(fkeyinv(kA[t]) - mA);
                    myp[pos] = ((unsigned long long)__float_as_uint(w) << 32)
                             | (unsigned)(t * 32 + lane);
                }
                offA += __popc(msel);
                tieA += __popc(meq);
            }
            {
                const bool gt = kB[t] > TB;
                const bool eq = kB[t] == TB;
                const unsigned meq = __ballot_sync(FULL, eq);
                const bool sel = gt || (eq && (tieB + __popc(meq & lanelt) < extraB));
                const unsigned msel = __ballot_sync(FULL, sel);
                if (sel) {
                    const int pos = offB + __popc(msel & lanelt);
                    const float w = __expf(fkeyinv(kB[t]) - mB);
                    myp[32 + pos] = ((unsigned long long)__float_as_uint(w) << 32)
                                  | (unsigned)(t * 32 + lane);
                }
                offB += __popc(msel);
                tieB += __popc(meq);
            }
        }
        __syncwarp();

        // ---- fused softmax-normalize + AV over the 32-entry compact list ----
        float oA = 0.f, dA = 0.f, oB = 0.f, dB = 0.f;
#pragma unroll 8
        for (int i = 0; i < 32; ++i) {
            const unsigned long long pa = myp[i];
            const unsigned long long pb = myp[32 + i];
            const float wa = __uint_as_float((unsigned)(pa >> 32));
            const float wb = __uint_as_float((unsigned)(pb >> 32));
            const int ja = (int)(pa & 0xffffu);
            const int jb = (int)(pb & 0xffffu);
            dA += wa; dB += wb;
            oA = fmaf(wa, Vs[ja * 32 + lane], oA);
            oB = fmaf(wb, Vs[jb * 32 + lane], oB);
        }
        g_O[qbase + sA * 32 + lane] = oA / dA;
        g_O[qbase + sB * 32 + lane] = oB / dB;
        __syncwarp();
    }
}

// ---------------------------------------------------------------------------
// t = attn_out (seq->spatial) + LePE depthwise 3x3 over V, NHWC
// ---------------------------------------------------------------------------
__global__ void lepe_kernel(const float* __restrict__ lw,
                            const float* __restrict__ lb)
{
    const int idx = blockIdx.x * 256 + threadIdx.x;
    const int c   = idx & 255;
    const int pos = idx >> 8;
    const int w   = pos % 56;
    const int t2  = pos / 56;
    const int h   = t2 % 56;
    const int b   = t2 / 56;
    const int mh = c >> 5, d = c & 31;
    const int hbase = (b * 8 + mh) * 49;
    const int oaddr = (hbase + (h >> 3) * 7 + (w >> 3)) * 2048
                    + (((h & 7) << 3) | (w & 7)) * 32 + d;
    float acc = lb[c];
#pragma unroll
    for (int ky = 0; ky < 3; ++ky) {
        const int y = h + ky - 1;
        if (y < 0 || y >= 56) continue;
#pragma unroll
        for (int kx = 0; kx < 3; ++kx) {
            const int x = w + kx - 1;
            if (x < 0 || x >= 56) continue;
            const int va = (hbase + (y >> 3) * 7 + (x >> 3)) * 2048
                         + (((y & 7) << 3) | (x & 7)) * 32 + d;
            acc += g_V[va] * lw[c * 9 + ky * 3 + kx];
        }
    }
    g_T[idx] = g_O[oaddr] + acc;
}

// ---------------------------------------------------------------------------
// Output projection GEMM (M=25088, N=256, K=256), 128x128 tile, 8x8 micro.
// ---------------------------------------------------------------------------
__global__ void __launch_bounds__(256, 2)
out_gemm_kernel(const float* __restrict__ wo,
                const float* __restrict__ bo,
                float* __restrict__ out)
{
    __shared__ float As[16][132];
    __shared__ float Bs[16][132];
    const int tx = threadIdx.x, ty = threadIdx.y;
    const int tid = ty * 16 + tx;
    const int m0 = blockIdx.y * 128, n0 = blockIdx.x * 128;

    float acc[8][8];
#pragma unroll
    for (int i = 0; i < 8; ++i)
#pragma unroll
        for (int j = 0; j < 8; ++j) acc[i][j] = 0.f;

    const int r0 = tid >> 2, c0 = tid & 3;

    for (int k0 = 0; k0 < 256; k0 += 16) {
#pragma unroll
        for (int p = 0; p < 2; ++p) {
            const int r = r0 + p * 64;
            float4 av = *(const float4*)&g_T[(m0 + r) * 256 + k0 + c0 * 4];
            float4 bv = *(const float4*)&wo [(n0 + r) * 256 + k0 + c0 * 4];
            As[c0*4+0][r] = av.x; As[c0*4+1][r] = av.y;
            As[c0*4+2][r] = av.z; As[c0*4+3][r] = av.w;
            Bs[c0*4+0][r] = bv.x; Bs[c0*4+1][r] = bv.y;
            Bs[c0*4+2][r] = bv.z; Bs[c0*4+3][r] = bv.w;
        }
        __syncthreads();
#pragma unroll
        for (int k = 0; k < 16; ++k) {
            float a[8], b[8];
            *(float4*)&a[0] = *(float4*)&As[k][ty * 8];
            *(float4*)&a[4] = *(float4*)&As[k][ty * 8 + 4];
            *(float4*)&b[0] = *(float4*)&Bs[k][tx * 8];
            *(float4*)&b[4] = *(float4*)&Bs[k][tx * 8 + 4];
#pragma unroll
            for (int i = 0; i < 8; ++i)
#pragma unroll
                for (int j = 0; j < 8; ++j) acc[i][j] = fmaf(a[i], b[j], acc[i][j]);
        }
        __syncthreads();
    }

    const int nbase = n0 + tx * 8;
    float bb[8];
    *(float4*)&bb[0] = *(const float4*)&bo[nbase];
    *(float4*)&bb[4] = *(const float4*)&bo[nbase + 4];
#pragma unroll
    for (int i = 0; i < 8; ++i) {
        const int m = m0 + ty * 8 + i;
        float4 v0 = make_float4(acc[i][0]+bb[0], acc[i][1]+bb[1], acc[i][2]+bb[2], acc[i][3]+bb[3]);
        float4 v1 = make_float4(acc[i][4]+bb[4], acc[i][5]+bb[5], acc[i][6]+bb[6], acc[i][7]+bb[7]);
        *(float4*)&out[m * 256 + nbase]     = v0;
        *(float4*)&out[m * 256 + nbase + 4] = v1;
    }
}

// ---------------------------------------------------------------------------
extern "C" void kernel_launch(void* const* d_in, const int* in_sizes, int n_in,
                              void* d_out, int out_size)
{
    const float* x      = (const float*)d_in[0];
    const float* qkv_w  = (const float*)d_in[1];
    const float* qkv_b  = (const float*)d_in[2];
    const float* lepe_w = (const float*)d_in[3];
    const float* lepe_b = (const float*)d_in[4];
    const float* out_w  = (const float*)d_in[5];
    const float* out_b  = (const float*)d_in[6];
    float* out = (float*)d_out;

    const int attn_smem = (9216 + 8192) * 4 + 16 * 64 * 8;   // 77824 B
    cudaFuncSetAttribute(attn_kernel, cudaFuncAttributeMaxDynamicSharedMemorySize, attn_smem);

    qkv_gemm_kernel<<<dim3(6, 196), dim3(16, 16)>>>(x, qkv_w, qkv_b);
    pool_kernel<<<392, 256>>>();
    route_kernel<<<392, 256>>>();
    attn_kernel<<<BATCH * NHD * NREG, 512, attn_smem>>>();
    lepe_kernel<<<M_TOK, 256>>>(lepe_w, lepe_b);
    out_gemm_kernel<<<dim3(2, 196), dim3(16, 16)>>>(out_w, out_b, out);
}

// round 6
// speedup vs baseline: 1.9454x; 1.1074x over previous
#include <cuda_runtime.h>
#include <math.h>

#define BATCH 8
#define NHD 8
#define HD 32
#define NREG 49
#define SREG 64
#define TOPK 4
#define M_TOK (BATCH*56*56)                 // 25088
#define SEQ_SIZE (BATCH*NHD*NREG*SREG*HD)   // 6422528

__device__ float g_Q[SEQ_SIZE];
__device__ float g_K[SEQ_SIZE];
__device__ float g_V[SEQ_SIZE];
__device__ float g_O[SEQ_SIZE];
__device__ float g_T[SEQ_SIZE];
__device__ float g_poolq[BATCH*NREG*256];
__device__ float g_poolk[BATCH*NREG*256];
__device__ int   g_topk[BATCH*NREG*TOPK];

// ---------------------------------------------------------------------------
// QKV GEMM (M=25088, N=768, K=256): 128x128 tile, 8x8 microtile.
// ---------------------------------------------------------------------------
__global__ void __launch_bounds__(256, 2)
qkv_gemm_kernel(const float* __restrict__ x,
                const float* __restrict__ wq,
                const float* __restrict__ bias)
{
    __shared__ float As[16][132];
    __shared__ float Bs[16][132];
    const int tx = threadIdx.x, ty = threadIdx.y;
    const int tid = ty * 16 + tx;
    const int m0 = blockIdx.y * 128, n0 = blockIdx.x * 128;

    float acc[8][8];
#pragma unroll
    for (int i = 0; i < 8; ++i)
#pragma unroll
        for (int j = 0; j < 8; ++j) acc[i][j] = 0.f;

    const int r0 = tid >> 2, c0 = tid & 3;

    for (int k0 = 0; k0 < 256; k0 += 16) {
#pragma unroll
        for (int p = 0; p < 2; ++p) {
            const int r = r0 + p * 64;
            float4 av = *(const float4*)&x [(m0 + r) * 256 + k0 + c0 * 4];
            float4 bv = *(const float4*)&wq[(n0 + r) * 256 + k0 + c0 * 4];
            As[c0*4+0][r] = av.x; As[c0*4+1][r] = av.y;
            As[c0*4+2][r] = av.z; As[c0*4+3][r] = av.w;
            Bs[c0*4+0][r] = bv.x; Bs[c0*4+1][r] = bv.y;
            Bs[c0*4+2][r] = bv.z; Bs[c0*4+3][r] = bv.w;
        }
        __syncthreads();
#pragma unroll
        for (int k = 0; k < 16; ++k) {
            float a[8], b[8];
            *(float4*)&a[0] = *(float4*)&As[k][ty * 8];
            *(float4*)&a[4] = *(float4*)&As[k][ty * 8 + 4];
            *(float4*)&b[0] = *(float4*)&Bs[k][tx * 8];
            *(float4*)&b[4] = *(float4*)&Bs[k][tx * 8 + 4];
#pragma unroll
            for (int i = 0; i < 8; ++i)
#pragma unroll
                for (int j = 0; j < 8; ++j) acc[i][j] = fmaf(a[i], b[j], acc[i][j]);
        }
        __syncthreads();
    }

    const int nbase = n0 + tx * 8;
    const int sec = nbase >> 8;
    const int cch = nbase & 255;
    const int mh  = cch >> 5, d0 = cch & 31;
    float* dst = (sec == 0) ? g_Q : (sec == 1 ? g_K : g_V);
    float bb[8];
    *(float4*)&bb[0] = *(const float4*)&bias[nbase];
    *(float4*)&bb[4] = *(const float4*)&bias[nbase + 4];

#pragma unroll
    for (int i = 0; i < 8; ++i) {
        int m  = m0 + ty * 8 + i;
        int b  = m / 3136;
        int hw = m - b * 3136;
        int h  = hw / 56;
        int w  = hw - h * 56;
        int r  = (h >> 3) * 7 + (w >> 3);
        int ss = ((h & 7) << 3) | (w & 7);
        int off = ((b * 8 + mh) * 49 + r) * 2048 + ss * 32 + d0;
        float4 v0 = make_float4(acc[i][0]+bb[0], acc[i][1]+bb[1], acc[i][2]+bb[2], acc[i][3]+bb[3]);
        float4 v1 = make_float4(acc[i][4]+bb[4], acc[i][5]+bb[5], acc[i][6]+bb[6], acc[i][7]+bb[7]);
        *(float4*)&dst[off]     = v0;
        *(float4*)&dst[off + 4] = v1;
    }
}

// ---------------------------------------------------------------------------
// Region average pooling of Q and K
// ---------------------------------------------------------------------------
__global__ void pool_kernel()
{
    const int b = blockIdx.x / 49, r = blockIdx.x % 49;
    const int c = threadIdx.x;
    const int mh = c >> 5, d = c & 31;
    const int base = ((b * 8 + mh) * 49 + r) * 2048 + d;
    float sq = 0.f, sk = 0.f;
#pragma unroll 8
    for (int s = 0; s < 64; ++s) {
        sq += g_Q[base + s * 32];
        sk += g_K[base + s * 32];
    }
    g_poolq[(b * 49 + r) * 256 + c] = sq * (1.f / 64.f);
    g_poolk[(b * 49 + r) * 256 + c] = sk * (1.f / 64.f);
}

// ---------------------------------------------------------------------------
// Coarse routing: top-4 region set per (b, region)
// ---------------------------------------------------------------------------
__global__ void route_kernel()
{
    const int b = blockIdx.x / 49, i = blockIdx.x % 49;
    __shared__ float qrow[256];
    __shared__ float scores[49];
    const int tid = threadIdx.x;
    qrow[tid] = g_poolq[(b * 49 + i) * 256 + tid];
    __syncthreads();
    const int warp = tid >> 5, lane = tid & 31;
    for (int j = warp; j < 49; j += 8) {
        const float* kr = g_poolk + (b * 49 + j) * 256;
        float s = 0.f;
#pragma unroll
        for (int cc = lane; cc < 256; cc += 32) s += qrow[cc] * kr[cc];
#pragma unroll
        for (int off = 16; off; off >>= 1) s += __shfl_xor_sync(0xffffffffu, s, off);
        if (lane == 0) scores[j] = s;
    }
    __syncthreads();
    if (tid == 0) {
        for (int t = 0; t < 4; ++t) {
            float bv = -INFINITY; int bj = 0;
            for (int j = 0; j < 49; ++j)
                if (scores[j] > bv) { bv = scores[j]; bj = j; }
            g_topk[(b * 49 + i) * 4 + t] = bj;
            scores[bj] = -INFINITY;
        }
    }
}

// ---------------------------------------------------------------------------
// Sparse attention per (b, head, region). 512 threads, 16 warps, 4 rows/warp.
// Token top-32: 16-step bit-search on the top 16 key bits (two rows packed
// per REDUX) + exact full-key tail resolution within the boundary bucket
// (ties -> lowest index, matching lax.top_k). Scores use ascending-d fmaf
// accumulation + post-scale to match the reference's selection sets.
// ---------------------------------------------------------------------------
__device__ __forceinline__ unsigned fkey(float v) {
    unsigned u = __float_as_uint(v);
    return (u & 0x80000000u) ? ~u : (u | 0x80000000u);
}
__device__ __forceinline__ float fkeyinv(unsigned k) {
    return __uint_as_float((k & 0x80000000u) ? (k & 0x7fffffffu) : ~k);
}

__global__ void __launch_bounds__(512, 2) attn_kernel()
{
    extern __shared__ float smem[];
    float* Ks = smem;                       // 256 rows * stride 36 = 9216 f
    float* Vs = smem + 9216;                // 256*32 = 8192 f
    unsigned long long* plist =
        (unsigned long long*)(smem + 9216 + 8192);  // 16 warps * 64 u64 = 8192 B

    const int blk = blockIdx.x;
    const int b   = blk / (NHD * NREG);
    const int rem = blk % (NHD * NREG);
    const int mh  = rem / NREG;
    const int r   = rem % NREG;
    const int tid = threadIdx.x;
    const int qbase = ((b * 8 + mh) * 49 + r) * 2048;
    const float scale = 0.0625f;
    const unsigned FULL = 0xffffffffu;

#pragma unroll
    for (int t = 0; t < 4; ++t) {
        const int rr = g_topk[(b * 49 + r) * 4 + t];
        const int base = ((b * 8 + mh) * 49 + rr) * 2048;
        for (int idx = tid; idx < 2048; idx += 512) {
            Ks[(t * 64 + (idx >> 5)) * 36 + (idx & 31)] = g_K[base + idx];
            Vs[t * 2048 + idx] = g_V[base + idx];
        }
    }
    __syncthreads();

    const int warp = tid >> 5, lane = tid & 31;
    const unsigned lanelt = (1u << lane) - 1u;
    unsigned long long* myp = plist + warp * 64;

#pragma unroll 1
    for (int pr = 0; pr < 2; ++pr) {
        const int sA = warp * 4 + pr * 2, sB = sA + 1;

        // ---- scores: ascending-d fmaf accumulation (matches reference sets) --
        float aA[8], aB[8];
#pragma unroll
        for (int t = 0; t < 8; ++t) { aA[t] = 0.f; aB[t] = 0.f; }
        const float* qA = g_Q + qbase + sA * 32;
        const float* qB = g_Q + qbase + sB * 32;
#pragma unroll
        for (int i = 0; i < 8; ++i) {
            const float4 q4A = *(const float4*)&qA[i * 4];
            const float4 q4B = *(const float4*)&qB[i * 4];
#pragma unroll
            for (int t = 0; t < 8; ++t) {
                const float4 k4 = *(const float4*)&Ks[(t * 32 + lane) * 36 + i * 4];
                aA[t] = fmaf(q4A.x, k4.x, aA[t]);
                aA[t] = fmaf(q4A.y, k4.y, aA[t]);
                aA[t] = fmaf(q4A.z, k4.z, aA[t]);
                aA[t] = fmaf(q4A.w, k4.w, aA[t]);
                aB[t] = fmaf(q4B.x, k4.x, aB[t]);
                aB[t] = fmaf(q4B.y, k4.y, aB[t]);
                aB[t] = fmaf(q4B.z, k4.z, aB[t]);
                aB[t] = fmaf(q4B.w, k4.w, aB[t]);
            }
        }

        unsigned kA[8], kB[8], mxA = 0u, mxB = 0u;
#pragma unroll
        for (int t = 0; t < 8; ++t) {
            kA[t] = fkey(aA[t] * scale);
            kB[t] = fkey(aB[t] * scale);
            mxA = kA[t] > mxA ? kA[t] : mxA;
            mxB = kB[t] > mxB ? kB[t] : mxB;
        }
        mxA = __reduce_max_sync(FULL, mxA);
        mxB = __reduce_max_sync(FULL, mxB);
        const float mA = fkeyinv(mxA), mB = fkeyinv(mxB);

        // ---- 16-step bit-search on top 16 key bits (both rows packed) ----
        unsigned TA = 0u, TB = 0u;
#pragma unroll
        for (int bit = 15; bit >= 0; --bit) {
            const unsigned cA = (TA | (1u << bit)) << 16;
            const unsigned cB = (TB | (1u << bit)) << 16;
            unsigned n = 0;
#pragma unroll
            for (int t = 0; t < 8; ++t) {
                n += (kA[t] >= cA);
                n += (kB[t] >= cB) << 16;
            }
            n = __reduce_add_sync(FULL, n);
            if ((n & 0xffffu) >= 32) TA |= 1u << bit;
            if ((n >> 16)     >= 32) TB |= 1u << bit;
        }
        const unsigned thrA = (TA + 1u) << 16;   // full keys >= thrA are in
        const unsigned thrB = (TB + 1u) << 16;
        const unsigned loA  = TA << 16;          // bucket: [loA, thrA)
        const unsigned loB  = TB << 16;

        // ---- compaction of definite winners + bucket candidate build ----
        __syncwarp();
        unsigned candA[8], candB[8];
        int posA = 0, posB = 0;
#pragma unroll
        for (int t = 0; t < 8; ++t) {
            const unsigned j = (unsigned)(t * 32 + lane);
            {
                const bool sel = kA[t] >= thrA;
                const unsigned ms = __ballot_sync(FULL, sel);
                if (sel) {
                    const float w = __expf(fkeyinv(kA[t]) - mA);
                    myp[posA + __popc(ms & lanelt)] =
                        ((unsigned long long)__float_as_uint(w) << 32) | j;
                }
                candA[t] = (!sel && kA[t] >= loA)
                         ? (((kA[t] & 0xffffu) << 8) | (255u - j) | (1u << 24)) : 0u;
                posA += __popc(ms);
            }
            {
                const bool sel = kB[t] >= thrB;
                const unsigned ms = __ballot_sync(FULL, sel);
                if (sel) {
                    const float w = __expf(fkeyinv(kB[t]) - mB);
                    myp[32 + posB + __popc(ms & lanelt)] =
                        ((unsigned long long)__float_as_uint(w) << 32) | j;
                }
                candB[t] = (!sel && kB[t] >= loB)
                         ? (((kB[t] & 0xffffu) << 8) | (255u - j) | (1u << 24)) : 0u;
                posB += __popc(ms);
            }
        }

        // ---- exact tail: pop (32-posA) largest full keys from bucket A ----
        while (posA < 32) {
            unsigned lm = candA[0];
#pragma unroll
            for (int t = 1; t < 8; ++t) lm = candA[t] > lm ? candA[t] : lm;
            const unsigned wm = __reduce_max_sync(FULL, lm);
            if (lm == wm) {
#pragma unroll
                for (int t = 0; t < 8; ++t) {
                    if (candA[t] == wm) {
                        const unsigned key = loA | ((wm >> 8) & 0xffffu);
                        const float w = __expf(fkeyinv(key) - mA);
                        myp[posA] = ((unsigned long long)__float_as_uint(w) << 32)
                                  | (255u - (wm & 0xffu));
                        candA[t] = 0u;
                    }
                }
            }
            ++posA;
        }
        while (posB < 32) {
            unsigned lm = candB[0];
#pragma unroll
            for (int t = 1; t < 8; ++t) lm = candB[t] > lm ? candB[t] : lm;
            const unsigned wm = __reduce_max_sync(FULL, lm);
            if (lm == wm) {
#pragma unroll
                for (int t = 0; t < 8; ++t) {
                    if (candB[t] == wm) {
                        const unsigned key = loB | ((wm >> 8) & 0xffffu);
                        const float w = __expf(fkeyinv(key) - mB);
                        myp[32 + posB] = ((unsigned long long)__float_as_uint(w) << 32)
                                       | (255u - (wm & 0xffu));
                        candB[t] = 0u;
                    }
                }
            }
            ++posB;
        }
        __syncwarp();

        // ---- fused softmax-normalize + AV over the 32-entry compact list ----
        float oA = 0.f, dA = 0.f, oB = 0.f, dB = 0.f;
#pragma unroll 8
        for (int i = 0; i < 32; ++i) {
            const unsigned long long pa = myp[i];
            const unsigned long long pb = myp[32 + i];
            const float wa = __uint_as_float((unsigned)(pa >> 32));
            const float wb = __uint_as_float((unsigned)(pb >> 32));
            const int ja = (int)(pa & 0xffffu);
            const int jb = (int)(pb & 0xffffu);
            dA += wa; dB += wb;
            oA = fmaf(wa, Vs[ja * 32 + lane], oA);
            oB = fmaf(wb, Vs[jb * 32 + lane], oB);
        }
        g_O[qbase + sA * 32 + lane] = oA / dA;
        g_O[qbase + sB * 32 + lane] = oB / dB;
        __syncwarp();
    }
}

// ---------------------------------------------------------------------------
// t = attn_out (seq->spatial) + LePE depthwise 3x3 over V, NHWC
// ---------------------------------------------------------------------------
__global__ void lepe_kernel(const float* __restrict__ lw,
                            const float* __restrict__ lb)
{
    const int idx = blockIdx.x * 256 + threadIdx.x;
    const int c   = idx & 255;
    const int pos = idx >> 8;
    const int w   = pos % 56;
    const int t2  = pos / 56;
    const int h   = t2 % 56;
    const int b   = t2 / 56;
    const int mh = c >> 5, d = c & 31;
    const int hbase = (b * 8 + mh) * 49;
    const int oaddr = (hbase + (h >> 3) * 7 + (w >> 3)) * 2048
                    + (((h & 7) << 3) | (w & 7)) * 32 + d;
    float acc = lb[c];
#pragma unroll
    for (int ky = 0; ky < 3; ++ky) {
        const int y = h + ky - 1;
        if (y < 0 || y >= 56) continue;
#pragma unroll
        for (int kx = 0; kx < 3; ++kx) {
            const int x = w + kx - 1;
            if (x < 0 || x >= 56) continue;
            const int va = (hbase + (y >> 3) * 7 + (x >> 3)) * 2048
                         + (((y & 7) << 3) | (x & 7)) * 32 + d;
            acc += g_V[va] * lw[c * 9 + ky * 3 + kx];
        }
    }
    g_T[idx] = g_O[oaddr] + acc;
}

// ---------------------------------------------------------------------------
// Output projection GEMM (M=25088, N=256, K=256), 128x128 tile, 8x8 micro.
// ---------------------------------------------------------------------------
__global__ void __launch_bounds__(256, 2)
out_gemm_kernel(const float* __restrict__ wo,
                const float* __restrict__ bo,
                float* __restrict__ out)
{
    __shared__ float As[16][132];
    __shared__ float Bs[16][132];
    const int tx = threadIdx.x, ty = threadIdx.y;
    const int tid = ty * 16 + tx;
    const int m0 = blockIdx.y * 128, n0 = blockIdx.x * 128;

    float acc[8][8];
#pragma unroll
    for (int i = 0; i < 8; ++i)
#pragma unroll
        for (int j = 0; j < 8; ++j) acc[i][j] = 0.f;

    const int r0 = tid >> 2, c0 = tid & 3;

    for (int k0 = 0; k0 < 256; k0 += 16) {
#pragma unroll
        for (int p = 0; p < 2; ++p) {
            const int r = r0 + p * 64;
            float4 av = *(const float4*)&g_T[(m0 + r) * 256 + k0 + c0 * 4];
            float4 bv = *(const float4*)&wo [(n0 + r) * 256 + k0 + c0 * 4];
            As[c0*4+0][r] = av.x; As[c0*4+1][r] = av.y;
            As[c0*4+2][r] = av.z; As[c0*4+3][r] = av.w;
            Bs[c0*4+0][r] = bv.x; Bs[c0*4+1][r] = bv.y;
            Bs[c0*4+2][r] = bv.z; Bs[c0*4+3][r] = bv.w;
        }
        __syncthreads();
#pragma unroll
        for (int k = 0; k < 16; ++k) {
            float a[8], b[8];
            *(float4*)&a[0] = *(float4*)&As[k][ty * 8];
            *(float4*)&a[4] = *(float4*)&As[k][ty * 8 + 4];
            *(float4*)&b[0] = *(float4*)&Bs[k][tx * 8];
            *(float4*)&b[4] = *(float4*)&Bs[k][tx * 8 + 4];
#pragma unroll
            for (int i = 0; i < 8; ++i)
#pragma unroll
                for (int j = 0; j < 8; ++j) acc[i][j] = fmaf(a[i], b[j], acc[i][j]);
        }
        __syncthreads();
    }

    const int nbase = n0 + tx * 8;
    float bb[8];
    *(float4*)&bb[0] = *(const float4*)&bo[nbase];
    *(float4*)&bb[4] = *(const float4*)&bo[nbase + 4];
#pragma unroll
    for (int i = 0; i < 8; ++i) {
        const int m = m0 + ty * 8 + i;
        float4 v0 = make_float4(acc[i][0]+bb[0], acc[i][1]+bb[1], acc[i][2]+bb[2], acc[i][3]+bb[3]);
        float4 v1 = make_float4(acc[i][4]+bb[4], acc[i][5]+bb[5], acc[i][6]+bb[6], acc[i][7]+bb[7]);
        *(float4*)&out[m * 256 + nbase]     = v0;
        *(float4*)&out[m * 256 + nbase + 4] = v1;
    }
}

// ---------------------------------------------------------------------------
extern "C" void kernel_launch(void* const* d_in, const int* in_sizes, int n_in,
                              void* d_out, int out_size)
{
    const float* x      = (const float*)d_in[0];
    const float* qkv_w  = (const float*)d_in[1];
    const float* qkv_b  = (const float*)d_in[2];
    const float* lepe_w = (const float*)d_in[3];
    const float* lepe_b = (const float*)d_in[4];
    const float* out_w  = (const float*)d_in[5];
    const float* out_b  = (const float*)d_in[6];
    float* out = (float*)d_out;

    const int attn_smem = (9216 + 8192) * 4 + 16 * 64 * 8;   // 77824 B
    cudaFuncSetAttribute(attn_kernel, cudaFuncAttributeMaxDynamicSharedMemorySize, attn_smem);

    qkv_gemm_kernel<<<dim3(6, 196), dim3(16, 16)>>>(x, qkv_w, qkv_b);
    pool_kernel<<<392, 256>>>();
    route_kernel<<<392, 256>>>();
    attn_kernel<<<BATCH * NHD * NREG, 512, attn_smem>>>();
    lepe_kernel<<<M_TOK, 256>>>(lepe_w, lepe_b);
    out_gemm_kernel<<<dim3(2, 196), dim3(16, 16)>>>(out_w, out_b, out);
}

// round 8
// speedup vs baseline: 1.9507x; 1.0028x over previous
#include <cuda_runtime.h>
#include <math.h>

#define BATCH 8
#define NHD 8
#define HD 32
#define NREG 49
#define SREG 64
#define TOPK 4
#define M_TOK (BATCH*56*56)                 // 25088
#define SEQ_SIZE (BATCH*NHD*NREG*SREG*HD)   // 6422528

__device__ float g_Q[SEQ_SIZE];
__device__ float g_K[SEQ_SIZE];
__device__ float g_V[SEQ_SIZE];
__device__ float g_O[SEQ_SIZE];
__device__ float g_T[SEQ_SIZE];
__device__ float g_poolq[BATCH*NREG*256];
__device__ float g_poolk[BATCH*NREG*256];
__device__ int   g_topk[BATCH*NREG*TOPK];

// ---- packed fp32x2 helpers (two independent IEEE fp32 ops -> bit-exact) ----
__device__ __forceinline__ unsigned long long pk2(float lo, float hi) {
    unsigned long long d;
    asm("mov.b64 %0, {%1, %2};" : "=l"(d)
        : "r"(__float_as_uint(lo)), "r"(__float_as_uint(hi)));
    return d;
}
__device__ __forceinline__ void upk2(unsigned long long v, float& lo, float& hi) {
    unsigned a, b;
    asm("mov.b64 {%0, %1}, %2;" : "=r"(a), "=r"(b) : "l"(v));
    lo = __uint_as_float(a); hi = __uint_as_float(b);
}
__device__ __forceinline__ void ffma2(unsigned long long& acc,
                                      unsigned long long a, unsigned long long b) {
    asm("fma.rn.f32x2 %0, %1, %2, %3;" : "=l"(acc) : "l"(a), "l"(b), "l"(acc));
}

// ---------------------------------------------------------------------------
// QKV GEMM (M=25088, N=768, K=256): 128x128 tile, 8x8 microtile, f32x2.
// ---------------------------------------------------------------------------
__global__ void __launch_bounds__(256, 2)
qkv_gemm_kernel(const float* __restrict__ x,
                const float* __restrict__ wq,
                const float* __restrict__ bias)
{
    __shared__ float As[16][132];
    __shared__ float Bs[16][132];
    const int tx = threadIdx.x, ty = threadIdx.y;
    const int tid = ty * 16 + tx;
    const int m0 = blockIdx.y * 128, n0 = blockIdx.x * 128;

    unsigned long long acc2[8][4];
#pragma unroll
    for (int i = 0; i < 8; ++i)
#pragma unroll
        for (int j = 0; j < 4; ++j) acc2[i][j] = 0ull;

    const int r0 = tid >> 2, c0 = tid & 3;

    for (int k0 = 0; k0 < 256; k0 += 16) {
#pragma unroll
        for (int p = 0; p < 2; ++p) {
            const int r = r0 + p * 64;
            float4 av = *(const float4*)&x [(m0 + r) * 256 + k0 + c0 * 4];
            float4 bv = *(const float4*)&wq[(n0 + r) * 256 + k0 + c0 * 4];
            As[c0*4+0][r] = av.x; As[c0*4+1][r] = av.y;
            As[c0*4+2][r] = av.z; As[c0*4+3][r] = av.w;
            Bs[c0*4+0][r] = bv.x; Bs[c0*4+1][r] = bv.y;
            Bs[c0*4+2][r] = bv.z; Bs[c0*4+3][r] = bv.w;
        }
        __syncthreads();
#pragma unroll
        for (int k = 0; k < 16; ++k) {
            float a[8];
            *(float4*)&a[0] = *(float4*)&As[k][ty * 8];
            *(float4*)&a[4] = *(float4*)&As[k][ty * 8 + 4];
            const ulonglong2 b01 = *(const ulonglong2*)&Bs[k][tx * 8];
            const ulonglong2 b23 = *(const ulonglong2*)&Bs[k][tx * 8 + 4];
#pragma unroll
            for (int i = 0; i < 8; ++i) {
                const unsigned long long ap = pk2(a[i], a[i]);
                ffma2(acc2[i][0], ap, b01.x);
                ffma2(acc2[i][1], ap, b01.y);
                ffma2(acc2[i][2], ap, b23.x);
                ffma2(acc2[i][3], ap, b23.y);
            }
        }
        __syncthreads();
    }

    const int nbase = n0 + tx * 8;
    const int sec = nbase >> 8;
    const int cch = nbase & 255;
    const int mh  = cch >> 5, d0 = cch & 31;
    float* dst = (sec == 0) ? g_Q : (sec == 1 ? g_K : g_V);
    float bb[8];
    *(float4*)&bb[0] = *(const float4*)&bias[nbase];
    *(float4*)&bb[4] = *(const float4*)&bias[nbase + 4];

#pragma unroll
    for (int i = 0; i < 8; ++i) {
        int m  = m0 + ty * 8 + i;
        int b  = m / 3136;
        int hw = m - b * 3136;
        int h  = hw / 56;
        int w  = hw - h * 56;
        int rg = (h >> 3) * 7 + (w >> 3);
        int ss = ((h & 7) << 3) | (w & 7);
        int off = ((b * 8 + mh) * 49 + rg) * 2048 + ss * 32 + d0;
        float ac[8];
#pragma unroll
        for (int j = 0; j < 4; ++j) upk2(acc2[i][j], ac[2*j], ac[2*j+1]);
        float4 v0 = make_float4(ac[0]+bb[0], ac[1]+bb[1], ac[2]+bb[2], ac[3]+bb[3]);
        float4 v1 = make_float4(ac[4]+bb[4], ac[5]+bb[5], ac[6]+bb[6], ac[7]+bb[7]);
        *(float4*)&dst[off]     = v0;
        *(float4*)&dst[off + 4] = v1;
    }
}

// ---------------------------------------------------------------------------
// Region average pooling of Q and K
// ---------------------------------------------------------------------------
__global__ void pool_kernel()
{
    const int b = blockIdx.x / 49, r = blockIdx.x % 49;
    const int c = threadIdx.x;
    const int mh = c >> 5, d = c & 31;
    const int base = ((b * 8 + mh) * 49 + r) * 2048 + d;
    float sq = 0.f, sk = 0.f;
#pragma unroll 8
    for (int s = 0; s < 64; ++s) {
        sq += g_Q[base + s * 32];
        sk += g_K[base + s * 32];
    }
    g_poolq[(b * 49 + r) * 256 + c] = sq * (1.f / 64.f);
    g_poolk[(b * 49 + r) * 256 + c] = sk * (1.f / 64.f);
}

// ---------------------------------------------------------------------------
// Coarse routing: top-4 region set per (b, region)
// ---------------------------------------------------------------------------
__global__ void route_kernel()
{
    const int b = blockIdx.x / 49, i = blockIdx.x % 49;
    __shared__ float qrow[256];
    __shared__ float scores[49];
    const int tid = threadIdx.x;
    qrow[tid] = g_poolq[(b * 49 + i) * 256 + tid];
    __syncthreads();
    const int warp = tid >> 5, lane = tid & 31;
    for (int j = warp; j < 49; j += 8) {
        const float* kr = g_poolk + (b * 49 + j) * 256;
        float s = 0.f;
#pragma unroll
        for (int cc = lane; cc < 256; cc += 32) s += qrow[cc] * kr[cc];
#pragma unroll
        for (int off = 16; off; off >>= 1) s += __shfl_xor_sync(0xffffffffu, s, off);
        if (lane == 0) scores[j] = s;
    }
    __syncthreads();
    if (tid == 0) {
        for (int t = 0; t < 4; ++t) {
            float bv = -INFINITY; int bj = 0;
            for (int j = 0; j < 49; ++j)
                if (scores[j] > bv) { bv = scores[j]; bj = j; }
            g_topk[(b * 49 + i) * 4 + t] = bj;
            scores[bj] = -INFINITY;
        }
    }
}

// ---------------------------------------------------------------------------
// Sparse attention per (b, head, region). 512 threads, 16 warps, 4 rows/warp.
// f32x2 packed score phase (pair-interleaved K smem), 16-step bit-search on
// top 16 key bits + exact tail (ties -> lowest index, matching lax.top_k).
// All fp arithmetic bit-identical to the scalar R5 version.
// ---------------------------------------------------------------------------
__device__ __forceinline__ unsigned fkey(float v) {
    unsigned u = __float_as_uint(v);
    return (u & 0x80000000u) ? ~u : (u | 0x80000000u);
}
__device__ __forceinline__ float fkeyinv(unsigned k) {
    return __uint_as_float((k & 0x80000000u) ? (k & 0x7fffffffu) : ~k);
}

__global__ void __launch_bounds__(512, 2) attn_kernel()
{
    extern __shared__ float smem[];
    float* Kp = smem;                       // pair-interleaved K: 8192 f = 32KB
    float* Vs = smem + 8192;                // 256*32 = 8192 f = 32KB
    unsigned long long* plist =
        (unsigned long long*)(smem + 16384); // 16 warps * 64 u64 = 8KB

    const int blk = blockIdx.x;
    const int b   = blk / (NHD * NREG);
    const int rem = blk % (NHD * NREG);
    const int mh  = rem / NREG;
    const int r   = rem % NREG;
    const int tid = threadIdx.x;
    const int qbase = ((b * 8 + mh) * 49 + r) * 2048;
    const float scale = 0.0625f;
    const unsigned FULL = 0xffffffffu;

    // V tiles (vectorized) + K in pair-interleaved layout:
    // Kp[((u*16+dp)*32+ln)*4 + {0..3}] = (K[64u+ln][2dp], K[64u+32+ln][2dp],
    //                                     K[64u+ln][2dp+1], K[64u+32+ln][2dp+1])
    {
        const int dp = (tid >> 5) & 15;
        const int ln = tid & 31;
#pragma unroll
        for (int t = 0; t < 4; ++t) {
            const int rr = g_topk[(b * 49 + r) * 4 + t];
            const int base = ((b * 8 + mh) * 49 + rr) * 2048;
            *(float4*)&Vs[t * 2048 + tid * 4] = *(const float4*)&g_V[base + tid * 4];
            const float2 va = *(const float2*)&g_K[base + ln * 32 + dp * 2];
            const float2 vb = *(const float2*)&g_K[base + (ln + 32) * 32 + dp * 2];
            *(float4*)&Kp[((t * 16 + dp) * 32 + ln) * 4] =
                make_float4(va.x, vb.x, va.y, vb.y);
        }
    }
    __syncthreads();

    const int warp = tid >> 5, lane = tid & 31;
    const unsigned lanelt = (1u << lane) - 1u;
    unsigned long long* myp = plist + warp * 64;
    const char* Vb = (const char*)Vs;
    const int laneoff = lane * 4;

#pragma unroll 1
    for (int pr = 0; pr < 2; ++pr) {
        const int sA = warp * 4 + pr * 2, sB = sA + 1;

        // ---- packed scores: lo half = even t, hi half = odd t; each half
        //      accumulates in exact ascending-d order ----
        unsigned long long accA[4], accB[4];
#pragma unroll
        for (int u = 0; u < 4; ++u) { accA[u] = 0ull; accB[u] = 0ull; }
        const float* qA = g_Q + qbase + sA * 32;
        const float* qB = g_Q + qbase + sB * 32;
#pragma unroll
        for (int dp = 0; dp < 16; ++dp) {
            const float2 qa = *(const float2*)&qA[dp * 2];
            const float2 qb = *(const float2*)&qB[dp * 2];
            const unsigned long long qa0 = pk2(qa.x, qa.x);
            const unsigned long long qa1 = pk2(qa.y, qa.y);
            const unsigned long long qb0 = pk2(qb.x, qb.x);
            const unsigned long long qb1 = pk2(qb.y, qb.y);
#pragma unroll
            for (int u = 0; u < 4; ++u) {
                const ulonglong2 kk =
                    *(const ulonglong2*)&Kp[((u * 16 + dp) * 32 + lane) * 4];
                ffma2(accA[u], qa0, kk.x);
                ffma2(accA[u], qa1, kk.y);
                ffma2(accB[u], qb0, kk.x);
                ffma2(accB[u], qb1, kk.y);
            }
        }
        float aA[8], aB[8];
#pragma unroll
        for (int u = 0; u < 4; ++u) {
            upk2(accA[u], aA[2*u], aA[2*u+1]);
            upk2(accB[u], aB[2*u], aB[2*u+1]);
        }

        unsigned kA[8], kB[8], mxA = 0u, mxB = 0u;
#pragma unroll
        for (int t = 0; t < 8; ++t) {
            kA[t] = fkey(aA[t] * scale);
            kB[t] = fkey(aB[t] * scale);
            mxA = kA[t] > mxA ? kA[t] : mxA;
            mxB = kB[t] > mxB ? kB[t] : mxB;
        }
        mxA = __reduce_max_sync(FULL, mxA);
        mxB = __reduce_max_sync(FULL, mxB);
        const float mA = fkeyinv(mxA), mB = fkeyinv(mxB);

        // ---- 16-step bit-search on top 16 key bits (both rows packed) ----
        unsigned TA = 0u, TB = 0u;
#pragma unroll
        for (int bit = 15; bit >= 0; --bit) {
            const unsigned cA = (TA | (1u << bit)) << 16;
            const unsigned cB = (TB | (1u << bit)) << 16;
            unsigned n = 0;
#pragma unroll
            for (int t = 0; t < 8; ++t) {
                n += (kA[t] >= cA);
                n += (kB[t] >= cB) << 16;
            }
            n = __reduce_add_sync(FULL, n);
            if ((n & 0xffffu) >= 32) TA |= 1u << bit;
            if ((n >> 16)     >= 32) TB |= 1u << bit;
        }
        const unsigned thrA = (TA + 1u) << 16;
        const unsigned thrB = (TB + 1u) << 16;
        const unsigned loA  = TA << 16;
        const unsigned loB  = TB << 16;

        // ---- compaction of definite winners + bucket candidate build ----
        __syncwarp();
        unsigned candA[8], candB[8];
        int posA = 0, posB = 0;
#pragma unroll
        for (int t = 0; t < 8; ++t) {
            const unsigned j = (unsigned)(t * 32 + lane);
            {
                const bool sel = kA[t] >= thrA;
                const unsigned ms = __ballot_sync(FULL, sel);
                if (sel) {
                    const float w = __expf(fkeyinv(kA[t]) - mA);
                    myp[posA + __popc(ms & lanelt)] =
                        ((unsigned long long)__float_as_uint(w) << 32) | (j << 7);
                }
                candA[t] = (!sel && kA[t] >= loA)
                         ? (((kA[t] & 0xffffu) << 8) | (255u - j) | (1u << 24)) : 0u;
                posA += __popc(ms);
            }
            {
                const bool sel = kB[t] >= thrB;
                const unsigned ms = __ballot_sync(FULL, sel);
                if (sel) {
                    const float w = __expf(fkeyinv(kB[t]) - mB);
                    myp[32 + posB + __popc(ms & lanelt)] =
                        ((unsigned long long)__float_as_uint(w) << 32) | (j << 7);
                }
                candB[t] = (!sel && kB[t] >= loB)
                         ? (((kB[t] & 0xffffu) << 8) | (255u - j) | (1u << 24)) : 0u;
                posB += __popc(ms);
            }
        }

        // ---- exact tail: pop largest full keys from the boundary bucket ----
        while (posA < 32) {
            unsigned lm = candA[0];
#pragma unroll
            for (int t = 1; t < 8; ++t) lm = candA[t] > lm ? candA[t] : lm;
            const unsigned wm = __reduce_max_sync(FULL, lm);
            if (lm == wm) {
#pragma unroll
                for (int t = 0; t < 8; ++t) {
                    if (candA[t] == wm) {
                        const unsigned key = loA | ((wm >> 8) & 0xffffu);
                        const float w = __expf(fkeyinv(key) - mA);
                        myp[posA] = ((unsigned long long)__float_as_uint(w) << 32)
                                  | ((255u - (wm & 0xffu)) << 7);
                        candA[t] = 0u;
                    }
                }
            }
            ++posA;
        }
        while (posB < 32) {
            unsigned lm = candB[0];
#pragma unroll
            for (int t = 1; t < 8; ++t) lm = candB[t] > lm ? candB[t] : lm;
            const unsigned wm = __reduce_max_sync(FULL, lm);
            if (lm == wm) {
#pragma unroll
                for (int t = 0; t < 8; ++t) {
                    if (candB[t] == wm) {
                        const unsigned key = loB | ((wm >> 8) & 0xffffu);
                        const float w = __expf(fkeyinv(key) - mB);
                        myp[32 + posB] = ((unsigned long long)__float_as_uint(w) << 32)
                                       | ((255u - (wm & 0xffu)) << 7);
                        candB[t] = 0u;
                    }
                }
            }
            ++posB;
        }
        __syncwarp();

        // ---- fused softmax-normalize + AV over 32-entry compact lists ----
        float oA = 0.f, dA = 0.f, oB = 0.f, dB = 0.f;
#pragma unroll
        for (int i = 0; i < 32; i += 2) {
            const ulonglong2 ea = *(const ulonglong2*)&myp[i];
            const ulonglong2 eb = *(const ulonglong2*)&myp[32 + i];
            const float wa0 = __uint_as_float((unsigned)(ea.x >> 32));
            const float wa1 = __uint_as_float((unsigned)(ea.y >> 32));
            const float wb0 = __uint_as_float((unsigned)(eb.x >> 32));
            const float wb1 = __uint_as_float((unsigned)(eb.y >> 32));
            dA += wa0;
            oA = fmaf(wa0, *(const float*)(Vb + (unsigned)ea.x + laneoff), oA);
            dA += wa1;
            oA = fmaf(wa1, *(const float*)(Vb + (unsigned)ea.y + laneoff), oA);
            dB += wb0;
            oB = fmaf(wb0, *(const float*)(Vb + (unsigned)eb.x + laneoff), oB);
            dB += wb1;
            oB = fmaf(wb1, *(const float*)(Vb + (unsigned)eb.y + laneoff), oB);
        }
        g_O[qbase + sA * 32 + lane] = oA / dA;
        g_O[qbase + sB * 32 + lane] = oB / dB;
        __syncwarp();
    }
}

// ---------------------------------------------------------------------------
// t = attn_out (seq->spatial) + LePE depthwise 3x3 over V, NHWC
// ---------------------------------------------------------------------------
__global__ void lepe_kernel(const float* __restrict__ lw,
                            const float* __restrict__ lb)
{
    const int idx = blockIdx.x * 256 + threadIdx.x;
    const int c   = idx & 255;
    const int pos = idx >> 8;
    const int w   = pos % 56;
    const int t2  = pos / 56;
    const int h   = t2 % 56;
    const int b   = t2 / 56;
    const int mh = c >> 5, d = c & 31;
    const int hbase = (b * 8 + mh) * 49;
    const int oaddr = (hbase + (h >> 3) * 7 + (w >> 3)) * 2048
                    + (((h & 7) << 3) | (w & 7)) * 32 + d;
    float acc = lb[c];
#pragma unroll
    for (int ky = 0; ky < 3; ++ky) {
        const int y = h + ky - 1;
        if (y < 0 || y >= 56) continue;
#pragma unroll
        for (int kx = 0; kx < 3; ++kx) {
            const int x = w + kx - 1;
            if (x < 0 || x >= 56) continue;
            const int va = (hbase + (y >> 3) * 7 + (x >> 3)) * 2048
                         + (((y & 7) << 3) | (x & 7)) * 32 + d;
            acc += g_V[va] * lw[c * 9 + ky * 3 + kx];
        }
    }
    g_T[idx] = g_O[oaddr] + acc;
}

// ---------------------------------------------------------------------------
// Output projection GEMM (M=25088, N=256, K=256), 128x128 tile, f32x2.
// ---------------------------------------------------------------------------
__global__ void __launch_bounds__(256, 2)
out_gemm_kernel(const float* __restrict__ wo,
                const float* __restrict__ bo,
                float* __restrict__ out)
{
    __shared__ float As[16][132];
    __shared__ float Bs[16][132];
    const int tx = threadIdx.x, ty = threadIdx.y;
    const int tid = ty * 16 + tx;
    const int m0 = blockIdx.y * 128, n0 = blockIdx.x * 128;

    unsigned long long acc2[8][4];
#pragma unroll
    for (int i = 0; i < 8; ++i)
#pragma unroll
        for (int j = 0; j < 4; ++j) acc2[i][j] = 0ull;

    const int r0 = tid >> 2, c0 = tid & 3;

    for (int k0 = 0; k0 < 256; k0 += 16) {
#pragma unroll
        for (int p = 0; p < 2; ++p) {
            const int r = r0 + p * 64;
            float4 av = *(const float4*)&g_T[(m0 + r) * 256 + k0 + c0 * 4];
            float4 bv = *(const float4*)&wo [(n0 + r) * 256 + k0 + c0 * 4];
            As[c0*4+0][r] = av.x; As[c0*4+1][r] = av.y;
            As[c0*4+2][r] = av.z; As[c0*4+3][r] = av.w;
            Bs[c0*4+0][r] = bv.x; Bs[c0*4+1][r] = bv.y;
            Bs[c0*4+2][r] = bv.z; Bs[c0*4+3][r] = bv.w;
        }
        __syncthreads();
#pragma unroll
        for (int k = 0; k < 16; ++k) {
            float a[8];
            *(float4*)&a[0] = *(float4*)&As[k][ty * 8];
            *(float4*)&a[4] = *(float4*)&As[k][ty * 8 + 4];
            const ulonglong2 b01 = *(const ulonglong2*)&Bs[k][tx * 8];
            const ulonglong2 b23 = *(const ulonglong2*)&Bs[k][tx * 8 + 4];
#pragma unroll
            for (int i = 0; i < 8; ++i) {
                const unsigned long long ap = pk2(a[i], a[i]);
                ffma2(acc2[i][0], ap, b01.x);
                ffma2(acc2[i][1], ap, b01.y);
                ffma2(acc2[i][2], ap, b23.x);
                ffma2(acc2[i][3], ap, b23.y);
            }
        }
        __syncthreads();
    }

    const int nbase = n0 + tx * 8;
    float bb[8];
    *(float4*)&bb[0] = *(const float4*)&bo[nbase];
    *(float4*)&bb[4] = *(const float4*)&bo[nbase + 4];
#pragma unroll
    for (int i = 0; i < 8; ++i) {
        const int m = m0 + ty * 8 + i;
        float ac[8];
#pragma unroll
        for (int j = 0; j < 4; ++j) upk2(acc2[i][j], ac[2*j], ac[2*j+1]);
        float4 v0 = make_float4(ac[0]+bb[0], ac[1]+bb[1], ac[2]+bb[2], ac[3]+bb[3]);
        float4 v1 = make_float4(ac[4]+bb[4], ac[5]+bb[5], ac[6]+bb[6], ac[7]+bb[7]);
        *(float4*)&out[m * 256 + nbase]     = v0;
        *(float4*)&out[m * 256 + nbase + 4] = v1;
    }
}

// ---------------------------------------------------------------------------
extern "C" void kernel_launch(void* const* d_in, const int* in_sizes, int n_in,
                              void* d_out, int out_size)
{
    const float* x      = (const float*)d_in[0];
    const float* qkv_w  = (const float*)d_in[1];
    const float* qkv_b  = (const float*)d_in[2];
    const float* lepe_w = (const float*)d_in[3];
    const float* lepe_b = (const float*)d_in[4];
    const float* out_w  = (const float*)d_in[5];
    const float* out_b  = (const float*)d_in[6];
    float* out = (float*)d_out;

    const int attn_smem = 8192 * 4 + 8192 * 4 + 16 * 64 * 8;   // 73728 B
    cudaFuncSetAttribute(attn_kernel, cudaFuncAttributeMaxDynamicSharedMemorySize, attn_smem);

    qkv_gemm_kernel<<<dim3(6, 196), dim3(16, 16)>>>(x, qkv_w, qkv_b);
    pool_kernel<<<392, 256>>>();
    route_kernel<<<392, 256>>>();
    attn_kernel<<<BATCH * NHD * NREG, 512, attn_smem>>>();
    lepe_kernel<<<M_TOK, 256>>>(lepe_w, lepe_b);
    out_gemm_kernel<<<dim3(2, 196), dim3(16, 16)>>>(out_w, out_b, out);
}

// round 10
// speedup vs baseline: 2.0806x; 1.0666x over previous
#include <cuda_runtime.h>
#include <math.h>

#define BATCH 8
#define NHD 8
#define HD 32
#define NREG 49
#define SREG 64
#define TOPK 4
#define M_TOK (BATCH*56*56)                 // 25088
#define SEQ_SIZE (BATCH*NHD*NREG*SREG*HD)   // 6422528

__device__ float g_Q[SEQ_SIZE];
__device__ float g_K[SEQ_SIZE];
__device__ float g_V[SEQ_SIZE];
__device__ float g_O[SEQ_SIZE];
__device__ float g_T[SEQ_SIZE];
__device__ float g_poolq[BATCH*NREG*256];
__device__ float g_poolk[BATCH*NREG*256];
__device__ int   g_topk[BATCH*NREG*TOPK];

// ---- packed fp32x2 helpers (two independent IEEE fp32 ops -> bit-exact) ----
__device__ __forceinline__ unsigned long long pk2(float lo, float hi) {
    unsigned long long d;
    asm("mov.b64 %0, {%1, %2};" : "=l"(d)
        : "r"(__float_as_uint(lo)), "r"(__float_as_uint(hi)));
    return d;
}
__device__ __forceinline__ void upk2(unsigned long long v, float& lo, float& hi) {
    unsigned a, b;
    asm("mov.b64 {%0, %1}, %2;" : "=r"(a), "=r"(b) : "l"(v));
    lo = __uint_as_float(a); hi = __uint_as_float(b);
}
__device__ __forceinline__ void ffma2(unsigned long long& acc,
                                      unsigned long long a, unsigned long long b) {
    asm("fma.rn.f32x2 %0, %1, %2, %3;" : "=l"(acc) : "l"(a), "l"(b), "l"(acc));
}

// ---------------------------------------------------------------------------
// QKV GEMM (M=25088, N=768, K=256): 128x128 tile, 8x8 microtile (scalar FFMA).
// ---------------------------------------------------------------------------
__global__ void __launch_bounds__(256, 2)
qkv_gemm_kernel(const float* __restrict__ x,
                const float* __restrict__ wq,
                const float* __restrict__ bias)
{
    __shared__ float As[16][132];
    __shared__ float Bs[16][132];
    const int tx = threadIdx.x, ty = threadIdx.y;
    const int tid = ty * 16 + tx;
    const int m0 = blockIdx.y * 128, n0 = blockIdx.x * 128;

    float acc[8][8];
#pragma unroll
    for (int i = 0; i < 8; ++i)
#pragma unroll
        for (int j = 0; j < 8; ++j) acc[i][j] = 0.f;

    const int r0 = tid >> 2, c0 = tid & 3;

    for (int k0 = 0; k0 < 256; k0 += 16) {
#pragma unroll
        for (int p = 0; p < 2; ++p) {
            const int r = r0 + p * 64;
            float4 av = *(const float4*)&x [(m0 + r) * 256 + k0 + c0 * 4];
            float4 bv = *(const float4*)&wq[(n0 + r) * 256 + k0 + c0 * 4];
            As[c0*4+0][r] = av.x; As[c0*4+1][r] = av.y;
            As[c0*4+2][r] = av.z; As[c0*4+3][r] = av.w;
            Bs[c0*4+0][r] = bv.x; Bs[c0*4+1][r] = bv.y;
            Bs[c0*4+2][r] = bv.z; Bs[c0*4+3][r] = bv.w;
        }
        __syncthreads();
#pragma unroll
        for (int k = 0; k < 16; ++k) {
            float a[8], b[8];
            *(float4*)&a[0] = *(float4*)&As[k][ty * 8];
            *(float4*)&a[4] = *(float4*)&As[k][ty * 8 + 4];
            *(float4*)&b[0] = *(float4*)&Bs[k][tx * 8];
            *(float4*)&b[4] = *(float4*)&Bs[k][tx * 8 + 4];
#pragma unroll
            for (int i = 0; i < 8; ++i)
#pragma unroll
                for (int j = 0; j < 8; ++j) acc[i][j] = fmaf(a[i], b[j], acc[i][j]);
        }
        __syncthreads();
    }

    const int nbase = n0 + tx * 8;
    const int sec = nbase >> 8;
    const int cch = nbase & 255;
    const int mh  = cch >> 5, d0 = cch & 31;
    float* dst = (sec == 0) ? g_Q : (sec == 1 ? g_K : g_V);
    float bb[8];
    *(float4*)&bb[0] = *(const float4*)&bias[nbase];
    *(float4*)&bb[4] = *(const float4*)&bias[nbase + 4];

#pragma unroll
    for (int i = 0; i < 8; ++i) {
        int m  = m0 + ty * 8 + i;
        int b  = m / 3136;
        int hw = m - b * 3136;
        int h  = hw / 56;
        int w  = hw - h * 56;
        int r  = (h >> 3) * 7 + (w >> 3);
        int ss = ((h & 7) << 3) | (w & 7);
        int off = ((b * 8 + mh) * 49 + r) * 2048 + ss * 32 + d0;
        float4 v0 = make_float4(acc[i][0]+bb[0], acc[i][1]+bb[1], acc[i][2]+bb[2], acc[i][3]+bb[3]);
        float4 v1 = make_float4(acc[i][4]+bb[4], acc[i][5]+bb[5], acc[i][6]+bb[6], acc[i][7]+bb[7]);
        *(float4*)&dst[off]     = v0;
        *(float4*)&dst[off + 4] = v1;
    }
}

// ---------------------------------------------------------------------------
// Region average pooling of Q and K
// ---------------------------------------------------------------------------
__global__ void pool_kernel()
{
    const int b = blockIdx.x / 49, r = blockIdx.x % 49;
    const int c = threadIdx.x;
    const int mh = c >> 5, d = c & 31;
    const int base = ((b * 8 + mh) * 49 + r) * 2048 + d;
    float sq = 0.f, sk = 0.f;
#pragma unroll 8
    for (int s = 0; s < 64; ++s) {
        sq += g_Q[base + s * 32];
        sk += g_K[base + s * 32];
    }
    g_poolq[(b * 49 + r) * 256 + c] = sq * (1.f / 64.f);
    g_poolk[(b * 49 + r) * 256 + c] = sk * (1.f / 64.f);
}

// ---------------------------------------------------------------------------
// Coarse routing: top-4 region set per (b, region)
// ---------------------------------------------------------------------------
__global__ void route_kernel()
{
    const int b = blockIdx.x / 49, i = blockIdx.x % 49;
    __shared__ float qrow[256];
    __shared__ float scores[49];
    const int tid = threadIdx.x;
    qrow[tid] = g_poolq[(b * 49 + i) * 256 + tid];
    __syncthreads();
    const int warp = tid >> 5, lane = tid & 31;
    for (int j = warp; j < 49; j += 8) {
        const float* kr = g_poolk + (b * 49 + j) * 256;
        float s = 0.f;
#pragma unroll
        for (int cc = lane; cc < 256; cc += 32) s += qrow[cc] * kr[cc];
#pragma unroll
        for (int off = 16; off; off >>= 1) s += __shfl_xor_sync(0xffffffffu, s, off);
        if (lane == 0) scores[j] = s;
    }
    __syncthreads();
    if (tid == 0) {
        for (int t = 0; t < 4; ++t) {
            float bv = -INFINITY; int bj = 0;
            for (int j = 0; j < 49; ++j)
                if (scores[j] > bv) { bv = scores[j]; bj = j; }
            g_topk[(b * 49 + i) * 4 + t] = bj;
            scores[bj] = -INFINITY;
        }
    }
}

// ---------------------------------------------------------------------------
// Sparse attention per (b, head, region). 512 threads, 16 warps,
// 4 rows/warp in ONE pass over K (halves K smem traffic; two independent
// packed REDUX chains in the bit-search). Candidate words overwrite key
// registers in place to stay at the 64-reg occupancy cliff.
// Selection = exact lax.top_k sets (ties -> lowest index); all fp math
// bit-identical to prior rounds.
// ---------------------------------------------------------------------------
__device__ __forceinline__ unsigned fkey(float v) {
    unsigned u = __float_as_uint(v);
    return (u & 0x80000000u) ? ~u : (u | 0x80000000u);
}
__device__ __forceinline__ float fkeyinv(unsigned k) {
    return __uint_as_float((k & 0x80000000u) ? (k & 0x7fffffffu) : ~k);
}

__global__ void __launch_bounds__(512, 2) attn_kernel()
{
    extern __shared__ float smem[];
    float* Kp = smem;                        // pair-interleaved K: 8192 f
    float* Vs = smem + 8192;                 // 256*32 = 8192 f
    unsigned long long* plist =
        (unsigned long long*)(smem + 16384); // 16 warps * 128 u64 = 16 KB

    const int blk = blockIdx.x;
    const int b   = blk / (NHD * NREG);
    const int rem = blk % (NHD * NREG);
    const int mh  = rem / NREG;
    const int r   = rem % NREG;
    const int tid = threadIdx.x;
    const int qbase = ((b * 8 + mh) * 49 + r) * 2048;
    const float scale = 0.0625f;
    const unsigned FULL = 0xffffffffu;

    // V tiles (vectorized) + K in pair-interleaved layout:
    // Kp[((u*16+dp)*32+ln)*4 + {0..3}] = (K[64u+ln][2dp], K[64u+32+ln][2dp],
    //                                     K[64u+ln][2dp+1], K[64u+32+ln][2dp+1])
    {
        const int dp = (tid >> 5) & 15;
        const int ln = tid & 31;
#pragma unroll
        for (int t = 0; t < 4; ++t) {
            const int rr = g_topk[(b * 49 + r) * 4 + t];
            const int base = ((b * 8 + mh) * 49 + rr) * 2048;
            *(float4*)&Vs[t * 2048 + tid * 4] = *(const float4*)&g_V[base + tid * 4];
            const float2 va = *(const float2*)&g_K[base + ln * 32 + dp * 2];
            const float2 vb = *(const float2*)&g_K[base + (ln + 32) * 32 + dp * 2];
            *(float4*)&Kp[((t * 16 + dp) * 32 + ln) * 4] =
                make_float4(va.x, vb.x, va.y, vb.y);
        }
    }
    __syncthreads();

    const int warp = tid >> 5, lane = tid & 31;
    const unsigned lanelt = (1u << lane) - 1u;
    unsigned long long* myp = plist + warp * 128;
    const char* Vb = (const char*)Vs;
    const int laneoff = lane * 4;
    const int s0 = warp * 4;

    // ---- scores for 4 rows in one K pass; each f32x2 half accumulates in
    //      exact ascending-d order (bit-identical to scalar version) ----
    unsigned long long acc[4][4];   // [row][u]; lo=even t, hi=odd t
#pragma unroll
    for (int rr2 = 0; rr2 < 4; ++rr2)
#pragma unroll
        for (int u = 0; u < 4; ++u) acc[rr2][u] = 0ull;

    const float* q0 = g_Q + qbase + s0 * 32;
#pragma unroll
    for (int dp = 0; dp < 16; ++dp) {
        unsigned long long p0[4], p1[4];
#pragma unroll
        for (int rr2 = 0; rr2 < 4; ++rr2) {
            const float2 qv = *(const float2*)&q0[rr2 * 32 + dp * 2];
            p0[rr2] = pk2(qv.x, qv.x);
            p1[rr2] = pk2(qv.y, qv.y);
        }
#pragma unroll
        for (int u = 0; u < 4; ++u) {
            const ulonglong2 kk =
                *(const ulonglong2*)&Kp[((u * 16 + dp) * 32 + lane) * 4];
#pragma unroll
            for (int rr2 = 0; rr2 < 4; ++rr2) {
                ffma2(acc[rr2][u], p0[rr2], kk.x);
                ffma2(acc[rr2][u], p1[rr2], kk.y);
            }
        }
    }

    // ---- keys + per-row max ----
    unsigned key[4][8];
    float m[4];
#pragma unroll
    for (int rr2 = 0; rr2 < 4; ++rr2) {
        float a[8];
#pragma unroll
        for (int u = 0; u < 4; ++u) upk2(acc[rr2][u], a[2*u], a[2*u+1]);
        unsigned mx = 0u;
#pragma unroll
        for (int t = 0; t < 8; ++t) {
            key[rr2][t] = fkey(a[t] * scale);
            mx = key[rr2][t] > mx ? key[rr2][t] : mx;
        }
        mx = __reduce_max_sync(FULL, mx);
        m[rr2] = fkeyinv(mx);
    }

    // ---- 16-step bit-search on top 16 key bits; rows (0,1) and (2,3)
    //      packed into two independent REDUX chains ----
    unsigned T[4] = {0u, 0u, 0u, 0u};
#pragma unroll
    for (int bit = 15; bit >= 0; --bit) {
        unsigned c0 = (T[0] | (1u << bit)) << 16;
        unsigned c1 = (T[1] | (1u << bit)) << 16;
        unsigned c2 = (T[2] | (1u << bit)) << 16;
        unsigned c3 = (T[3] | (1u << bit)) << 16;
        unsigned n01 = 0, n23 = 0;
#pragma unroll
        for (int t = 0; t < 8; ++t) {
            n01 += (key[0][t] >= c0);
            n01 += (key[1][t] >= c1) << 16;
            n23 += (key[2][t] >= c2);
            n23 += (key[3][t] >= c3) << 16;
        }
        n01 = __reduce_add_sync(FULL, n01);
        n23 = __reduce_add_sync(FULL, n23);
        if ((n01 & 0xffffu) >= 32) T[0] |= 1u << bit;
        if ((n01 >> 16)     >= 32) T[1] |= 1u << bit;
        if ((n23 & 0xffffu) >= 32) T[2] |= 1u << bit;
        if ((n23 >> 16)     >= 32) T[3] |= 1u << bit;
    }

    // ---- compaction of definite winners; key[] overwritten in place with
    //      boundary-bucket candidate words ----
    __syncwarp();
    int pos[4] = {0, 0, 0, 0};
#pragma unroll
    for (int t = 0; t < 8; ++t) {
        const unsigned j = (unsigned)(t * 32 + lane);
#pragma unroll
        for (int rr2 = 0; rr2 < 4; ++rr2) {
            const unsigned thr = (T[rr2] + 1u) << 16;
            const unsigned lo  = T[rr2] << 16;
            const unsigned kv  = key[rr2][t];
            const bool sel = kv >= thr;
            const unsigned ms = __ballot_sync(FULL, sel);
            if (sel) {
                const float w = __expf(fkeyinv(kv) - m[rr2]);
                myp[rr2 * 32 + pos[rr2] + __popc(ms & lanelt)] =
                    ((unsigned long long)__float_as_uint(w) << 32) | (j << 7);
            }
            key[rr2][t] = (!sel && kv >= lo)
                        ? (((kv & 0xffffu) << 8) | (255u - j) | (1u << 24)) : 0u;
            pos[rr2] += __popc(ms);
        }
    }

    // ---- exact tail: pop largest full keys from each boundary bucket ----
#pragma unroll
    for (int rr2 = 0; rr2 < 4; ++rr2) {
        const unsigned lo = T[rr2] << 16;
        while (pos[rr2] < 32) {
            unsigned lm = key[rr2][0];
#pragma unroll
            for (int t = 1; t < 8; ++t) lm = key[rr2][t] > lm ? key[rr2][t] : lm;
            const unsigned wm = __reduce_max_sync(FULL, lm);
            if (lm == wm) {
#pragma unroll
                for (int t = 0; t < 8; ++t) {
                    if (key[rr2][t] == wm) {
                        const unsigned kfull = lo | ((wm >> 8) & 0xffffu);
                        const float w = __expf(fkeyinv(kfull) - m[rr2]);
                        myp[rr2 * 32 + pos[rr2]] =
                            ((unsigned long long)__float_as_uint(w) << 32)
                            | ((255u - (wm & 0xffu)) << 7);
                        key[rr2][t] = 0u;
                    }
                }
            }
            ++pos[rr2];
        }
    }
    __syncwarp();

    // ---- fused softmax-normalize + AV, 4 rows interleaved for ILP ----
    float o[4] = {0.f, 0.f, 0.f, 0.f};
    float dnm[4] = {0.f, 0.f, 0.f, 0.f};
#pragma unroll
    for (int i = 0; i < 32; i += 2) {
#pragma unroll
        for (int rr2 = 0; rr2 < 4; ++rr2) {
            const ulonglong2 e = *(const ulonglong2*)&myp[rr2 * 32 + i];
            const float w0 = __uint_as_float((unsigned)(e.x >> 32));
            const float w1 = __uint_as_float((unsigned)(e.y >> 32));
            dnm[rr2] += w0;
            o[rr2] = fmaf(w0, *(const float*)(Vb + (unsigned)e.x + laneoff), o[rr2]);
            dnm[rr2] += w1;
            o[rr2] = fmaf(w1, *(const float*)(Vb + (unsigned)e.y + laneoff), o[rr2]);
        }
    }
#pragma unroll
    for (int rr2 = 0; rr2 < 4; ++rr2)
        g_O[qbase + (s0 + rr2) * 32 + lane] = o[rr2] / dnm[rr2];
}

// ---------------------------------------------------------------------------
// t = attn_out (seq->spatial) + LePE depthwise 3x3 over V, NHWC
// ---------------------------------------------------------------------------
__global__ void lepe_kernel(const float* __restrict__ lw,
                            const float* __restrict__ lb)
{
    const int idx = blockIdx.x * 256 + threadIdx.x;
    const int c   = idx & 255;
    const int pos = idx >> 8;
    const int w   = pos % 56;
    const int t2  = pos / 56;
    const int h   = t2 % 56;
    const int b   = t2 / 56;
    const int mh = c >> 5, d = c & 31;
    const int hbase = (b * 8 + mh) * 49;
    const int oaddr = (hbase + (h >> 3) * 7 + (w >> 3)) * 2048
                    + (((h & 7) << 3) | (w & 7)) * 32 + d;
    float acc = lb[c];
#pragma unroll
    for (int ky = 0; ky < 3; ++ky) {
        const int y = h + ky - 1;
        if (y < 0 || y >= 56) continue;
#pragma unroll
        for (int kx = 0; kx < 3; ++kx) {
            const int x = w + kx - 1;
            if (x < 0 || x >= 56) continue;
            const int va = (hbase + (y >> 3) * 7 + (x >> 3)) * 2048
                         + (((y & 7) << 3) | (x & 7)) * 32 + d;
            acc += g_V[va] * lw[c * 9 + ky * 3 + kx];
        }
    }
    g_T[idx] = g_O[oaddr] + acc;
}

// ---------------------------------------------------------------------------
// Output projection GEMM (M=25088, N=256, K=256), 128x128 tile (scalar FFMA).
// ---------------------------------------------------------------------------
__global__ void __launch_bounds__(256, 2)
out_gemm_kernel(const float* __restrict__ wo,
                const float* __restrict__ bo,
                float* __restrict__ out)
{
    __shared__ float As[16][132];
    __shared__ float Bs[16][132];
    const int tx = threadIdx.x, ty = threadIdx.y;
    const int tid = ty * 16 + tx;
    const int m0 = blockIdx.y * 128, n0 = blockIdx.x * 128;

    float acc[8][8];
#pragma unroll
    for (int i = 0; i < 8; ++i)
#pragma unroll
        for (int j = 0; j < 8; ++j) acc[i][j] = 0.f;

    const int r0 = tid >> 2, c0 = tid & 3;

    for (int k0 = 0; k0 < 256; k0 += 16) {
#pragma unroll
        for (int p = 0; p < 2; ++p) {
            const int r = r0 + p * 64;
            float4 av = *(const float4*)&g_T[(m0 + r) * 256 + k0 + c0 * 4];
            float4 bv = *(const float4*)&wo [(n0 + r) * 256 + k0 + c0 * 4];
            As[c0*4+0][r] = av.x; As[c0*4+1][r] = av.y;
            As[c0*4+2][r] = av.z; As[c0*4+3][r] = av.w;
            Bs[c0*4+0][r] = bv.x; Bs[c0*4+1][r] = bv.y;
            Bs[c0*4+2][r] = bv.z; Bs[c0*4+3][r] = bv.w;
        }
        __syncthreads();
#pragma unroll
        for (int k = 0; k < 16; ++k) {
            float a[8], b[8];
            *(float4*)&a[0] = *(float4*)&As[k][ty * 8];
            *(float4*)&a[4] = *(float4*)&As[k][ty * 8 + 4];
            *(float4*)&b[0] = *(float4*)&Bs[k][tx * 8];
            *(float4*)&b[4] = *(float4*)&Bs[k][tx * 8 + 4];
#pragma unroll
            for (int i = 0; i < 8; ++i)
#pragma unroll
                for (int j = 0; j < 8; ++j) acc[i][j] = fmaf(a[i], b[j], acc[i][j]);
        }
        __syncthreads();
    }

    const int nbase = n0 + tx * 8;
    float bb[8];
    *(float4*)&bb[0] = *(const float4*)&bo[nbase];
    *(float4*)&bb[4] = *(const float4*)&bo[nbase + 4];
#pragma unroll
    for (int i = 0; i < 8; ++i) {
        const int m = m0 + ty * 8 + i;
        float4 v0 = make_float4(acc[i][0]+bb[0], acc[i][1]+bb[1], acc[i][2]+bb[2], acc[i][3]+bb[3]);
        float4 v1 = make_float4(acc[i][4]+bb[4], acc[i][5]+bb[5], acc[i][6]+bb[6], acc[i][7]+bb[7]);
        *(float4*)&out[m * 256 + nbase]     = v0;
        *(float4*)&out[m * 256 + nbase + 4] = v1;
    }
}

// ---------------------------------------------------------------------------
extern "C" void kernel_launch(void* const* d_in, const int* in_sizes, int n_in,
                              void* d_out, int out_size)
{
    const float* x      = (const float*)d_in[0];
    const float* qkv_w  = (const float*)d_in[1];
    const float* qkv_b  = (const float*)d_in[2];
    const float* lepe_w = (const float*)d_in[3];
    const float* lepe_b = (const float*)d_in[4];
    const float* out_w  = (const float*)d_in[5];
    const float* out_b  = (const float*)d_in[6];
    float* out = (float*)d_out;

    const int attn_smem = 8192 * 4 + 8192 * 4 + 16 * 128 * 8;  // 81920 B
    cudaFuncSetAttribute(attn_kernel, cudaFuncAttributeMaxDynamicSharedMemorySize, attn_smem);

    qkv_gemm_kernel<<<dim3(6, 196), dim3(16, 16)>>>(x, qkv_w, qkv_b);
    pool_kernel<<<392, 256>>>();
    route_kernel<<<392, 256>>>();
    attn_kernel<<<BATCH * NHD * NREG, 512, attn_smem>>>();
    lepe_kernel<<<M_TOK, 256>>>(lepe_w, lepe_b);
    out_gemm_kernel<<<dim3(2, 196), dim3(16, 16)>>>(out_w, out_b, out);
}

// round 13
// speedup vs baseline: 2.1323x; 1.0248x over previous
#include <cuda_runtime.h>
#include <math.h>

#define BATCH 8
#define NHD 8
#define HD 32
#define NREG 49
#define SREG 64
#define TOPK 4
#define M_TOK (BATCH*56*56)                 // 25088
#define SEQ_SIZE (BATCH*NHD*NREG*SREG*HD)   // 6422528

__device__ float g_Q[SEQ_SIZE];
__device__ float g_K[SEQ_SIZE];
__device__ float g_V[SEQ_SIZE];
__device__ float g_O[SEQ_SIZE];
__device__ float g_T[SEQ_SIZE];
__device__ float g_poolq[BATCH*NREG*256];
__device__ float g_poolk[BATCH*NREG*256];
__device__ int   g_topk[BATCH*NREG*TOPK];

// ---- packed fp32x2 helpers (two independent IEEE fp32 ops -> bit-exact) ----
__device__ __forceinline__ unsigned long long pk2(float lo, float hi) {
    unsigned long long d;
    asm("mov.b64 %0, {%1, %2};" : "=l"(d)
        : "r"(__float_as_uint(lo)), "r"(__float_as_uint(hi)));
    return d;
}
__device__ __forceinline__ void upk2(unsigned long long v, float& lo, float& hi) {
    unsigned a, b;
    asm("mov.b64 {%0, %1}, %2;" : "=r"(a), "=r"(b) : "l"(v));
    lo = __uint_as_float(a); hi = __uint_as_float(b);
}
__device__ __forceinline__ void ffma2(unsigned long long& acc,
                                      unsigned long long a, unsigned long long b) {
    asm("fma.rn.f32x2 %0, %1, %2, %3;" : "=l"(acc) : "l"(a), "l"(b), "l"(acc));
}

// ---------------------------------------------------------------------------
// QKV GEMM (M=25088, N=768, K=256): 128x128 tile, 8x8 microtile, scalar FFMA,
// register-staged software pipeline (LDG for chunk c+1 issued before compute
// of chunk c). Accumulation order (ascending k) unchanged -> bit-exact.
// ---------------------------------------------------------------------------
__global__ void __launch_bounds__(256, 2)
qkv_gemm_kernel(const float* __restrict__ x,
                const float* __restrict__ wq,
                const float* __restrict__ bias)
{
    __shared__ float As[16][132];
    __shared__ float Bs[16][132];
    const int tx = threadIdx.x, ty = threadIdx.y;
    const int tid = ty * 16 + tx;
    const int m0 = blockIdx.y * 128, n0 = blockIdx.x * 128;

    float acc[8][8];
#pragma unroll
    for (int i = 0; i < 8; ++i)
#pragma unroll
        for (int j = 0; j < 8; ++j) acc[i][j] = 0.f;

    const int r0 = tid >> 2, c0 = tid & 3;

    // prologue: load chunk 0 into registers, stage to smem
    float4 pa[2], pb[2];
#pragma unroll
    for (int p = 0; p < 2; ++p) {
        const int r = r0 + p * 64;
        pa[p] = *(const float4*)&x [(m0 + r) * 256 + c0 * 4];
        pb[p] = *(const float4*)&wq[(n0 + r) * 256 + c0 * 4];
    }
#pragma unroll
    for (int p = 0; p < 2; ++p) {
        const int r = r0 + p * 64;
        As[c0*4+0][r] = pa[p].x; As[c0*4+1][r] = pa[p].y;
        As[c0*4+2][r] = pa[p].z; As[c0*4+3][r] = pa[p].w;
        Bs[c0*4+0][r] = pb[p].x; Bs[c0*4+1][r] = pb[p].y;
        Bs[c0*4+2][r] = pb[p].z; Bs[c0*4+3][r] = pb[p].w;
    }
    __syncthreads();

    for (int kc = 0; kc < 16; ++kc) {
        // prefetch next chunk into registers (latency hidden behind compute)
        if (kc < 15) {
            const int kn = (kc + 1) * 16;
#pragma unroll
            for (int p = 0; p < 2; ++p) {
                const int r = r0 + p * 64;
                pa[p] = *(const float4*)&x [(m0 + r) * 256 + kn + c0 * 4];
                pb[p] = *(const float4*)&wq[(n0 + r) * 256 + kn + c0 * 4];
            }
        }
#pragma unroll
        for (int k = 0; k < 16; ++k) {
            float a[8], b[8];
            *(float4*)&a[0] = *(float4*)&As[k][ty * 8];
            *(float4*)&a[4] = *(float4*)&As[k][ty * 8 + 4];
            *(float4*)&b[0] = *(float4*)&Bs[k][tx * 8];
            *(float4*)&b[4] = *(float4*)&Bs[k][tx * 8 + 4];
#pragma unroll
            for (int i = 0; i < 8; ++i)
#pragma unroll
                for (int j = 0; j < 8; ++j) acc[i][j] = fmaf(a[i], b[j], acc[i][j]);
        }
        __syncthreads();
        if (kc < 15) {
#pragma unroll
            for (int p = 0; p < 2; ++p) {
                const int r = r0 + p * 64;
                As[c0*4+0][r] = pa[p].x; As[c0*4+1][r] = pa[p].y;
                As[c0*4+2][r] = pa[p].z; As[c0*4+3][r] = pa[p].w;
                Bs[c0*4+0][r] = pb[p].x; Bs[c0*4+1][r] = pb[p].y;
                Bs[c0*4+2][r] = pb[p].z; Bs[c0*4+3][r] = pb[p].w;
            }
            __syncthreads();
        }
    }

    const int nbase = n0 + tx * 8;
    const int sec = nbase >> 8;
    const int cch = nbase & 255;
    const int mh  = cch >> 5, d0 = cch & 31;
    float* dst = (sec == 0) ? g_Q : (sec == 1 ? g_K : g_V);
    float bb[8];
    *(float4*)&bb[0] = *(const float4*)&bias[nbase];
    *(float4*)&bb[4] = *(const float4*)&bias[nbase + 4];

#pragma unroll
    for (int i = 0; i < 8; ++i) {
        int m  = m0 + ty * 8 + i;
        int b  = m / 3136;
        int hw = m - b * 3136;
        int h  = hw / 56;
        int w  = hw - h * 56;
        int r  = (h >> 3) * 7 + (w >> 3);
        int ss = ((h & 7) << 3) | (w & 7);
        int off = ((b * 8 + mh) * 49 + r) * 2048 + ss * 32 + d0;
        float4 v0 = make_float4(acc[i][0]+bb[0], acc[i][1]+bb[1], acc[i][2]+bb[2], acc[i][3]+bb[3]);
        float4 v1 = make_float4(acc[i][4]+bb[4], acc[i][5]+bb[5], acc[i][6]+bb[6], acc[i][7]+bb[7]);
        *(float4*)&dst[off]     = v0;
        *(float4*)&dst[off + 4] = v1;
    }
}

// ---------------------------------------------------------------------------
// Region average pooling of Q and K
// ---------------------------------------------------------------------------
__global__ void pool_kernel()
{
    const int b = blockIdx.x / 49, r = blockIdx.x % 49;
    const int c = threadIdx.x;
    const int mh = c >> 5, d = c & 31;
    const int base = ((b * 8 + mh) * 49 + r) * 2048 + d;
    float sq = 0.f, sk = 0.f;
#pragma unroll 8
    for (int s = 0; s < 64; ++s) {
        sq += g_Q[base + s * 32];
        sk += g_K[base + s * 32];
    }
    g_poolq[(b * 49 + r) * 256 + c] = sq * (1.f / 64.f);
    g_poolk[(b * 49 + r) * 256 + c] = sk * (1.f / 64.f);
}

// ---------------------------------------------------------------------------
// Coarse routing: top-4 region set per (b, region)
// ---------------------------------------------------------------------------
__global__ void route_kernel()
{
    const int b = blockIdx.x / 49, i = blockIdx.x % 49;
    __shared__ float qrow[256];
    __shared__ float scores[49];
    const int tid = threadIdx.x;
    qrow[tid] = g_poolq[(b * 49 + i) * 256 + tid];
    __syncthreads();
    const int warp = tid >> 5, lane = tid & 31;
    for (int j = warp; j < 49; j += 8) {
        const float* kr = g_poolk + (b * 49 + j) * 256;
        float s = 0.f;
#pragma unroll
        for (int cc = lane; cc < 256; cc += 32) s += qrow[cc] * kr[cc];
#pragma unroll
        for (int off = 16; off; off >>= 1) s += __shfl_xor_sync(0xffffffffu, s, off);
        if (lane == 0) scores[j] = s;
    }
    __syncthreads();
    if (tid == 0) {
        for (int t = 0; t < 4; ++t) {
            float bv = -INFINITY; int bj = 0;
            for (int j = 0; j < 49; ++j)
                if (scores[j] > bv) { bv = scores[j]; bj = j; }
            g_topk[(b * 49 + i) * 4 + t] = bj;
            scores[bj] = -INFINITY;
        }
    }
}

// ---------------------------------------------------------------------------
// Sparse attention per (b, head, region). 512 threads, 16 warps,
// 4 rows/warp in ONE pass over K; two independent packed REDUX chains in the
// bit-search; key[] overwritten in place by boundary-bucket candidates.
// Selection = exact lax.top_k sets (ties -> lowest index); all fp math
// bit-identical to prior rounds. (Unchanged from R9.)
// ---------------------------------------------------------------------------
__device__ __forceinline__ unsigned fkey(float v) {
    unsigned u = __float_as_uint(v);
    return (u & 0x80000000u) ? ~u : (u | 0x80000000u);
}
__device__ __forceinline__ float fkeyinv(unsigned k) {
    return __uint_as_float((k & 0x80000000u) ? (k & 0x7fffffffu) : ~k);
}

__global__ void __launch_bounds__(512, 2) attn_kernel()
{
    extern __shared__ float smem[];
    float* Kp = smem;                        // pair-interleaved K: 8192 f
    float* Vs = smem + 8192;                 // 256*32 = 8192 f
    unsigned long long* plist =
        (unsigned long long*)(smem + 16384); // 16 warps * 128 u64 = 16 KB

    const int blk = blockIdx.x;
    const int b   = blk / (NHD * NREG);
    const int rem = blk % (NHD * NREG);
    const int mh  = rem / NREG;
    const int r   = rem % NREG;
    const int tid = threadIdx.x;
    const int qbase = ((b * 8 + mh) * 49 + r) * 2048;
    const float scale = 0.0625f;
    const unsigned FULL = 0xffffffffu;

    {
        const int dp = (tid >> 5) & 15;
        const int ln = tid & 31;
#pragma unroll
        for (int t = 0; t < 4; ++t) {
            const int rr = g_topk[(b * 49 + r) * 4 + t];
            const int base = ((b * 8 + mh) * 49 + rr) * 2048;
            *(float4*)&Vs[t * 2048 + tid * 4] = *(const float4*)&g_V[base + tid * 4];
            const float2 va = *(const float2*)&g_K[base + ln * 32 + dp * 2];
            const float2 vb = *(const float2*)&g_K[base + (ln + 32) * 32 + dp * 2];
            *(float4*)&Kp[((t * 16 + dp) * 32 + ln) * 4] =
                make_float4(va.x, vb.x, va.y, vb.y);
        }
    }
    __syncthreads();

    const int warp = tid >> 5, lane = tid & 31;
    const unsigned lanelt = (1u << lane) - 1u;
    unsigned long long* myp = plist + warp * 128;
    const char* Vb = (const char*)Vs;
    const int laneoff = lane * 4;
    const int s0 = warp * 4;

    unsigned long long acc[4][4];
#pragma unroll
    for (int rr2 = 0; rr2 < 4; ++rr2)
#pragma unroll
        for (int u = 0; u < 4; ++u) acc[rr2][u] = 0ull;

    const float* q0 = g_Q + qbase + s0 * 32;
#pragma unroll
    for (int dp = 0; dp < 16; ++dp) {
        unsigned long long p0[4], p1[4];
#pragma unroll
        for (int rr2 = 0; rr2 < 4; ++rr2) {
            const float2 qv = *(const float2*)&q0[rr2 * 32 + dp * 2];
            p0[rr2] = pk2(qv.x, qv.x);
            p1[rr2] = pk2(qv.y, qv.y);
        }
#pragma unroll
        for (int u = 0; u < 4; ++u) {
            const ulonglong2 kk =
                *(const ulonglong2*)&Kp[((u * 16 + dp) * 32 + lane) * 4];
#pragma unroll
            for (int rr2 = 0; rr2 < 4; ++rr2) {
                ffma2(acc[rr2][u], p0[rr2], kk.x);
                ffma2(acc[rr2][u], p1[rr2], kk.y);
            }
        }
    }

    unsigned key[4][8];
    float m[4];
#pragma unroll
    for (int rr2 = 0; rr2 < 4; ++rr2) {
        float a[8];
#pragma unroll
        for (int u = 0; u < 4; ++u) upk2(acc[rr2][u], a[2*u], a[2*u+1]);
        unsigned mx = 0u;
#pragma unroll
        for (int t = 0; t < 8; ++t) {
            key[rr2][t] = fkey(a[t] * scale);
            mx = key[rr2][t] > mx ? key[rr2][t] : mx;
        }
        mx = __reduce_max_sync(FULL, mx);
        m[rr2] = fkeyinv(mx);
    }

    unsigned T[4] = {0u, 0u, 0u, 0u};
#pragma unroll
    for (int bit = 15; bit >= 0; --bit) {
        unsigned c0 = (T[0] | (1u << bit)) << 16;
        unsigned c1 = (T[1] | (1u << bit)) << 16;
        unsigned c2 = (T[2] | (1u << bit)) << 16;
        unsigned c3 = (T[3] | (1u << bit)) << 16;
        unsigned n01 = 0, n23 = 0;
#pragma unroll
        for (int t = 0; t < 8; ++t) {
            n01 += (key[0][t] >= c0);
            n01 += (key[1][t] >= c1) << 16;
            n23 += (key[2][t] >= c2);
            n23 += (key[3][t] >= c3) << 16;
        }
        n01 = __reduce_add_sync(FULL, n01);
        n23 = __reduce_add_sync(FULL, n23);
        if ((n01 & 0xffffu) >= 32) T[0] |= 1u << bit;
        if ((n01 >> 16)     >= 32) T[1] |= 1u << bit;
        if ((n23 & 0xffffu) >= 32) T[2] |= 1u << bit;
        if ((n23 >> 16)     >= 32) T[3] |= 1u << bit;
    }

    __syncwarp();
    int pos[4] = {0, 0, 0, 0};
#pragma unroll
    for (int t = 0; t < 8; ++t) {
        const unsigned j = (unsigned)(t * 32 + lane);
#pragma unroll
        for (int rr2 = 0; rr2 < 4; ++rr2) {
            const unsigned thr = (T[rr2] + 1u) << 16;
            const unsigned lo  = T[rr2] << 16;
            const unsigned kv  = key[rr2][t];
            const bool sel = kv >= thr;
            const unsigned ms = __ballot_sync(FULL, sel);
            if (sel) {
                const float w = __expf(fkeyinv(kv) - m[rr2]);
                myp[rr2 * 32 + pos[rr2] + __popc(ms & lanelt)] =
                    ((unsigned long long)__float_as_uint(w) << 32) | (j << 7);
            }
            key[rr2][t] = (!sel && kv >= lo)
                        ? (((kv & 0xffffu) << 8) | (255u - j) | (1u << 24)) : 0u;
            pos[rr2] += __popc(ms);
        }
    }

#pragma unroll
    for (int rr2 = 0; rr2 < 4; ++rr2) {
        const unsigned lo = T[rr2] << 16;
        while (pos[rr2] < 32) {
            unsigned lm = key[rr2][0];
#pragma unroll
            for (int t = 1; t < 8; ++t) lm = key[rr2][t] > lm ? key[rr2][t] : lm;
            const unsigned wm = __reduce_max_sync(FULL, lm);
            if (lm == wm) {
#pragma unroll
                for (int t = 0; t < 8; ++t) {
                    if (key[rr2][t] == wm) {
                        const unsigned kfull = lo | ((wm >> 8) & 0xffffu);
                        const float w = __expf(fkeyinv(kfull) - m[rr2]);
                        myp[rr2 * 32 + pos[rr2]] =
                            ((unsigned long long)__float_as_uint(w) << 32)
                            | ((255u - (wm & 0xffu)) << 7);
                        key[rr2][t] = 0u;
                    }
                }
            }
            ++pos[rr2];
        }
    }
    __syncwarp();

    float o[4] = {0.f, 0.f, 0.f, 0.f};
    float dnm[4] = {0.f, 0.f, 0.f, 0.f};
#pragma unroll
    for (int i = 0; i < 32; i += 2) {
#pragma unroll
        for (int rr2 = 0; rr2 < 4; ++rr2) {
            const ulonglong2 e = *(const ulonglong2*)&myp[rr2 * 32 + i];
            const float w0 = __uint_as_float((unsigned)(e.x >> 32));
            const float w1 = __uint_as_float((unsigned)(e.y >> 32));
            dnm[rr2] += w0;
            o[rr2] = fmaf(w0, *(const float*)(Vb + (unsigned)e.x + laneoff), o[rr2]);
            dnm[rr2] += w1;
            o[rr2] = fmaf(w1, *(const float*)(Vb + (unsigned)e.y + laneoff), o[rr2]);
        }
    }
#pragma unroll
    for (int rr2 = 0; rr2 < 4; ++rr2)
        g_O[qbase + (s0 + rr2) * 32 + lane] = o[rr2] / dnm[rr2];
}

// ---------------------------------------------------------------------------
// t = attn_out (seq->spatial) + LePE depthwise 3x3 over V, NHWC
// ---------------------------------------------------------------------------
__global__ void lepe_kernel(const float* __restrict__ lw,
                            const float* __restrict__ lb)
{
    const int idx = blockIdx.x * 256 + threadIdx.x;
    const int c   = idx & 255;
    const int pos = idx >> 8;
    const int w   = pos % 56;
    const int t2  = pos / 56;
    const int h   = t2 % 56;
    const int b   = t2 / 56;
    const int mh = c >> 5, d = c & 31;
    const int hbase = (b * 8 + mh) * 49;
    const int oaddr = (hbase + (h >> 3) * 7 + (w >> 3)) * 2048
                    + (((h & 7) << 3) | (w & 7)) * 32 + d;
    float acc = lb[c];
#pragma unroll
    for (int ky = 0; ky < 3; ++ky) {
        const int y = h + ky - 1;
        if (y < 0 || y >= 56) continue;
#pragma unroll
        for (int kx = 0; kx < 3; ++kx) {
            const int x = w + kx - 1;
            if (x < 0 || x >= 56) continue;
            const int va = (hbase + (y >> 3) * 7 + (x >> 3)) * 2048
                         + (((y & 7) << 3) | (x & 7)) * 32 + d;
            acc += g_V[va] * lw[c * 9 + ky * 3 + kx];
        }
    }
    g_T[idx] = g_O[oaddr] + acc;
}

// ---------------------------------------------------------------------------
// Output projection GEMM (M=25088, N=256, K=256), 128x128 tile, scalar FFMA,
// register-staged software pipeline. Bit-exact accumulation order.
// ---------------------------------------------------------------------------
__global__ void __launch_bounds__(256, 2)
out_gemm_kernel(const float* __restrict__ wo,
                const float* __restrict__ bo,
                float* __restrict__ out)
{
    __shared__ float As[16][132];
    __shared__ float Bs[16][132];
    const int tx = threadIdx.x, ty = threadIdx.y;
    const int tid = ty * 16 + tx;
    const int m0 = blockIdx.y * 128, n0 = blockIdx.x * 128;

    float acc[8][8];
#pragma unroll
    for (int i = 0; i < 8; ++i)
#pragma unroll
        for (int j = 0; j < 8; ++j) acc[i][j] = 0.f;

    const int r0 = tid >> 2, c0 = tid & 3;

    float4 pa[2], pb[2];
#pragma unroll
    for (int p = 0; p < 2; ++p) {
        const int r = r0 + p * 64;
        pa[p] = *(const float4*)&g_T[(m0 + r) * 256 + c0 * 4];
        pb[p] = *(const float4*)&wo [(n0 + r) * 256 + c0 * 4];
    }
#pragma unroll
    for (int p = 0; p < 2; ++p) {
        const int r = r0 + p * 64;
        As[c0*4+0][r] = pa[p].x; As[c0*4+1][r] = pa[p].y;
        As[c0*4+2][r] = pa[p].z; As[c0*4+3][r] = pa[p].w;
        Bs[c0*4+0][r] = pb[p].x; Bs[c0*4+1][r] = pb[p].y;
        Bs[c0*4+2][r] = pb[p].z; Bs[c0*4+3][r] = pb[p].w;
    }
    __syncthreads();

    for (int kc = 0; kc < 16; ++kc) {
        if (kc < 15) {
            const int kn = (kc + 1) * 16;
#pragma unroll
            for (int p = 0; p < 2; ++p) {
                const int r = r0 + p * 64;
                pa[p] = *(const float4*)&g_T[(m0 + r) * 256 + kn + c0 * 4];
                pb[p] = *(const float4*)&wo [(n0 + r) * 256 + kn + c0 * 4];
            }
        }
#pragma unroll
        for (int k = 0; k < 16; ++k) {
            float a[8], b[8];
            *(float4*)&a[0] = *(float4*)&As[k][ty * 8];
            *(float4*)&a[4] = *(float4*)&As[k][ty * 8 + 4];
            *(float4*)&b[0] = *(float4*)&Bs[k][tx * 8];
            *(float4*)&b[4] = *(float4*)&Bs[k][tx * 8 + 4];
#pragma unroll
            for (int i = 0; i < 8; ++i)
#pragma unroll
                for (int j = 0; j < 8; ++j) acc[i][j] = fmaf(a[i], b[j], acc[i][j]);
        }
        __syncthreads();
        if (kc < 15) {
#pragma unroll
            for (int p = 0; p < 2; ++p) {
                const int r = r0 + p * 64;
                As[c0*4+0][r] = pa[p].x; As[c0*4+1][r] = pa[p].y;
                As[c0*4+2][r] = pa[p].z; As[c0*4+3][r] = pa[p].w;
                Bs[c0*4+0][r] = pb[p].x; Bs[c0*4+1][r] = pb[p].y;
                Bs[c0*4+2][r] = pb[p].z; Bs[c0*4+3][r] = pb[p].w;
            }
            __syncthreads();
        }
    }

    const int nbase = n0 + tx * 8;
    float bb[8];
    *(float4*)&bb[0] = *(const float4*)&bo[nbase];
    *(float4*)&bb[4] = *(const float4*)&bo[nbase + 4];
#pragma unroll
    for (int i = 0; i < 8; ++i) {
        const int m = m0 + ty * 8 + i;
        float4 v0 = make_float4(acc[i][0]+bb[0], acc[i][1]+bb[1], acc[i][2]+bb[2], acc[i][3]+bb[3]);
        float4 v1 = make_float4(acc[i][4]+bb[4], acc[i][5]+bb[5], acc[i][6]+bb[6], acc[i][7]+bb[7]);
        *(float4*)&out[m * 256 + nbase]     = v0;
        *(float4*)&out[m * 256 + nbase + 4] = v1;
    }
}

// ---------------------------------------------------------------------------
extern "C" void kernel_launch(void* const* d_in, const int* in_sizes, int n_in,
                              void* d_out, int out_size)
{
    const float* x      = (const float*)d_in[0];
    const float* qkv_w  = (const float*)d_in[1];
    const float* qkv_b  = (const float*)d_in[2];
    const float* lepe_w = (const float*)d_in[3];
    const float* lepe_b = (const float*)d_in[4];
    const float* out_w  = (const float*)d_in[5];
    const float* out_b  = (const float*)d_in[6];
    float* out = (float*)d_out;

    const int attn_smem = 8192 * 4 + 8192 * 4 + 16 * 128 * 8;  // 81920 B
    cudaFuncSetAttribute(attn_kernel, cudaFuncAttributeMaxDynamicSharedMemorySize, attn_smem);

    qkv_gemm_kernel<<<dim3(6, 196), dim3(16, 16)>>>(x, qkv_w, qkv_b);
    pool_kernel<<<392, 256>>>();
    route_kernel<<<392, 256>>>();
    attn_kernel<<<BATCH * NHD * NREG, 512, attn_smem>>>();
    lepe_kernel<<<M_TOK, 256>>>(lepe_w, lepe_b);
    out_gemm_kernel<<<dim3(2, 196), dim3(16, 16)>>>(out_w, out_b, out);
}

// round 14
// speedup vs baseline: 2.1511x; 1.0088x over previous
#include <cuda_runtime.h>
#include <math.h>

#define BATCH 8
#define NHD 8
#define HD 32
#define NREG 49
#define SREG 64
#define TOPK 4
#define M_TOK (BATCH*56*56)                 // 25088
#define SEQ_SIZE (BATCH*NHD*NREG*SREG*HD)   // 6422528

__device__ float g_Q[SEQ_SIZE];
__device__ float g_K[SEQ_SIZE];
__device__ float g_V[SEQ_SIZE];
__device__ float g_O[SEQ_SIZE];
__device__ float g_T[SEQ_SIZE];
__device__ float g_poolq[BATCH*NREG*256];
__device__ float g_poolk[BATCH*NREG*256];
__device__ int   g_topk[BATCH*NREG*TOPK];

// ---- packed fp32x2 helpers (two independent IEEE fp32 ops -> bit-exact) ----
__device__ __forceinline__ unsigned long long pk2(float lo, float hi) {
    unsigned long long d;
    asm("mov.b64 %0, {%1, %2};" : "=l"(d)
        : "r"(__float_as_uint(lo)), "r"(__float_as_uint(hi)));
    return d;
}
__device__ __forceinline__ void upk2(unsigned long long v, float& lo, float& hi) {
    unsigned a, b;
    asm("mov.b64 {%0, %1}, %2;" : "=r"(a), "=r"(b) : "l"(v));
    lo = __uint_as_float(a); hi = __uint_as_float(b);
}
__device__ __forceinline__ void ffma2(unsigned long long& acc,
                                      unsigned long long a, unsigned long long b) {
    asm("fma.rn.f32x2 %0, %1, %2, %3;" : "=l"(acc) : "l"(a), "l"(b), "l"(acc));
}

// ---------------------------------------------------------------------------
// QKV GEMM (M=25088, N=768, K=256): 128x128 tile, 8x8 microtile, scalar FFMA,
// register-staged software pipeline. Bit-exact ascending-k accumulation.
// ---------------------------------------------------------------------------
__global__ void __launch_bounds__(256, 2)
qkv_gemm_kernel(const float* __restrict__ x,
                const float* __restrict__ wq,
                const float* __restrict__ bias)
{
    __shared__ float As[16][132];
    __shared__ float Bs[16][132];
    const int tx = threadIdx.x, ty = threadIdx.y;
    const int tid = ty * 16 + tx;
    const int m0 = blockIdx.y * 128, n0 = blockIdx.x * 128;

    float acc[8][8];
#pragma unroll
    for (int i = 0; i < 8; ++i)
#pragma unroll
        for (int j = 0; j < 8; ++j) acc[i][j] = 0.f;

    const int r0 = tid >> 2, c0 = tid & 3;

    float4 pa[2], pb[2];
#pragma unroll
    for (int p = 0; p < 2; ++p) {
        const int r = r0 + p * 64;
        pa[p] = *(const float4*)&x [(m0 + r) * 256 + c0 * 4];
        pb[p] = *(const float4*)&wq[(n0 + r) * 256 + c0 * 4];
    }
#pragma unroll
    for (int p = 0; p < 2; ++p) {
        const int r = r0 + p * 64;
        As[c0*4+0][r] = pa[p].x; As[c0*4+1][r] = pa[p].y;
        As[c0*4+2][r] = pa[p].z; As[c0*4+3][r] = pa[p].w;
        Bs[c0*4+0][r] = pb[p].x; Bs[c0*4+1][r] = pb[p].y;
        Bs[c0*4+2][r] = pb[p].z; Bs[c0*4+3][r] = pb[p].w;
    }
    __syncthreads();

    for (int kc = 0; kc < 16; ++kc) {
        if (kc < 15) {
            const int kn = (kc + 1) * 16;
#pragma unroll
            for (int p = 0; p < 2; ++p) {
                const int r = r0 + p * 64;
                pa[p] = *(const float4*)&x [(m0 + r) * 256 + kn + c0 * 4];
                pb[p] = *(const float4*)&wq[(n0 + r) * 256 + kn + c0 * 4];
            }
        }
#pragma unroll
        for (int k = 0; k < 16; ++k) {
            float a[8], b[8];
            *(float4*)&a[0] = *(float4*)&As[k][ty * 8];
            *(float4*)&a[4] = *(float4*)&As[k][ty * 8 + 4];
            *(float4*)&b[0] = *(float4*)&Bs[k][tx * 8];
            *(float4*)&b[4] = *(float4*)&Bs[k][tx * 8 + 4];
#pragma unroll
            for (int i = 0; i < 8; ++i)
#pragma unroll
                for (int j = 0; j < 8; ++j) acc[i][j] = fmaf(a[i], b[j], acc[i][j]);
        }
        __syncthreads();
        if (kc < 15) {
#pragma unroll
            for (int p = 0; p < 2; ++p) {
                const int r = r0 + p * 64;
                As[c0*4+0][r] = pa[p].x; As[c0*4+1][r] = pa[p].y;
                As[c0*4+2][r] = pa[p].z; As[c0*4+3][r] = pa[p].w;
                Bs[c0*4+0][r] = pb[p].x; Bs[c0*4+1][r] = pb[p].y;
                Bs[c0*4+2][r] = pb[p].z; Bs[c0*4+3][r] = pb[p].w;
            }
            __syncthreads();
        }
    }

    const int nbase = n0 + tx * 8;
    const int sec = nbase >> 8;
    const int cch = nbase & 255;
    const int mh  = cch >> 5, d0 = cch & 31;
    float* dst = (sec == 0) ? g_Q : (sec == 1 ? g_K : g_V);
    float bb[8];
    *(float4*)&bb[0] = *(const float4*)&bias[nbase];
    *(float4*)&bb[4] = *(const float4*)&bias[nbase + 4];

#pragma unroll
    for (int i = 0; i < 8; ++i) {
        int m  = m0 + ty * 8 + i;
        int b  = m / 3136;
        int hw = m - b * 3136;
        int h  = hw / 56;
        int w  = hw - h * 56;
        int r  = (h >> 3) * 7 + (w >> 3);
        int ss = ((h & 7) << 3) | (w & 7);
        int off = ((b * 8 + mh) * 49 + r) * 2048 + ss * 32 + d0;
        float4 v0 = make_float4(acc[i][0]+bb[0], acc[i][1]+bb[1], acc[i][2]+bb[2], acc[i][3]+bb[3]);
        float4 v1 = make_float4(acc[i][4]+bb[4], acc[i][5]+bb[5], acc[i][6]+bb[6], acc[i][7]+bb[7]);
        *(float4*)&dst[off]     = v0;
        *(float4*)&dst[off + 4] = v1;
    }
}

// ---------------------------------------------------------------------------
// Region average pooling of Q and K
// ---------------------------------------------------------------------------
__global__ void pool_kernel()
{
    const int b = blockIdx.x / 49, r = blockIdx.x % 49;
    const int c = threadIdx.x;
    const int mh = c >> 5, d = c & 31;
    const int base = ((b * 8 + mh) * 49 + r) * 2048 + d;
    float sq = 0.f, sk = 0.f;
#pragma unroll 8
    for (int s = 0; s < 64; ++s) {
        sq += g_Q[base + s * 32];
        sk += g_K[base + s * 32];
    }
    g_poolq[(b * 49 + r) * 256 + c] = sq * (1.f / 64.f);
    g_poolk[(b * 49 + r) * 256 + c] = sk * (1.f / 64.f);
}

// ---------------------------------------------------------------------------
// Coarse routing: top-4 region set per (b, region)
// ---------------------------------------------------------------------------
__global__ void route_kernel()
{
    const int b = blockIdx.x / 49, i = blockIdx.x % 49;
    __shared__ float qrow[256];
    __shared__ float scores[49];
    const int tid = threadIdx.x;
    qrow[tid] = g_poolq[(b * 49 + i) * 256 + tid];
    __syncthreads();
    const int warp = tid >> 5, lane = tid & 31;
    for (int j = warp; j < 49; j += 8) {
        const float* kr = g_poolk + (b * 49 + j) * 256;
        float s = 0.f;
#pragma unroll
        for (int cc = lane; cc < 256; cc += 32) s += qrow[cc] * kr[cc];
#pragma unroll
        for (int off = 16; off; off >>= 1) s += __shfl_xor_sync(0xffffffffu, s, off);
        if (lane == 0) scores[j] = s;
    }
    __syncthreads();
    if (tid == 0) {
        for (int t = 0; t < 4; ++t) {
            float bv = -INFINITY; int bj = 0;
            for (int j = 0; j < 49; ++j)
                if (scores[j] > bv) { bv = scores[j]; bj = j; }
            g_topk[(b * 49 + i) * 4 + t] = bj;
            scores[bj] = -INFINITY;
        }
    }
}

// ---------------------------------------------------------------------------
// Sparse attention per (b, head, region). Unchanged from R12 (bit-identical).
// ---------------------------------------------------------------------------
__device__ __forceinline__ unsigned fkey(float v) {
    unsigned u = __float_as_uint(v);
    return (u & 0x80000000u) ? ~u : (u | 0x80000000u);
}
__device__ __forceinline__ float fkeyinv(unsigned k) {
    return __uint_as_float((k & 0x80000000u) ? (k & 0x7fffffffu) : ~k);
}

__global__ void __launch_bounds__(512, 2) attn_kernel()
{
    extern __shared__ float smem[];
    float* Kp = smem;                        // pair-interleaved K: 8192 f
    float* Vs = smem + 8192;                 // 256*32 = 8192 f
    unsigned long long* plist =
        (unsigned long long*)(smem + 16384); // 16 warps * 128 u64 = 16 KB

    const int blk = blockIdx.x;
    const int b   = blk / (NHD * NREG);
    const int rem = blk % (NHD * NREG);
    const int mh  = rem / NREG;
    const int r   = rem % NREG;
    const int tid = threadIdx.x;
    const int qbase = ((b * 8 + mh) * 49 + r) * 2048;
    const float scale = 0.0625f;
    const unsigned FULL = 0xffffffffu;

    {
        const int dp = (tid >> 5) & 15;
        const int ln = tid & 31;
#pragma unroll
        for (int t = 0; t < 4; ++t) {
            const int rr = g_topk[(b * 49 + r) * 4 + t];
            const int base = ((b * 8 + mh) * 49 + rr) * 2048;
            *(float4*)&Vs[t * 2048 + tid * 4] = *(const float4*)&g_V[base + tid * 4];
            const float2 va = *(const float2*)&g_K[base + ln * 32 + dp * 2];
            const float2 vb = *(const float2*)&g_K[base + (ln + 32) * 32 + dp * 2];
            *(float4*)&Kp[((t * 16 + dp) * 32 + ln) * 4] =
                make_float4(va.x, vb.x, va.y, vb.y);
        }
    }
    __syncthreads();

    const int warp = tid >> 5, lane = tid & 31;
    const unsigned lanelt = (1u << lane) - 1u;
    unsigned long long* myp = plist + warp * 128;
    const char* Vb = (const char*)Vs;
    const int laneoff = lane * 4;
    const int s0 = warp * 4;

    unsigned long long acc[4][4];
#pragma unroll
    for (int rr2 = 0; rr2 < 4; ++rr2)
#pragma unroll
        for (int u = 0; u < 4; ++u) acc[rr2][u] = 0ull;

    const float* q0 = g_Q + qbase + s0 * 32;
#pragma unroll
    for (int dp = 0; dp < 16; ++dp) {
        unsigned long long p0[4], p1[4];
#pragma unroll
        for (int rr2 = 0; rr2 < 4; ++rr2) {
            const float2 qv = *(const float2*)&q0[rr2 * 32 + dp * 2];
            p0[rr2] = pk2(qv.x, qv.x);
            p1[rr2] = pk2(qv.y, qv.y);
        }
#pragma unroll
        for (int u = 0; u < 4; ++u) {
            const ulonglong2 kk =
                *(const ulonglong2*)&Kp[((u * 16 + dp) * 32 + lane) * 4];
#pragma unroll
            for (int rr2 = 0; rr2 < 4; ++rr2) {
                ffma2(acc[rr2][u], p0[rr2], kk.x);
                ffma2(acc[rr2][u], p1[rr2], kk.y);
            }
        }
    }

    unsigned key[4][8];
    float m[4];
#pragma unroll
    for (int rr2 = 0; rr2 < 4; ++rr2) {
        float a[8];
#pragma unroll
        for (int u = 0; u < 4; ++u) upk2(acc[rr2][u], a[2*u], a[2*u+1]);
        unsigned mx = 0u;
#pragma unroll
        for (int t = 0; t < 8; ++t) {
            key[rr2][t] = fkey(a[t] * scale);
            mx = key[rr2][t] > mx ? key[rr2][t] : mx;
        }
        mx = __reduce_max_sync(FULL, mx);
        m[rr2] = fkeyinv(mx);
    }

    unsigned T[4] = {0u, 0u, 0u, 0u};
#pragma unroll
    for (int bit = 15; bit >= 0; --bit) {
        unsigned c0 = (T[0] | (1u << bit)) << 16;
        unsigned c1 = (T[1] | (1u << bit)) << 16;
        unsigned c2 = (T[2] | (1u << bit)) << 16;
        unsigned c3 = (T[3] | (1u << bit)) << 16;
        unsigned n01 = 0, n23 = 0;
#pragma unroll
        for (int t = 0; t < 8; ++t) {
            n01 += (key[0][t] >= c0);
            n01 += (key[1][t] >= c1) << 16;
            n23 += (key[2][t] >= c2);
            n23 += (key[3][t] >= c3) << 16;
        }
        n01 = __reduce_add_sync(FULL, n01);
        n23 = __reduce_add_sync(FULL, n23);
        if ((n01 & 0xffffu) >= 32) T[0] |= 1u << bit;
        if ((n01 >> 16)     >= 32) T[1] |= 1u << bit;
        if ((n23 & 0xffffu) >= 32) T[2] |= 1u << bit;
        if ((n23 >> 16)     >= 32) T[3] |= 1u << bit;
    }

    __syncwarp();
    int pos[4] = {0, 0, 0, 0};
#pragma unroll
    for (int t = 0; t < 8; ++t) {
        const unsigned j = (unsigned)(t * 32 + lane);
#pragma unroll
        for (int rr2 = 0; rr2 < 4; ++rr2) {
            const unsigned thr = (T[rr2] + 1u) << 16;
            const unsigned lo  = T[rr2] << 16;
            const unsigned kv  = key[rr2][t];
            const bool sel = kv >= thr;
            const unsigned ms = __ballot_sync(FULL, sel);
            if (sel) {
                const float w = __expf(fkeyinv(kv) - m[rr2]);
                myp[rr2 * 32 + pos[rr2] + __popc(ms & lanelt)] =
                    ((unsigned long long)__float_as_uint(w) << 32) | (j << 7);
            }
            key[rr2][t] = (!sel && kv >= lo)
                        ? (((kv & 0xffffu) << 8) | (255u - j) | (1u << 24)) : 0u;
            pos[rr2] += __popc(ms);
        }
    }

#pragma unroll
    for (int rr2 = 0; rr2 < 4; ++rr2) {
        const unsigned lo = T[rr2] << 16;
        while (pos[rr2] < 32) {
            unsigned lm = key[rr2][0];
#pragma unroll
            for (int t = 1; t < 8; ++t) lm = key[rr2][t] > lm ? key[rr2][t] : lm;
            const unsigned wm = __reduce_max_sync(FULL, lm);
            if (lm == wm) {
#pragma unroll
                for (int t = 0; t < 8; ++t) {
                    if (key[rr2][t] == wm) {
                        const unsigned kfull = lo | ((wm >> 8) & 0xffffu);
                        const float w = __expf(fkeyinv(kfull) - m[rr2]);
                        myp[rr2 * 32 + pos[rr2]] =
                            ((unsigned long long)__float_as_uint(w) << 32)
                            | ((255u - (wm & 0xffu)) << 7);
                        key[rr2][t] = 0u;
                    }
                }
            }
            ++pos[rr2];
        }
    }
    __syncwarp();

    float o[4] = {0.f, 0.f, 0.f, 0.f};
    float dnm[4] = {0.f, 0.f, 0.f, 0.f};
#pragma unroll
    for (int i = 0; i < 32; i += 2) {
#pragma unroll
        for (int rr2 = 0; rr2 < 4; ++rr2) {
            const ulonglong2 e = *(const ulonglong2*)&myp[rr2 * 32 + i];
            const float w0 = __uint_as_float((unsigned)(e.x >> 32));
            const float w1 = __uint_as_float((unsigned)(e.y >> 32));
            dnm[rr2] += w0;
            o[rr2] = fmaf(w0, *(const float*)(Vb + (unsigned)e.x + laneoff), o[rr2]);
            dnm[rr2] += w1;
            o[rr2] = fmaf(w1, *(const float*)(Vb + (unsigned)e.y + laneoff), o[rr2]);
        }
    }
#pragma unroll
    for (int rr2 = 0; rr2 < 4; ++rr2)
        g_O[qbase + (s0 + rr2) * 32 + lane] = o[rr2] / dnm[rr2];
}

// ---------------------------------------------------------------------------
// LePE (smem-tiled): one block per (b, region, 128-ch half). Loads a 10x10
// token halo tile of V into smem (zero-padded at image borders), computes the
// 3x3 depthwise conv from smem with register weights, adds attn output g_O,
// writes g_T. Accumulation order identical to the untiled version; OOB adds
// an exact 0*w -> bit-identical results.
// ---------------------------------------------------------------------------
__global__ void __launch_bounds__(256, 4)
lepe_kernel(const float* __restrict__ lw, const float* __restrict__ lb)
{
    extern __shared__ float Vt[];            // 100 positions * 128 ch = 51200 B

    const int breg = blockIdx.x;             // b*49 + r
    const int b  = breg / 49, r = breg % 49;
    const int ch0 = blockIdx.y << 7;         // 0 or 128
    const int h0 = (r / 7) * 8, w0 = (r % 7) * 8;
    const int tid = threadIdx.x;
    const int hbase = b * 8 * 49;

    // ---- load 10x10 halo tile (4 channels per thread, 8 position groups) ----
    {
        const int c4 = (tid & 31) * 4;       // local channel quad 0..124
        const int ch = ch0 + c4;
        const int mh = ch >> 5, d = ch & 31;
        for (int p = (tid >> 5); p < 100; p += 8) {
            const int gy = h0 - 1 + p / 10;
            const int gx = w0 - 1 + p % 10;
            float4 v = make_float4(0.f, 0.f, 0.f, 0.f);
            if (gy >= 0 && gy < 56 && gx >= 0 && gx < 56) {
                const int rr = (gy >> 3) * 7 + (gx >> 3);
                const int ss = ((gy & 7) << 3) | (gx & 7);
                v = *(const float4*)&g_V[(hbase + mh * 49 + rr) * 2048 + ss * 32 + d];
            }
            *(float4*)&Vt[p * 128 + c4] = v;
        }
    }
    __syncthreads();

    // ---- compute: one channel per thread, 32 tokens each ----
    const int lc = tid & 127;                // local channel
    const int tg = tid >> 7;                 // token half (0/1)
    const int ch = ch0 + lc;
    const int mh = ch >> 5, d = ch & 31;
    float wgt[9];
#pragma unroll
    for (int i = 0; i < 9; ++i) wgt[i] = lw[ch * 9 + i];
    const float lbv = lb[ch];
    const int obase = (hbase + mh * 49 + r) * 2048 + d;

#pragma unroll 4
    for (int tk = tg * 32; tk < tg * 32 + 32; ++tk) {
        const int ty = tk >> 3, tx2 = tk & 7;
        float acc = lbv;
#pragma unroll
        for (int ky = 0; ky < 3; ++ky)
#pragma unroll
            for (int kx = 0; kx < 3; ++kx)
                acc = fmaf(Vt[((ty + ky) * 10 + tx2 + kx) * 128 + lc],
                           wgt[ky * 3 + kx], acc);
        const int h = h0 + ty, w = w0 + tx2;
        g_T[((b * 56 + h) * 56 + w) * 256 + ch] = g_O[obase + tk * 32] + acc;
    }
}

// ---------------------------------------------------------------------------
// Output projection GEMM (M=25088, N=256, K=256), 128x128 tile, scalar FFMA,
// register-staged software pipeline. Bit-exact accumulation order.
// ---------------------------------------------------------------------------
__global__ void __launch_bounds__(256, 2)
out_gemm_kernel(const float* __restrict__ wo,
                const float* __restrict__ bo,
                float* __restrict__ out)
{
    __shared__ float As[16][132];
    __shared__ float Bs[16][132];
    const int tx = threadIdx.x, ty = threadIdx.y;
    const int tid = ty * 16 + tx;
    const int m0 = blockIdx.y * 128, n0 = blockIdx.x * 128;

    float acc[8][8];
#pragma unroll
    for (int i = 0; i < 8; ++i)
#pragma unroll
        for (int j = 0; j < 8; ++j) acc[i][j] = 0.f;

    const int r0 = tid >> 2, c0 = tid & 3;

    float4 pa[2], pb[2];
#pragma unroll
    for (int p = 0; p < 2; ++p) {
        const int r = r0 + p * 64;
        pa[p] = *(const float4*)&g_T[(m0 + r) * 256 + c0 * 4];
        pb[p] = *(const float4*)&wo [(n0 + r) * 256 + c0 * 4];
    }
#pragma unroll
    for (int p = 0; p < 2; ++p) {
        const int r = r0 + p * 64;
        As[c0*4+0][r] = pa[p].x; As[c0*4+1][r] = pa[p].y;
        As[c0*4+2][r] = pa[p].z; As[c0*4+3][r] = pa[p].w;
        Bs[c0*4+0][r] = pb[p].x; Bs[c0*4+1][r] = pb[p].y;
        Bs[c0*4+2][r] = pb[p].z; Bs[c0*4+3][r] = pb[p].w;
    }
    __syncthreads();

    for (int kc = 0; kc < 16; ++kc) {
        if (kc < 15) {
            const int kn = (kc + 1) * 16;
#pragma unroll
            for (int p = 0; p < 2; ++p) {
                const int r = r0 + p * 64;
                pa[p] = *(const float4*)&g_T[(m0 + r) * 256 + kn + c0 * 4];
                pb[p] = *(const float4*)&wo [(n0 + r) * 256 + kn + c0 * 4];
            }
        }
#pragma unroll
        for (int k = 0; k < 16; ++k) {
            float a[8], b[8];
            *(float4*)&a[0] = *(float4*)&As[k][ty * 8];
            *(float4*)&a[4] = *(float4*)&As[k][ty * 8 + 4];
            *(float4*)&b[0] = *(float4*)&Bs[k][tx * 8];
            *(float4*)&b[4] = *(float4*)&Bs[k][tx * 8 + 4];
#pragma unroll
            for (int i = 0; i < 8; ++i)
#pragma unroll
                for (int j = 0; j < 8; ++j) acc[i][j] = fmaf(a[i], b[j], acc[i][j]);
        }
        __syncthreads();
        if (kc < 15) {
#pragma unroll
            for (int p = 0; p < 2; ++p) {
                const int r = r0 + p * 64;
                As[c0*4+0][r] = pa[p].x; As[c0*4+1][r] = pa[p].y;
                As[c0*4+2][r] = pa[p].z; As[c0*4+3][r] = pa[p].w;
                Bs[c0*4+0][r] = pb[p].x; Bs[c0*4+1][r] = pb[p].y;
                Bs[c0*4+2][r] = pb[p].z; Bs[c0*4+3][r] = pb[p].w;
            }
            __syncthreads();
        }
    }

    const int nbase = n0 + tx * 8;
    float bb[8];
    *(float4*)&bb[0] = *(const float4*)&bo[nbase];
    *(float4*)&bb[4] = *(const float4*)&bo[nbase + 4];
#pragma unroll
    for (int i = 0; i < 8; ++i) {
        const int m = m0 + ty * 8 + i;
        float4 v0 = make_float4(acc[i][0]+bb[0], acc[i][1]+bb[1], acc[i][2]+bb[2], acc[i][3]+bb[3]);
        float4 v1 = make_float4(acc[i][4]+bb[4], acc[i][5]+bb[5], acc[i][6]+bb[6], acc[i][7]+bb[7]);
        *(float4*)&out[m * 256 + nbase]     = v0;
        *(float4*)&out[m * 256 + nbase + 4] = v1;
    }
}

// ---------------------------------------------------------------------------
extern "C" void kernel_launch(void* const* d_in, const int* in_sizes, int n_in,
                              void* d_out, int out_size)
{
    const float* x      = (const float*)d_in[0];
    const float* qkv_w  = (const float*)d_in[1];
    const float* qkv_b  = (const float*)d_in[2];
    const float* lepe_w = (const float*)d_in[3];
    const float* lepe_b = (const float*)d_in[4];
    const float* out_w  = (const float*)d_in[5];
    const float* out_b  = (const float*)d_in[6];
    float* out = (float*)d_out;

    const int attn_smem = 8192 * 4 + 8192 * 4 + 16 * 128 * 8;  // 81920 B
    cudaFuncSetAttribute(attn_kernel, cudaFuncAttributeMaxDynamicSharedMemorySize, attn_smem);
    const int lepe_smem = 100 * 128 * 4;                       // 51200 B
    cudaFuncSetAttribute(lepe_kernel, cudaFuncAttributeMaxDynamicSharedMemorySize, lepe_smem);

    qkv_gemm_kernel<<<dim3(6, 196), dim3(16, 16)>>>(x, qkv_w, qkv_b);
    pool_kernel<<<392, 256>>>();
    route_kernel<<<392, 256>>>();
    attn_kernel<<<BATCH * NHD * NREG, 512, attn_smem>>>();
    lepe_kernel<<<dim3(392, 2), 256, lepe_smem>>>(lepe_w, lepe_b);
    out_gemm_kernel<<<dim3(2, 196), dim3(16, 16)>>>(out_w, out_b, out);
}

// round 16
// speedup vs baseline: 2.1833x; 1.0150x over previous
#include <cuda_runtime.h>
#include <math.h>

#define BATCH 8
#define NHD 8
#define HD 32
#define NREG 49
#define SREG 64
#define TOPK 4
#define M_TOK (BATCH*56*56)                 // 25088
#define SEQ_SIZE (BATCH*NHD*NREG*SREG*HD)   // 6422528

__device__ float g_Q[SEQ_SIZE];
__device__ float g_K[SEQ_SIZE];
__device__ float g_V[SEQ_SIZE];
__device__ float g_O[SEQ_SIZE];
__device__ float g_T[SEQ_SIZE];
__device__ float g_poolq[BATCH*NREG*256];
__device__ float g_poolk[BATCH*NREG*256];
__device__ int   g_topk[BATCH*NREG*TOPK];

// ---- packed fp32x2 helpers (two independent IEEE fp32 ops -> bit-exact) ----
__device__ __forceinline__ unsigned long long pk2(float lo, float hi) {
    unsigned long long d;
    asm("mov.b64 %0, {%1, %2};" : "=l"(d)
        : "r"(__float_as_uint(lo)), "r"(__float_as_uint(hi)));
    return d;
}
__device__ __forceinline__ void upk2(unsigned long long v, float& lo, float& hi) {
    unsigned a, b;
    asm("mov.b64 {%0, %1}, %2;" : "=r"(a), "=r"(b) : "l"(v));
    lo = __uint_as_float(a); hi = __uint_as_float(b);
}
__device__ __forceinline__ void ffma2(unsigned long long& acc,
                                      unsigned long long a, unsigned long long b) {
    asm("fma.rn.f32x2 %0, %1, %2, %3;" : "=l"(acc) : "l"(a), "l"(b), "l"(acc));
}

// ---------------------------------------------------------------------------
// QKV GEMM (M=25088, N=768, K=256): 128x128 tile, 8x8 microtile, scalar FFMA,
// double-buffered smem (one __syncthreads per k-chunk). Bit-exact ascending-k.
// ---------------------------------------------------------------------------
__global__ void __launch_bounds__(256, 2)
qkv_gemm_kernel(const float* __restrict__ x,
                const float* __restrict__ wq,
                const float* __restrict__ bias)
{
    __shared__ float As[2][16][132];
    __shared__ float Bs[2][16][132];
    const int tx = threadIdx.x, ty = threadIdx.y;
    const int tid = ty * 16 + tx;
    const int m0 = blockIdx.y * 128, n0 = blockIdx.x * 128;

    float acc[8][8];
#pragma unroll
    for (int i = 0; i < 8; ++i)
#pragma unroll
        for (int j = 0; j < 8; ++j) acc[i][j] = 0.f;

    const int r0 = tid >> 2, c0 = tid & 3;

    float4 pa[2], pb[2];
#pragma unroll
    for (int p = 0; p < 2; ++p) {
        const int r = r0 + p * 64;
        pa[p] = *(const float4*)&x [(m0 + r) * 256 + c0 * 4];
        pb[p] = *(const float4*)&wq[(n0 + r) * 256 + c0 * 4];
    }
#pragma unroll
    for (int p = 0; p < 2; ++p) {
        const int r = r0 + p * 64;
        As[0][c0*4+0][r] = pa[p].x; As[0][c0*4+1][r] = pa[p].y;
        As[0][c0*4+2][r] = pa[p].z; As[0][c0*4+3][r] = pa[p].w;
        Bs[0][c0*4+0][r] = pb[p].x; Bs[0][c0*4+1][r] = pb[p].y;
        Bs[0][c0*4+2][r] = pb[p].z; Bs[0][c0*4+3][r] = pb[p].w;
    }
    __syncthreads();

    int cur = 0;
    for (int kc = 0; kc < 16; ++kc) {
        if (kc < 15) {
            const int kn = (kc + 1) * 16;
#pragma unroll
            for (int p = 0; p < 2; ++p) {
                const int r = r0 + p * 64;
                pa[p] = *(const float4*)&x [(m0 + r) * 256 + kn + c0 * 4];
                pb[p] = *(const float4*)&wq[(n0 + r) * 256 + kn + c0 * 4];
            }
        }
#pragma unroll
        for (int k = 0; k < 16; ++k) {
            float a[8], b[8];
            *(float4*)&a[0] = *(float4*)&As[cur][k][ty * 8];
            *(float4*)&a[4] = *(float4*)&As[cur][k][ty * 8 + 4];
            *(float4*)&b[0] = *(float4*)&Bs[cur][k][tx * 8];
            *(float4*)&b[4] = *(float4*)&Bs[cur][k][tx * 8 + 4];
#pragma unroll
            for (int i = 0; i < 8; ++i)
#pragma unroll
                for (int j = 0; j < 8; ++j) acc[i][j] = fmaf(a[i], b[j], acc[i][j]);
        }
        if (kc < 15) {
            const int nxt = cur ^ 1;
#pragma unroll
            for (int p = 0; p < 2; ++p) {
                const int r = r0 + p * 64;
                As[nxt][c0*4+0][r] = pa[p].x; As[nxt][c0*4+1][r] = pa[p].y;
                As[nxt][c0*4+2][r] = pa[p].z; As[nxt][c0*4+3][r] = pa[p].w;
                Bs[nxt][c0*4+0][r] = pb[p].x; Bs[nxt][c0*4+1][r] = pb[p].y;
                Bs[nxt][c0*4+2][r] = pb[p].z; Bs[nxt][c0*4+3][r] = pb[p].w;
            }
            __syncthreads();
            cur = nxt;
        }
    }

    const int nbase = n0 + tx * 8;
    const int sec = nbase >> 8;
    const int cch = nbase & 255;
    const int mh  = cch >> 5, d0 = cch & 31;
    float* dst = (sec == 0) ? g_Q : (sec == 1 ? g_K : g_V);
    float bb[8];
    *(float4*)&bb[0] = *(const float4*)&bias[nbase];
    *(float4*)&bb[4] = *(const float4*)&bias[nbase + 4];

#pragma unroll
    for (int i = 0; i < 8; ++i) {
        int m  = m0 + ty * 8 + i;
        int b  = m / 3136;
        int hw = m - b * 3136;
        int h  = hw / 56;
        int w  = hw - h * 56;
        int r  = (h >> 3) * 7 + (w >> 3);
        int ss = ((h & 7) << 3) | (w & 7);
        int off = ((b * 8 + mh) * 49 + r) * 2048 + ss * 32 + d0;
        float4 v0 = make_float4(acc[i][0]+bb[0], acc[i][1]+bb[1], acc[i][2]+bb[2], acc[i][3]+bb[3]);
        float4 v1 = make_float4(acc[i][4]+bb[4], acc[i][5]+bb[5], acc[i][6]+bb[6], acc[i][7]+bb[7]);
        *(float4*)&dst[off]     = v0;
        *(float4*)&dst[off + 4] = v1;
    }
}

// ---------------------------------------------------------------------------
// Region average pooling of Q and K
// ---------------------------------------------------------------------------
__global__ void pool_kernel()
{
    const int b = blockIdx.x / 49, r = blockIdx.x % 49;
    const int c = threadIdx.x;
    const int mh = c >> 5, d = c & 31;
    const int base = ((b * 8 + mh) * 49 + r) * 2048 + d;
    float sq = 0.f, sk = 0.f;
#pragma unroll 8
    for (int s = 0; s < 64; ++s) {
        sq += g_Q[base + s * 32];
        sk += g_K[base + s * 32];
    }
    g_poolq[(b * 49 + r) * 256 + c] = sq * (1.f / 64.f);
    g_poolk[(b * 49 + r) * 256 + c] = sk * (1.f / 64.f);
}

// ---------------------------------------------------------------------------
// Coarse routing: top-4 region set per (b, region)
// ---------------------------------------------------------------------------
__global__ void route_kernel()
{
    const int b = blockIdx.x / 49, i = blockIdx.x % 49;
    __shared__ float qrow[256];
    __shared__ float scores[49];
    const int tid = threadIdx.x;
    qrow[tid] = g_poolq[(b * 49 + i) * 256 + tid];
    __syncthreads();
    const int warp = tid >> 5, lane = tid & 31;
    for (int j = warp; j < 49; j += 8) {
        const float* kr = g_poolk + (b * 49 + j) * 256;
        float s = 0.f;
#pragma unroll
        for (int cc = lane; cc < 256; cc += 32) s += qrow[cc] * kr[cc];
#pragma unroll
        for (int off = 16; off; off >>= 1) s += __shfl_xor_sync(0xffffffffu, s, off);
        if (lane == 0) scores[j] = s;
    }
    __syncthreads();
    if (tid == 0) {
        for (int t = 0; t < 4; ++t) {
            float bv = -INFINITY; int bj = 0;
            for (int j = 0; j < 49; ++j)
                if (scores[j] > bv) { bv = scores[j]; bj = j; }
            g_topk[(b * 49 + i) * 4 + t] = bj;
            scores[bj] = -INFINITY;
        }
    }
}

// ---------------------------------------------------------------------------
// Sparse attention per (b, head, region). Scan-based winner compaction
// (order-free set; one packed 4-row warp scan replaces 64 ballots).
// Selection sets bit-identical to prior rounds.
// ---------------------------------------------------------------------------
__device__ __forceinline__ unsigned fkey(float v) {
    unsigned u = __float_as_uint(v);
    return (u & 0x80000000u) ? ~u : (u | 0x80000000u);
}
__device__ __forceinline__ float fkeyinv(unsigned k) {
    return __uint_as_float((k & 0x80000000u) ? (k & 0x7fffffffu) : ~k);
}

__global__ void __launch_bounds__(512, 2) attn_kernel()
{
    extern __shared__ float smem[];
    float* Kp = smem;                        // pair-interleaved K: 8192 f
    float* Vs = smem + 8192;                 // 256*32 = 8192 f
    unsigned long long* plist =
        (unsigned long long*)(smem + 16384); // 16 warps * 128 u64 = 16 KB

    const int blk = blockIdx.x;
    const int b   = blk / (NHD * NREG);
    const int rem = blk % (NHD * NREG);
    const int mh  = rem / NREG;
    const int r   = rem % NREG;
    const int tid = threadIdx.x;
    const int qbase = ((b * 8 + mh) * 49 + r) * 2048;
    const float scale = 0.0625f;
    const unsigned FULL = 0xffffffffu;

    {
        const int dp = (tid >> 5) & 15;
        const int ln = tid & 31;
#pragma unroll
        for (int t = 0; t < 4; ++t) {
            const int rr = g_topk[(b * 49 + r) * 4 + t];
            const int base = ((b * 8 + mh) * 49 + rr) * 2048;
            *(float4*)&Vs[t * 2048 + tid * 4] = *(const float4*)&g_V[base + tid * 4];
            const float2 va = *(const float2*)&g_K[base + ln * 32 + dp * 2];
            const float2 vb = *(const float2*)&g_K[base + (ln + 32) * 32 + dp * 2];
            *(float4*)&Kp[((t * 16 + dp) * 32 + ln) * 4] =
                make_float4(va.x, vb.x, va.y, vb.y);
        }
    }
    __syncthreads();

    const int warp = tid >> 5, lane = tid & 31;
    unsigned long long* myp = plist + warp * 128;
    const char* Vb = (const char*)Vs;
    const int laneoff = lane * 4;
    const int s0 = warp * 4;

    // ---- scores for 4 rows in one K pass (bit-exact f32x2, ascending d) ----
    unsigned long long acc[4][4];
#pragma unroll
    for (int rr2 = 0; rr2 < 4; ++rr2)
#pragma unroll
        for (int u = 0; u < 4; ++u) acc[rr2][u] = 0ull;

    const float* q0 = g_Q + qbase + s0 * 32;
#pragma unroll
    for (int dp = 0; dp < 16; ++dp) {
        unsigned long long p0[4], p1[4];
#pragma unroll
        for (int rr2 = 0; rr2 < 4; ++rr2) {
            const float2 qv = *(const float2*)&q0[rr2 * 32 + dp * 2];
            p0[rr2] = pk2(qv.x, qv.x);
            p1[rr2] = pk2(qv.y, qv.y);
        }
#pragma unroll
        for (int u = 0; u < 4; ++u) {
            const ulonglong2 kk =
                *(const ulonglong2*)&Kp[((u * 16 + dp) * 32 + lane) * 4];
#pragma unroll
            for (int rr2 = 0; rr2 < 4; ++rr2) {
                ffma2(acc[rr2][u], p0[rr2], kk.x);
                ffma2(acc[rr2][u], p1[rr2], kk.y);
            }
        }
    }

    unsigned key[4][8];
    float m[4];
#pragma unroll
    for (int rr2 = 0; rr2 < 4; ++rr2) {
        float a[8];
#pragma unroll
        for (int u = 0; u < 4; ++u) upk2(acc[rr2][u], a[2*u], a[2*u+1]);
        unsigned mx = 0u;
#pragma unroll
        for (int t = 0; t < 8; ++t) {
            key[rr2][t] = fkey(a[t] * scale);
            mx = key[rr2][t] > mx ? key[rr2][t] : mx;
        }
        mx = __reduce_max_sync(FULL, mx);
        m[rr2] = fkeyinv(mx);
    }

    // ---- 16-step bit-search on top 16 key bits (two packed REDUX chains) ----
    unsigned T[4] = {0u, 0u, 0u, 0u};
#pragma unroll
    for (int bit = 15; bit >= 0; --bit) {
        unsigned c0 = (T[0] | (1u << bit)) << 16;
        unsigned c1 = (T[1] | (1u << bit)) << 16;
        unsigned c2 = (T[2] | (1u << bit)) << 16;
        unsigned c3 = (T[3] | (1u << bit)) << 16;
        unsigned n01 = 0, n23 = 0;
#pragma unroll
        for (int t = 0; t < 8; ++t) {
            n01 += (key[0][t] >= c0);
            n01 += (key[1][t] >= c1) << 16;
            n23 += (key[2][t] >= c2);
            n23 += (key[3][t] >= c3) << 16;
        }
        n01 = __reduce_add_sync(FULL, n01);
        n23 = __reduce_add_sync(FULL, n23);
        if ((n01 & 0xffffu) >= 32) T[0] |= 1u << bit;
        if ((n01 >> 16)     >= 32) T[1] |= 1u << bit;
        if ((n23 & 0xffffu) >= 32) T[2] |= 1u << bit;
        if ((n23 >> 16)     >= 32) T[3] |= 1u << bit;
    }

    // ---- winner compaction via one packed 4-row exclusive warp scan ----
    __syncwarp();
    unsigned selm[4];
    unsigned cnt4 = 0;
#pragma unroll
    for (int rr2 = 0; rr2 < 4; ++rr2) {
        const unsigned thr = (T[rr2] + 1u) << 16;
        unsigned msk = 0;
#pragma unroll
        for (int t = 0; t < 8; ++t)
            if (key[rr2][t] >= thr) msk |= 1u << t;
        selm[rr2] = msk;
        cnt4 |= (unsigned)__popc(msk) << (8 * rr2);
    }
    unsigned off4 = cnt4;
#pragma unroll
    for (int d2 = 1; d2 < 32; d2 <<= 1) {
        const unsigned v = __shfl_up_sync(FULL, off4, d2);
        if (lane >= d2) off4 += v;
    }
    const unsigned my4  = off4 - cnt4;              // exclusive per-row offsets
    const unsigned tot4 = __shfl_sync(FULL, off4, 31);

    int pos[4];
#pragma unroll
    for (int rr2 = 0; rr2 < 4; ++rr2) {
        const unsigned thr = (T[rr2] + 1u) << 16;
        const unsigned lo  = T[rr2] << 16;
        const unsigned msk = selm[rr2];
        int wo = (int)((my4 >> (8 * rr2)) & 0xffu);
#pragma unroll
        for (int t = 0; t < 8; ++t) {
            const unsigned kv = key[rr2][t];
            const unsigned j  = (unsigned)(t * 32 + lane);
            if (msk & (1u << t)) {
                const float w = __expf(fkeyinv(kv) - m[rr2]);
                myp[rr2 * 32 + wo] =
                    ((unsigned long long)__float_as_uint(w) << 32) | (j << 7);
                ++wo;
            }
            key[rr2][t] = (kv < thr && kv >= lo)
                        ? (((kv & 0xffffu) << 8) | (255u - j) | (1u << 24)) : 0u;
        }
        pos[rr2] = (int)((tot4 >> (8 * rr2)) & 0xffu);
    }

    // ---- exact tail: pop largest full keys from each boundary bucket ----
#pragma unroll
    for (int rr2 = 0; rr2 < 4; ++rr2) {
        const unsigned lo = T[rr2] << 16;
        while (pos[rr2] < 32) {
            unsigned lm = key[rr2][0];
#pragma unroll
            for (int t = 1; t < 8; ++t) lm = key[rr2][t] > lm ? key[rr2][t] : lm;
            const unsigned wm = __reduce_max_sync(FULL, lm);
            if (lm == wm) {
#pragma unroll
                for (int t = 0; t < 8; ++t) {
                    if (key[rr2][t] == wm) {
                        const unsigned kfull = lo | ((wm >> 8) & 0xffffu);
                        const float w = __expf(fkeyinv(kfull) - m[rr2]);
                        myp[rr2 * 32 + pos[rr2]] =
                            ((unsigned long long)__float_as_uint(w) << 32)
                            | ((255u - (wm & 0xffu)) << 7);
                        key[rr2][t] = 0u;
                    }
                }
            }
            ++pos[rr2];
        }
    }
    __syncwarp();

    // ---- fused softmax-normalize + AV, 4 rows interleaved for ILP ----
    float o[4] = {0.f, 0.f, 0.f, 0.f};
    float dnm[4] = {0.f, 0.f, 0.f, 0.f};
#pragma unroll
    for (int i = 0; i < 32; i += 2) {
#pragma unroll
        for (int rr2 = 0; rr2 < 4; ++rr2) {
            const ulonglong2 e = *(const ulonglong2*)&myp[rr2 * 32 + i];
            const float w0 = __uint_as_float((unsigned)(e.x >> 32));
            const float w1 = __uint_as_float((unsigned)(e.y >> 32));
            dnm[rr2] += w0;
            o[rr2] = fmaf(w0, *(const float*)(Vb + (unsigned)e.x + laneoff), o[rr2]);
            dnm[rr2] += w1;
            o[rr2] = fmaf(w1, *(const float*)(Vb + (unsigned)e.y + laneoff), o[rr2]);
        }
    }
#pragma unroll
    for (int rr2 = 0; rr2 < 4; ++rr2)
        g_O[qbase + (s0 + rr2) * 32 + lane] = o[rr2] / dnm[rr2];
}

// ---------------------------------------------------------------------------
// LePE (smem-tiled, unchanged from R13 — bit-identical output)
// ---------------------------------------------------------------------------
__global__ void __launch_bounds__(256, 4)
lepe_kernel(const float* __restrict__ lw, const float* __restrict__ lb)
{
    extern __shared__ float Vt[];            // 100 positions * 128 ch = 51200 B

    const int breg = blockIdx.x;
    const int b  = breg / 49, r = breg % 49;
    const int ch0 = blockIdx.y << 7;
    const int h0 = (r / 7) * 8, w0 = (r % 7) * 8;
    const int tid = threadIdx.x;
    const int hbase = b * 8 * 49;

    {
        const int c4 = (tid & 31) * 4;
        const int ch = ch0 + c4;
        const int mh = ch >> 5, d = ch & 31;
        for (int p = (tid >> 5); p < 100; p += 8) {
            const int gy = h0 - 1 + p / 10;
            const int gx = w0 - 1 + p % 10;
            float4 v = make_float4(0.f, 0.f, 0.f, 0.f);
            if (gy >= 0 && gy < 56 && gx >= 0 && gx < 56) {
                const int rr = (gy >> 3) * 7 + (gx >> 3);
                const int ss = ((gy & 7) << 3) | (gx & 7);
                v = *(const float4*)&g_V[(hbase + mh * 49 + rr) * 2048 + ss * 32 + d];
            }
            *(float4*)&Vt[p * 128 + c4] = v;
        }
    }
    __syncthreads();

    const int lc = tid & 127;
    const int tg = tid >> 7;
    const int ch = ch0 + lc;
    const int mh = ch >> 5, d = ch & 31;
    float wgt[9];
#pragma unroll
    for (int i = 0; i < 9; ++i) wgt[i] = lw[ch * 9 + i];
    const float lbv = lb[ch];
    const int obase = (hbase + mh * 49 + r) * 2048 + d;

#pragma unroll 4
    for (int tk = tg * 32; tk < tg * 32 + 32; ++tk) {
        const int ty = tk >> 3, tx2 = tk & 7;
        float acc = lbv;
#pragma unroll
        for (int ky = 0; ky < 3; ++ky)
#pragma unroll
            for (int kx = 0; kx < 3; ++kx)
                acc = fmaf(Vt[((ty + ky) * 10 + tx2 + kx) * 128 + lc],
                           wgt[ky * 3 + kx], acc);
        const int h = h0 + ty, w = w0 + tx2;
        g_T[((b * 56 + h) * 56 + w) * 256 + ch] = g_O[obase + tk * 32] + acc;
    }
}

// ---------------------------------------------------------------------------
// Output projection GEMM (M=25088, N=256, K=256), double-buffered smem.
// Bit-exact accumulation order.
// ---------------------------------------------------------------------------
__global__ void __launch_bounds__(256, 2)
out_gemm_kernel(const float* __restrict__ wo,
                const float* __restrict__ bo,
                float* __restrict__ out)
{
    __shared__ float As[2][16][132];
    __shared__ float Bs[2][16][132];
    const int tx = threadIdx.x, ty = threadIdx.y;
    const int tid = ty * 16 + tx;
    const int m0 = blockIdx.y * 128, n0 = blockIdx.x * 128;

    float acc[8][8];
#pragma unroll
    for (int i = 0; i < 8; ++i)
#pragma unroll
        for (int j = 0; j < 8; ++j) acc[i][j] = 0.f;

    const int r0 = tid >> 2, c0 = tid & 3;

    float4 pa[2], pb[2];
#pragma unroll
    for (int p = 0; p < 2; ++p) {
        const int r = r0 + p * 64;
        pa[p] = *(const float4*)&g_T[(m0 + r) * 256 + c0 * 4];
        pb[p] = *(const float4*)&wo [(n0 + r) * 256 + c0 * 4];
    }
#pragma unroll
    for (int p = 0; p < 2; ++p) {
        const int r = r0 + p * 64;
        As[0][c0*4+0][r] = pa[p].x; As[0][c0*4+1][r] = pa[p].y;
        As[0][c0*4+2][r] = pa[p].z; As[0][c0*4+3][r] = pa[p].w;
        Bs[0][c0*4+0][r] = pb[p].x; Bs[0][c0*4+1][r] = pb[p].y;
        Bs[0][c0*4+2][r] = pb[p].z; Bs[0][c0*4+3][r] = pb[p].w;
    }
    __syncthreads();

    int cur = 0;
    for (int kc = 0; kc < 16; ++kc) {
        if (kc < 15) {
            const int kn = (kc + 1) * 16;
#pragma unroll
            for (int p = 0; p < 2; ++p) {
                const int r = r0 + p * 64;
                pa[p] = *(const float4*)&g_T[(m0 + r) * 256 + kn + c0 * 4];
                pb[p] = *(const float4*)&wo [(n0 + r) * 256 + kn + c0 * 4];
            }
        }
#pragma unroll
        for (int k = 0; k < 16; ++k) {
            float a[8], b[8];
            *(float4*)&a[0] = *(float4*)&As[cur][k][ty * 8];
            *(float4*)&a[4] = *(float4*)&As[cur][k][ty * 8 + 4];
            *(float4*)&b[0] = *(float4*)&Bs[cur][k][tx * 8];
            *(float4*)&b[4] = *(float4*)&Bs[cur][k][tx * 8 + 4];
#pragma unroll
            for (int i = 0; i < 8; ++i)
#pragma unroll
                for (int j = 0; j < 8; ++j) acc[i][j] = fmaf(a[i], b[j], acc[i][j]);
        }
        if (kc < 15) {
            const int nxt = cur ^ 1;
#pragma unroll
            for (int p = 0; p < 2; ++p) {
                const int r = r0 + p * 64;
                As[nxt][c0*4+0][r] = pa[p].x; As[nxt][c0*4+1][r] = pa[p].y;
                As[nxt][c0*4+2][r] = pa[p].z; As[nxt][c0*4+3][r] = pa[p].w;
                Bs[nxt][c0*4+0][r] = pb[p].x; Bs[nxt][c0*4+1][r] = pb[p].y;
                Bs[nxt][c0*4+2][r] = pb[p].z; Bs[nxt][c0*4+3][r] = pb[p].w;
            }
            __syncthreads();
            cur = nxt;
        }
    }

    const int nbase = n0 + tx * 8;
    float bb[8];
    *(float4*)&bb[0] = *(const float4*)&bo[nbase];
    *(float4*)&bb[4] = *(const float4*)&bo[nbase + 4];
#pragma unroll
    for (int i = 0; i < 8; ++i) {
        const int m = m0 + ty * 8 + i;
        float4 v0 = make_float4(acc[i][0]+bb[0], acc[i][1]+bb[1], acc[i][2]+bb[2], acc[i][3]+bb[3]);
        float4 v1 = make_float4(acc[i][4]+bb[4], acc[i][5]+bb[5], acc[i][6]+bb[6], acc[i][7]+bb[7]);
        *(float4*)&out[m * 256 + nbase]     = v0;
        *(float4*)&out[m * 256 + nbase + 4] = v1;
    }
}

// ---------------------------------------------------------------------------
extern "C" void kernel_launch(void* const* d_in, const int* in_sizes, int n_in,
                              void* d_out, int out_size)
{
    const float* x      = (const float*)d_in[0];
    const float* qkv_w  = (const float*)d_in[1];
    const float* qkv_b  = (const float*)d_in[2];
    const float* lepe_w = (const float*)d_in[3];
    const float* lepe_b = (const float*)d_in[4];
    const float* out_w  = (const float*)d_in[5];
    const float* out_b  = (const float*)d_in[6];
    float* out = (float*)d_out;

    const int attn_smem = 8192 * 4 + 8192 * 4 + 16 * 128 * 8;  // 81920 B
    cudaFuncSetAttribute(attn_kernel, cudaFuncAttributeMaxDynamicSharedMemorySize, attn_smem);
    const int lepe_smem = 100 * 128 * 4;                       // 51200 B
    cudaFuncSetAttribute(lepe_kernel, cudaFuncAttributeMaxDynamicSharedMemorySize, lepe_smem);

    qkv_gemm_kernel<<<dim3(6, 196), dim3(16, 16)>>>(x, qkv_w, qkv_b);
    pool_kernel<<<392, 256>>>();
    route_kernel<<<392, 256>>>();
    attn_kernel<<<BATCH * NHD * NREG, 512, attn_smem>>>();
    lepe_kernel<<<dim3(392, 2), 256, lepe_smem>>>(lepe_w, lepe_b);
    out_gemm_kernel<<<dim3(2, 196), dim3(16, 16)>>>(out_w, out_b, out);
}

// round 17
// speedup vs baseline: 2.2056x; 1.0102x over previous
#include <cuda_runtime.h>
#include <math.h>

#define BATCH 8
#define NHD 8
#define HD 32
#define NREG 49
#define SREG 64
#define TOPK 4
#define M_TOK (BATCH*56*56)                 // 25088
#define SEQ_SIZE (BATCH*NHD*NREG*SREG*HD)   // 6422528

__device__ float g_Q[SEQ_SIZE];
__device__ float g_K[SEQ_SIZE];
__device__ float g_V[SEQ_SIZE];
__device__ float g_O[SEQ_SIZE];
__device__ float g_T[SEQ_SIZE];
__device__ float g_poolq[BATCH*NREG*256];
__device__ float g_poolk[BATCH*NREG*256];
__device__ int   g_topk[BATCH*NREG*TOPK];

// ---- packed fp32x2 helpers (two independent IEEE fp32 ops -> bit-exact) ----
__device__ __forceinline__ unsigned long long pk2(float lo, float hi) {
    unsigned long long d;
    asm("mov.b64 %0, {%1, %2};" : "=l"(d)
        : "r"(__float_as_uint(lo)), "r"(__float_as_uint(hi)));
    return d;
}
__device__ __forceinline__ void upk2(unsigned long long v, float& lo, float& hi) {
    unsigned a, b;
    asm("mov.b64 {%0, %1}, %2;" : "=r"(a), "=r"(b) : "l"(v));
    lo = __uint_as_float(a); hi = __uint_as_float(b);
}
__device__ __forceinline__ void ffma2(unsigned long long& acc,
                                      unsigned long long a, unsigned long long b) {
    asm("fma.rn.f32x2 %0, %1, %2, %3;" : "=l"(acc) : "l"(a), "l"(b), "l"(acc));
}

// ---------------------------------------------------------------------------
// QKV GEMM (M=25088, N=768, K=256): 128x128 tile, 8x8 microtile, scalar FFMA,
// double-buffered smem. Bit-exact ascending-k accumulation. (Unchanged.)
// ---------------------------------------------------------------------------
__global__ void __launch_bounds__(256, 2)
qkv_gemm_kernel(const float* __restrict__ x,
                const float* __restrict__ wq,
                const float* __restrict__ bias)
{
    __shared__ float As[2][16][132];
    __shared__ float Bs[2][16][132];
    const int tx = threadIdx.x, ty = threadIdx.y;
    const int tid = ty * 16 + tx;
    const int m0 = blockIdx.y * 128, n0 = blockIdx.x * 128;

    float acc[8][8];
#pragma unroll
    for (int i = 0; i < 8; ++i)
#pragma unroll
        for (int j = 0; j < 8; ++j) acc[i][j] = 0.f;

    const int r0 = tid >> 2, c0 = tid & 3;

    float4 pa[2], pb[2];
#pragma unroll
    for (int p = 0; p < 2; ++p) {
        const int r = r0 + p * 64;
        pa[p] = *(const float4*)&x [(m0 + r) * 256 + c0 * 4];
        pb[p] = *(const float4*)&wq[(n0 + r) * 256 + c0 * 4];
    }
#pragma unroll
    for (int p = 0; p < 2; ++p) {
        const int r = r0 + p * 64;
        As[0][c0*4+0][r] = pa[p].x; As[0][c0*4+1][r] = pa[p].y;
        As[0][c0*4+2][r] = pa[p].z; As[0][c0*4+3][r] = pa[p].w;
        Bs[0][c0*4+0][r] = pb[p].x; Bs[0][c0*4+1][r] = pb[p].y;
        Bs[0][c0*4+2][r] = pb[p].z; Bs[0][c0*4+3][r] = pb[p].w;
    }
    __syncthreads();

    int cur = 0;
    for (int kc = 0; kc < 16; ++kc) {
        if (kc < 15) {
            const int kn = (kc + 1) * 16;
#pragma unroll
            for (int p = 0; p < 2; ++p) {
                const int r = r0 + p * 64;
                pa[p] = *(const float4*)&x [(m0 + r) * 256 + kn + c0 * 4];
                pb[p] = *(const float4*)&wq[(n0 + r) * 256 + kn + c0 * 4];
            }
        }
#pragma unroll
        for (int k = 0; k < 16; ++k) {
            float a[8], b[8];
            *(float4*)&a[0] = *(float4*)&As[cur][k][ty * 8];
            *(float4*)&a[4] = *(float4*)&As[cur][k][ty * 8 + 4];
            *(float4*)&b[0] = *(float4*)&Bs[cur][k][tx * 8];
            *(float4*)&b[4] = *(float4*)&Bs[cur][k][tx * 8 + 4];
#pragma unroll
            for (int i = 0; i < 8; ++i)
#pragma unroll
                for (int j = 0; j < 8; ++j) acc[i][j] = fmaf(a[i], b[j], acc[i][j]);
        }
        if (kc < 15) {
            const int nxt = cur ^ 1;
#pragma unroll
            for (int p = 0; p < 2; ++p) {
                const int r = r0 + p * 64;
                As[nxt][c0*4+0][r] = pa[p].x; As[nxt][c0*4+1][r] = pa[p].y;
                As[nxt][c0*4+2][r] = pa[p].z; As[nxt][c0*4+3][r] = pa[p].w;
                Bs[nxt][c0*4+0][r] = pb[p].x; Bs[nxt][c0*4+1][r] = pb[p].y;
                Bs[nxt][c0*4+2][r] = pb[p].z; Bs[nxt][c0*4+3][r] = pb[p].w;
            }
            __syncthreads();
            cur = nxt;
        }
    }

    const int nbase = n0 + tx * 8;
    const int sec = nbase >> 8;
    const int cch = nbase & 255;
    const int mh  = cch >> 5, d0 = cch & 31;
    float* dst = (sec == 0) ? g_Q : (sec == 1 ? g_K : g_V);
    float bb[8];
    *(float4*)&bb[0] = *(const float4*)&bias[nbase];
    *(float4*)&bb[4] = *(const float4*)&bias[nbase + 4];

#pragma unroll
    for (int i = 0; i < 8; ++i) {
        int m  = m0 + ty * 8 + i;
        int b  = m / 3136;
        int hw = m - b * 3136;
        int h  = hw / 56;
        int w  = hw - h * 56;
        int r  = (h >> 3) * 7 + (w >> 3);
        int ss = ((h & 7) << 3) | (w & 7);
        int off = ((b * 8 + mh) * 49 + r) * 2048 + ss * 32 + d0;
        float4 v0 = make_float4(acc[i][0]+bb[0], acc[i][1]+bb[1], acc[i][2]+bb[2], acc[i][3]+bb[3]);
        float4 v1 = make_float4(acc[i][4]+bb[4], acc[i][5]+bb[5], acc[i][6]+bb[6], acc[i][7]+bb[7]);
        *(float4*)&dst[off]     = v0;
        *(float4*)&dst[off + 4] = v1;
    }
}

// ---------------------------------------------------------------------------
// Region average pooling of Q and K
// ---------------------------------------------------------------------------
__global__ void pool_kernel()
{
    const int b = blockIdx.x / 49, r = blockIdx.x % 49;
    const int c = threadIdx.x;
    const int mh = c >> 5, d = c & 31;
    const int base = ((b * 8 + mh) * 49 + r) * 2048 + d;
    float sq = 0.f, sk = 0.f;
#pragma unroll 8
    for (int s = 0; s < 64; ++s) {
        sq += g_Q[base + s * 32];
        sk += g_K[base + s * 32];
    }
    g_poolq[(b * 49 + r) * 256 + c] = sq * (1.f / 64.f);
    g_poolk[(b * 49 + r) * 256 + c] = sk * (1.f / 64.f);
}

// ---------------------------------------------------------------------------
// Coarse routing: top-4 region set per (b, region)
// ---------------------------------------------------------------------------
__global__ void route_kernel()
{
    const int b = blockIdx.x / 49, i = blockIdx.x % 49;
    __shared__ float qrow[256];
    __shared__ float scores[49];
    const int tid = threadIdx.x;
    qrow[tid] = g_poolq[(b * 49 + i) * 256 + tid];
    __syncthreads();
    const int warp = tid >> 5, lane = tid & 31;
    for (int j = warp; j < 49; j += 8) {
        const float* kr = g_poolk + (b * 49 + j) * 256;
        float s = 0.f;
#pragma unroll
        for (int cc = lane; cc < 256; cc += 32) s += qrow[cc] * kr[cc];
#pragma unroll
        for (int off = 16; off; off >>= 1) s += __shfl_xor_sync(0xffffffffu, s, off);
        if (lane == 0) scores[j] = s;
    }
    __syncthreads();
    if (tid == 0) {
        for (int t = 0; t < 4; ++t) {
            float bv = -INFINITY; int bj = 0;
            for (int j = 0; j < 49; ++j)
                if (scores[j] > bv) { bv = scores[j]; bj = j; }
            g_topk[(b * 49 + i) * 4 + t] = bj;
            scores[bj] = -INFINITY;
        }
    }
}

// ---------------------------------------------------------------------------
// Sparse attention per (b, head, region). This round: packed-Q smem (no per-
// dp pack movs / LDG), dnm accumulated at selection time (one butterfly
// reduce per row instead of 32 redundant FADDs in AV). Selection sets
// identical; only dnm summation order changes (~1e-7 wiggle).
// ---------------------------------------------------------------------------
__device__ __forceinline__ unsigned fkey(float v) {
    unsigned u = __float_as_uint(v);
    return (u & 0x80000000u) ? ~u : (u | 0x80000000u);
}
__device__ __forceinline__ float fkeyinv(unsigned k) {
    return __uint_as_float((k & 0x80000000u) ? (k & 0x7fffffffu) : ~k);
}

__global__ void __launch_bounds__(512, 2) attn_kernel()
{
    extern __shared__ float smem[];
    float* Kp = smem;                        // pair-interleaved K: 8192 f (32KB)
    float* Vs = smem + 8192;                 // 256*32 = 8192 f (32KB)
    unsigned long long* Qp =
        (unsigned long long*)(smem + 16384); // 2048 u64 dup'd q (16KB)
    unsigned long long* plist =
        (unsigned long long*)(smem + 20480); // 16 warps * 128 u64 (16KB)

    const int blk = blockIdx.x;
    const int b   = blk / (NHD * NREG);
    const int rem = blk % (NHD * NREG);
    const int mh  = rem / NREG;
    const int r   = rem % NREG;
    const int tid = threadIdx.x;
    const int qbase = ((b * 8 + mh) * 49 + r) * 2048;
    const float scale = 0.0625f;
    const unsigned FULL = 0xffffffffu;

    {
        const int dp = (tid >> 5) & 15;
        const int ln = tid & 31;
#pragma unroll
        for (int t = 0; t < 4; ++t) {
            const int rr = g_topk[(b * 49 + r) * 4 + t];
            const int base = ((b * 8 + mh) * 49 + rr) * 2048;
            *(float4*)&Vs[t * 2048 + tid * 4] = *(const float4*)&g_V[base + tid * 4];
            const float2 va = *(const float2*)&g_K[base + ln * 32 + dp * 2];
            const float2 vb = *(const float2*)&g_K[base + (ln + 32) * 32 + dp * 2];
            *(float4*)&Kp[((t * 16 + dp) * 32 + ln) * 4] =
                make_float4(va.x, vb.x, va.y, vb.y);
        }
        // duplicated-pair Q: Qp[row*32+d] = (q, q)
#pragma unroll
        for (int e = tid; e < 2048; e += 512) {
            const float qv = g_Q[qbase + e];
            Qp[e] = pk2(qv, qv);
        }
    }
    __syncthreads();

    const int warp = tid >> 5, lane = tid & 31;
    unsigned long long* myp = plist + warp * 128;
    const char* Vb = (const char*)Vs;
    const int laneoff = lane * 4;
    const int s0 = warp * 4;

    // ---- scores for 4 rows in one K pass (bit-exact f32x2, ascending d) ----
    unsigned long long acc[4][4];
#pragma unroll
    for (int rr2 = 0; rr2 < 4; ++rr2)
#pragma unroll
        for (int u = 0; u < 4; ++u) acc[rr2][u] = 0ull;

#pragma unroll
    for (int dp = 0; dp < 16; ++dp) {
        unsigned long long p0[4], p1[4];
#pragma unroll
        for (int rr2 = 0; rr2 < 4; ++rr2) {
            const ulonglong2 qq =
                *(const ulonglong2*)&Qp[(s0 + rr2) * 32 + dp * 2];
            p0[rr2] = qq.x;
            p1[rr2] = qq.y;
        }
#pragma unroll
        for (int u = 0; u < 4; ++u) {
            const ulonglong2 kk =
                *(const ulonglong2*)&Kp[((u * 16 + dp) * 32 + lane) * 4];
#pragma unroll
            for (int rr2 = 0; rr2 < 4; ++rr2) {
                ffma2(acc[rr2][u], p0[rr2], kk.x);
                ffma2(acc[rr2][u], p1[rr2], kk.y);
            }
        }
    }

    unsigned key[4][8];
    float m[4];
#pragma unroll
    for (int rr2 = 0; rr2 < 4; ++rr2) {
        float a[8];
#pragma unroll
        for (int u = 0; u < 4; ++u) upk2(acc[rr2][u], a[2*u], a[2*u+1]);
        unsigned mx = 0u;
#pragma unroll
        for (int t = 0; t < 8; ++t) {
            key[rr2][t] = fkey(a[t] * scale);
            mx = key[rr2][t] > mx ? key[rr2][t] : mx;
        }
        mx = __reduce_max_sync(FULL, mx);
        m[rr2] = fkeyinv(mx);
    }

    // ---- 16-step bit-search on top 16 key bits (two packed REDUX chains) ----
    unsigned T[4] = {0u, 0u, 0u, 0u};
#pragma unroll
    for (int bit = 15; bit >= 0; --bit) {
        unsigned c0 = (T[0] | (1u << bit)) << 16;
        unsigned c1 = (T[1] | (1u << bit)) << 16;
        unsigned c2 = (T[2] | (1u << bit)) << 16;
        unsigned c3 = (T[3] | (1u << bit)) << 16;
        unsigned n01 = 0, n23 = 0;
#pragma unroll
        for (int t = 0; t < 8; ++t) {
            n01 += (key[0][t] >= c0);
            n01 += (key[1][t] >= c1) << 16;
            n23 += (key[2][t] >= c2);
            n23 += (key[3][t] >= c3) << 16;
        }
        n01 = __reduce_add_sync(FULL, n01);
        n23 = __reduce_add_sync(FULL, n23);
        if ((n01 & 0xffffu) >= 32) T[0] |= 1u << bit;
        if ((n01 >> 16)     >= 32) T[1] |= 1u << bit;
        if ((n23 & 0xffffu) >= 32) T[2] |= 1u << bit;
        if ((n23 >> 16)     >= 32) T[3] |= 1u << bit;
    }

    // ---- winner compaction via one packed 4-row exclusive warp scan;
    //      weights accumulated on owning lanes for dnm ----
    __syncwarp();
    unsigned selm[4];
    unsigned cnt4 = 0;
#pragma unroll
    for (int rr2 = 0; rr2 < 4; ++rr2) {
        const unsigned thr = (T[rr2] + 1u) << 16;
        unsigned msk = 0;
#pragma unroll
        for (int t = 0; t < 8; ++t)
            if (key[rr2][t] >= thr) msk |= 1u << t;
        selm[rr2] = msk;
        cnt4 |= (unsigned)__popc(msk) << (8 * rr2);
    }
    unsigned off4 = cnt4;
#pragma unroll
    for (int d2 = 1; d2 < 32; d2 <<= 1) {
        const unsigned v = __shfl_up_sync(FULL, off4, d2);
        if (lane >= d2) off4 += v;
    }
    const unsigned my4  = off4 - cnt4;
    const unsigned tot4 = __shfl_sync(FULL, off4, 31);

    float wsum[4] = {0.f, 0.f, 0.f, 0.f};
    int pos[4];
#pragma unroll
    for (int rr2 = 0; rr2 < 4; ++rr2) {
        const unsigned thr = (T[rr2] + 1u) << 16;
        const unsigned lo  = T[rr2] << 16;
        const unsigned msk = selm[rr2];
        int wo = (int)((my4 >> (8 * rr2)) & 0xffu);
#pragma unroll
        for (int t = 0; t < 8; ++t) {
            const unsigned kv = key[rr2][t];
            const unsigned j  = (unsigned)(t * 32 + lane);
            if (msk & (1u << t)) {
                const float w = __expf(fkeyinv(kv) - m[rr2]);
                wsum[rr2] += w;
                myp[rr2 * 32 + wo] =
                    ((unsigned long long)__float_as_uint(w) << 32) | (j << 7);
                ++wo;
            }
            key[rr2][t] = (kv < thr && kv >= lo)
                        ? (((kv & 0xffffu) << 8) | (255u - j) | (1u << 24)) : 0u;
        }
        pos[rr2] = (int)((tot4 >> (8 * rr2)) & 0xffu);
    }

    // ---- exact tail: pop largest full keys from each boundary bucket ----
#pragma unroll
    for (int rr2 = 0; rr2 < 4; ++rr2) {
        const unsigned lo = T[rr2] << 16;
        while (pos[rr2] < 32) {
            unsigned lm = key[rr2][0];
#pragma unroll
            for (int t = 1; t < 8; ++t) lm = key[rr2][t] > lm ? key[rr2][t] : lm;
            const unsigned wm = __reduce_max_sync(FULL, lm);
            const unsigned kfull = lo | ((wm >> 8) & 0xffffu);
            const float w = __expf(fkeyinv(kfull) - m[rr2]);
            if (lane == 0) wsum[rr2] += w;   // tail weight counted once
            if (lm == wm) {
#pragma unroll
                for (int t = 0; t < 8; ++t) {
                    if (key[rr2][t] == wm) {
                        myp[rr2 * 32 + pos[rr2]] =
                            ((unsigned long long)__float_as_uint(w) << 32)
                            | ((255u - (wm & 0xffu)) << 7);
                        key[rr2][t] = 0u;
                    }
                }
            }
            ++pos[rr2];
        }
    }
    __syncwarp();

    // ---- dnm via one butterfly reduce per row ----
    float dnm[4];
#pragma unroll
    for (int rr2 = 0; rr2 < 4; ++rr2) {
        float s = wsum[rr2];
#pragma unroll
        for (int off = 16; off; off >>= 1) s += __shfl_xor_sync(FULL, s, off);
        dnm[rr2] = s;
    }

    // ---- AV only (denominator precomputed), 4 rows interleaved for ILP ----
    float o[4] = {0.f, 0.f, 0.f, 0.f};
#pragma unroll
    for (int i = 0; i < 32; i += 2) {
#pragma unroll
        for (int rr2 = 0; rr2 < 4; ++rr2) {
            const ulonglong2 e = *(const ulonglong2*)&myp[rr2 * 32 + i];
            const float w0 = __uint_as_float((unsigned)(e.x >> 32));
            const float w1 = __uint_as_float((unsigned)(e.y >> 32));
            o[rr2] = fmaf(w0, *(const float*)(Vb + (unsigned)e.x + laneoff), o[rr2]);
            o[rr2] = fmaf(w1, *(const float*)(Vb + (unsigned)e.y + laneoff), o[rr2]);
        }
    }
#pragma unroll
    for (int rr2 = 0; rr2 < 4; ++rr2)
        g_O[qbase + (s0 + rr2) * 32 + lane] = o[rr2] / dnm[rr2];
}

// ---------------------------------------------------------------------------
// LePE (smem-tiled, unchanged — bit-identical output)
// ---------------------------------------------------------------------------
__global__ void __launch_bounds__(256, 4)
lepe_kernel(const float* __restrict__ lw, const float* __restrict__ lb)
{
    extern __shared__ float Vt[];            // 100 positions * 128 ch = 51200 B

    const int breg = blockIdx.x;
    const int b  = breg / 49, r = breg % 49;
    const int ch0 = blockIdx.y << 7;
    const int h0 = (r / 7) * 8, w0 = (r % 7) * 8;
    const int tid = threadIdx.x;
    const int hbase = b * 8 * 49;

    {
        const int c4 = (tid & 31) * 4;
        const int ch = ch0 + c4;
        const int mh = ch >> 5, d = ch & 31;
        for (int p = (tid >> 5); p < 100; p += 8) {
            const int gy = h0 - 1 + p / 10;
            const int gx = w0 - 1 + p % 10;
            float4 v = make_float4(0.f, 0.f, 0.f, 0.f);
            if (gy >= 0 && gy < 56 && gx >= 0 && gx < 56) {
                const int rr = (gy >> 3) * 7 + (gx >> 3);
                const int ss = ((gy & 7) << 3) | (gx & 7);
                v = *(const float4*)&g_V[(hbase + mh * 49 + rr) * 2048 + ss * 32 + d];
            }
            *(float4*)&Vt[p * 128 + c4] = v;
        }
    }
    __syncthreads();

    const int lc = tid & 127;
    const int tg = tid >> 7;
    const int ch = ch0 + lc;
    const int mh = ch >> 5, d = ch & 31;
    float wgt[9];
#pragma unroll
    for (int i = 0; i < 9; ++i) wgt[i] = lw[ch * 9 + i];
    const float lbv = lb[ch];
    const int obase = (hbase + mh * 49 + r) * 2048 + d;

#pragma unroll 4
    for (int tk = tg * 32; tk < tg * 32 + 32; ++tk) {
        const int ty = tk >> 3, tx2 = tk & 7;
        float acc = lbv;
#pragma unroll
        for (int ky = 0; ky < 3; ++ky)
#pragma unroll
            for (int kx = 0; kx < 3; ++kx)
                acc = fmaf(Vt[((ty + ky) * 10 + tx2 + kx) * 128 + lc],
                           wgt[ky * 3 + kx], acc);
        const int h = h0 + ty, w = w0 + tx2;
        g_T[((b * 56 + h) * 56 + w) * 256 + ch] = g_O[obase + tk * 32] + acc;
    }
}

// ---------------------------------------------------------------------------
// Output projection GEMM (M=25088, N=256, K=256), double-buffered smem.
// Bit-exact accumulation order. (Unchanged.)
// ---------------------------------------------------------------------------
__global__ void __launch_bounds__(256, 2)
out_gemm_kernel(const float* __restrict__ wo,
                const float* __restrict__ bo,
                float* __restrict__ out)
{
    __shared__ float As[2][16][132];
    __shared__ float Bs[2][16][132];
    const int tx = threadIdx.x, ty = threadIdx.y;
    const int tid = ty * 16 + tx;
    const int m0 = blockIdx.y * 128, n0 = blockIdx.x * 128;

    float acc[8][8];
#pragma unroll
    for (int i = 0; i < 8; ++i)
#pragma unroll
        for (int j = 0; j < 8; ++j) acc[i][j] = 0.f;

    const int r0 = tid >> 2, c0 = tid & 3;

    float4 pa[2], pb[2];
#pragma unroll
    for (int p = 0; p < 2; ++p) {
        const int r = r0 + p * 64;
        pa[p] = *(const float4*)&g_T[(m0 + r) * 256 + c0 * 4];
        pb[p] = *(const float4*)&wo [(n0 + r) * 256 + c0 * 4];
    }
#pragma unroll
    for (int p = 0; p < 2; ++p) {
        const int r = r0 + p * 64;
        As[0][c0*4+0][r] = pa[p].x; As[0][c0*4+1][r] = pa[p].y;
        As[0][c0*4+2][r] = pa[p].z; As[0][c0*4+3][r] = pa[p].w;
        Bs[0][c0*4+0][r] = pb[p].x; Bs[0][c0*4+1][r] = pb[p].y;
        Bs[0][c0*4+2][r] = pb[p].z; Bs[0][c0*4+3][r] = pb[p].w;
    }
    __syncthreads();

    int cur = 0;
    for (int kc = 0; kc < 16; ++kc) {
        if (kc < 15) {
            const int kn = (kc + 1) * 16;
#pragma unroll
            for (int p = 0; p < 2; ++p) {
                const int r = r0 + p * 64;
                pa[p] = *(const float4*)&g_T[(m0 + r) * 256 + kn + c0 * 4];
                pb[p] = *(const float4*)&wo [(n0 + r) * 256 + kn + c0 * 4];
            }
        }
#pragma unroll
        for (int k = 0; k < 16; ++k) {
            float a[8], b[8];
            *(float4*)&a[0] = *(float4*)&As[cur][k][ty * 8];
            *(float4*)&a[4] = *(float4*)&As[cur][k][ty * 8 + 4];
            *(float4*)&b[0] = *(float4*)&Bs[cur][k][tx * 8];
            *(float4*)&b[4] = *(float4*)&Bs[cur][k][tx * 8 + 4];
#pragma unroll
            for (int i = 0; i < 8; ++i)
#pragma unroll
                for (int j = 0; j < 8; ++j) acc[i][j] = fmaf(a[i], b[j], acc[i][j]);
        }
        if (kc < 15) {
            const int nxt = cur ^ 1;
#pragma unroll
            for (int p = 0; p < 2; ++p) {
                const int r = r0 + p * 64;
                As[nxt][c0*4+0][r] = pa[p].x; As[nxt][c0*4+1][r] = pa[p].y;
                As[nxt][c0*4+2][r] = pa[p].z; As[nxt][c0*4+3][r] = pa[p].w;
                Bs[nxt][c0*4+0][r] = pb[p].x; Bs[nxt][c0*4+1][r] = pb[p].y;
                Bs[nxt][c0*4+2][r] = pb[p].z; Bs[nxt][c0*4+3][r] = pb[p].w;
            }
            __syncthreads();
            cur = nxt;
        }
    }

    const int nbase = n0 + tx * 8;
    float bb[8];
    *(float4*)&bb[0] = *(const float4*)&bo[nbase];
    *(float4*)&bb[4] = *(const float4*)&bo[nbase + 4];
#pragma unroll
    for (int i = 0; i < 8; ++i) {
        const int m = m0 + ty * 8 + i;
        float4 v0 = make_float4(acc[i][0]+bb[0], acc[i][1]+bb[1], acc[i][2]+bb[2], acc[i][3]+bb[3]);
        float4 v1 = make_float4(acc[i][4]+bb[4], acc[i][5]+bb[5], acc[i][6]+bb[6], acc[i][7]+bb[7]);
        *(float4*)&out[m * 256 + nbase]     = v0;
        *(float4*)&out[m * 256 + nbase + 4] = v1;
    }
}

// ---------------------------------------------------------------------------
extern "C" void kernel_launch(void* const* d_in, const int* in_sizes, int n_in,
                              void* d_out, int out_size)
{
    const float* x      = (const float*)d_in[0];
    const float* qkv_w  = (const float*)d_in[1];
    const float* qkv_b  = (const float*)d_in[2];
    const float* lepe_w = (const float*)d_in[3];
    const float* lepe_b = (const float*)d_in[4];
    const float* out_w  = (const float*)d_in[5];
    const float* out_b  = (const float*)d_in[6];
    float* out = (float*)d_out;

    const int attn_smem = 8192 * 4 + 8192 * 4 + 2048 * 8 + 16 * 128 * 8;  // 98304 B
    cudaFuncSetAttribute(attn_kernel, cudaFuncAttributeMaxDynamicSharedMemorySize, attn_smem);
    const int lepe_smem = 100 * 128 * 4;                                   // 51200 B
    cudaFuncSetAttribute(lepe_kernel, cudaFuncAttributeMaxDynamicSharedMemorySize, lepe_smem);

    qkv_gemm_kernel<<<dim3(6, 196), dim3(16, 16)>>>(x, qkv_w, qkv_b);
    pool_kernel<<<392, 256>>>();
    route_kernel<<<392, 256>>>();
    attn_kernel<<<BATCH * NHD * NREG, 512, attn_smem>>>();
    lepe_kernel<<<dim3(392, 2), 256, lepe_smem>>>(lepe_w, lepe_b);
    out_gemm_kernel<<<dim3(2, 196), dim3(16, 16)>>>(out_w, out_b, out);
}